// round 1
// baseline (speedup 1.0000x reference)
#include <cuda_runtime.h>
#include <cuda_bf16.h>

// Problem constants
static constexpr int B_  = 8;
static constexpr int T_  = 2048;
static constexpr int D_  = 1024;
static constexpr int HD_ = 64;
static constexpr int M_  = B_ * T_;   // 16384 rows total

// Scratch for q, k, v projections (device globals — no allocation allowed)
__device__ float g_q[(size_t)M_ * HD_];
__device__ float g_k[(size_t)M_ * HD_];
__device__ float g_v[(size_t)M_ * HD_];

// ---------------------------------------------------------------------------
// Kernel 1: fused QKV projection.
// grid.x = M/64 blocks; each block computes a 64-row tile of q, k, v (64 cols
// each) reading x once. 256 threads, 16x16 thread grid, 4x4 micro-tile per
// matrix (3 matrices -> 48 accumulators).
// ---------------------------------------------------------------------------
__global__ __launch_bounds__(256) void proj_qkv_kernel(
    const float* __restrict__ x,
    const float* __restrict__ Wq,
    const float* __restrict__ Wk,
    const float* __restrict__ Wv)
{
    __shared__ float sx[16][68];    // x^T chunk: [k][m], padded
    __shared__ float sw[16][196];   // [k][ Wq(0:64) | Wk(64:128) | Wv(128:192) ]

    const int tid = threadIdx.x;
    const int tx = tid & 15;
    const int ty = tid >> 4;
    const int row0 = blockIdx.x * 64;

    float acc[3][4][4];
#pragma unroll
    for (int mtx = 0; mtx < 3; mtx++)
#pragma unroll
        for (int i = 0; i < 4; i++)
#pragma unroll
            for (int j = 0; j < 4; j++)
                acc[mtx][i][j] = 0.0f;

    for (int kc = 0; kc < D_; kc += 16) {
        // Load x chunk (64 rows x 16 k), store transposed sx[k][m]
        {
            const int row = tid >> 2;           // 0..63
            const int k4  = (tid & 3) * 4;      // 0,4,8,12
            float4 xv = *(const float4*)&x[(size_t)(row0 + row) * D_ + kc + k4];
            sx[k4 + 0][row] = xv.x;
            sx[k4 + 1][row] = xv.y;
            sx[k4 + 2][row] = xv.z;
            sx[k4 + 3][row] = xv.w;
        }
        // Load W chunk: 16 rows x 192 cols total = 768 float4, 3 per thread
#pragma unroll
        for (int r = 0; r < 3; r++) {
            const int f   = tid + r * 256;      // 0..767
            const int kk  = f / 48;             // 0..15
            const int col = (f % 48) * 4;       // 0..188
            const float* Wsrc;
            int wcol;
            if (col < 64)       { Wsrc = Wq; wcol = col; }
            else if (col < 128) { Wsrc = Wk; wcol = col - 64; }
            else                { Wsrc = Wv; wcol = col - 128; }
            float4 wv = *(const float4*)&Wsrc[(size_t)(kc + kk) * HD_ + wcol];
            *(float4*)&sw[kk][col] = wv;
        }
        __syncthreads();

#pragma unroll
        for (int kk = 0; kk < 16; kk++) {
            float4 a4 = *(const float4*)&sx[kk][ty * 4];
            float a[4] = {a4.x, a4.y, a4.z, a4.w};
            float4 b0 = *(const float4*)&sw[kk][tx * 4];
            float4 b1 = *(const float4*)&sw[kk][64 + tx * 4];
            float4 b2 = *(const float4*)&sw[kk][128 + tx * 4];
            float bq[4] = {b0.x, b0.y, b0.z, b0.w};
            float bk[4] = {b1.x, b1.y, b1.z, b1.w};
            float bv[4] = {b2.x, b2.y, b2.z, b2.w};
#pragma unroll
            for (int i = 0; i < 4; i++) {
#pragma unroll
                for (int j = 0; j < 4; j++) {
                    acc[0][i][j] = fmaf(a[i], bq[j], acc[0][i][j]);
                    acc[1][i][j] = fmaf(a[i], bk[j], acc[1][i][j]);
                    acc[2][i][j] = fmaf(a[i], bv[j], acc[2][i][j]);
                }
            }
        }
        __syncthreads();
    }

#pragma unroll
    for (int i = 0; i < 4; i++) {
        const size_t m = (size_t)(row0 + ty * 4 + i);
        *(float4*)&g_q[m * HD_ + tx * 4] =
            make_float4(acc[0][i][0], acc[0][i][1], acc[0][i][2], acc[0][i][3]);
        *(float4*)&g_k[m * HD_ + tx * 4] =
            make_float4(acc[1][i][0], acc[1][i][1], acc[1][i][2], acc[1][i][3]);
        *(float4*)&g_v[m * HD_ + tx * 4] =
            make_float4(acc[2][i][0], acc[2][i][1], acc[2][i][2], acc[2][i][3]);
    }
}

// ---------------------------------------------------------------------------
// Kernel 2: causal flash attention over 64x64 tiles with online softmax.
// grid = (T/64, B). Each block owns one 64-query tile of one batch and loops
// over key blocks 0..qt (causal skipping).
// SMEM tiles (all rows padded to 68 floats):
//   sq: Q^T [h][m]   sk: K^T [h][c]   sv: V [key][h]   sp: P^T [key][m]
// ---------------------------------------------------------------------------
static constexpr int ATTN_SMEM_FLOATS = 4 * 64 * 68;
static constexpr int ATTN_SMEM_BYTES  = ATTN_SMEM_FLOATS * 4;  // 69632

__global__ __launch_bounds__(256) void attn_kernel(float* __restrict__ out)
{
    extern __shared__ float smem[];
    float (*sq)[68] = (float(*)[68])(smem);
    float (*sk)[68] = (float(*)[68])(smem + 64 * 68);
    float (*sv)[68] = (float(*)[68])(smem + 2 * 64 * 68);
    float (*sp)[68] = (float(*)[68])(smem + 3 * 64 * 68);

    const int tid = threadIdx.x;
    const int tx = tid & 15;
    const int ty = tid >> 4;
    const int qt = blockIdx.x;
    const int b  = blockIdx.y;
    const size_t qrow0 = (size_t)b * T_ + (size_t)qt * 64;

    // Load Q tile transposed: sq[h][m]
#pragma unroll
    for (int it = 0; it < 4; it++) {
        const int li  = tid + it * 256;     // 0..1023
        const int row = li >> 4;            // 0..63
        const int h4  = (li & 15) * 4;      // 0..60
        float4 v4 = *(const float4*)&g_q[(qrow0 + row) * HD_ + h4];
        sq[h4 + 0][row] = v4.x;
        sq[h4 + 1][row] = v4.y;
        sq[h4 + 2][row] = v4.z;
        sq[h4 + 3][row] = v4.w;
    }

    float m_cur[4], l_cur[4], O[4][4];
#pragma unroll
    for (int i = 0; i < 4; i++) {
        m_cur[i] = -1e30f;
        l_cur[i] = 0.0f;
#pragma unroll
        for (int j = 0; j < 4; j++) O[i][j] = 0.0f;
    }

    for (int kt = 0; kt <= qt; kt++) {
        const size_t krow0 = (size_t)b * T_ + (size_t)kt * 64;
        // Load K tile transposed + V tile direct
#pragma unroll
        for (int it = 0; it < 4; it++) {
            const int li  = tid + it * 256;
            const int row = li >> 4;
            const int h4  = (li & 15) * 4;
            float4 kv = *(const float4*)&g_k[(krow0 + row) * HD_ + h4];
            sk[h4 + 0][row] = kv.x;
            sk[h4 + 1][row] = kv.y;
            sk[h4 + 2][row] = kv.z;
            sk[h4 + 3][row] = kv.w;
            float4 vv = *(const float4*)&g_v[(krow0 + row) * HD_ + h4];
            *(float4*)&sv[row][h4] = vv;
        }
        __syncthreads();

        // Scores S = Q @ K^T (64x64), micro-tile 4x4 per thread
        float S[4][4];
#pragma unroll
        for (int i = 0; i < 4; i++)
#pragma unroll
            for (int j = 0; j < 4; j++) S[i][j] = 0.0f;

#pragma unroll
        for (int h = 0; h < 64; h++) {
            float4 a4 = *(const float4*)&sq[h][ty * 4];
            float4 b4 = *(const float4*)&sk[h][tx * 4];
            float a[4]  = {a4.x, a4.y, a4.z, a4.w};
            float bb[4] = {b4.x, b4.y, b4.z, b4.w};
#pragma unroll
            for (int i = 0; i < 4; i++)
#pragma unroll
                for (int j = 0; j < 4; j++)
                    S[i][j] = fmaf(a[i], bb[j], S[i][j]);
        }

        // Scale + causal mask (only diagonal block needs masking)
        const float scale = 0.125f;  // 1/sqrt(64)
        const bool diag = (kt == qt);
#pragma unroll
        for (int i = 0; i < 4; i++) {
#pragma unroll
            for (int j = 0; j < 4; j++) {
                float s = S[i][j] * scale;
                if (diag && (tx * 4 + j > ty * 4 + i)) s = -1e30f;
                S[i][j] = s;
            }
        }

        // Online softmax: row-wise max / sum across 16 tx threads (shfl, 16-wide)
        float alpha[4];
#pragma unroll
        for (int i = 0; i < 4; i++) {
            float mx = fmaxf(fmaxf(S[i][0], S[i][1]), fmaxf(S[i][2], S[i][3]));
            mx = fmaxf(mx, __shfl_xor_sync(0xffffffffu, mx, 1));
            mx = fmaxf(mx, __shfl_xor_sync(0xffffffffu, mx, 2));
            mx = fmaxf(mx, __shfl_xor_sync(0xffffffffu, mx, 4));
            mx = fmaxf(mx, __shfl_xor_sync(0xffffffffu, mx, 8));
            const float mnew = fmaxf(m_cur[i], mx);
            alpha[i] = __expf(m_cur[i] - mnew);
            m_cur[i] = mnew;

            float sum = 0.0f;
#pragma unroll
            for (int j = 0; j < 4; j++) {
                float p = __expf(S[i][j] - mnew);
                S[i][j] = p;
                sum += p;
            }
            sum += __shfl_xor_sync(0xffffffffu, sum, 1);
            sum += __shfl_xor_sync(0xffffffffu, sum, 2);
            sum += __shfl_xor_sync(0xffffffffu, sum, 4);
            sum += __shfl_xor_sync(0xffffffffu, sum, 8);
            l_cur[i] = l_cur[i] * alpha[i] + sum;
        }

        // Write P transposed into sp[key][m]; rescale O
#pragma unroll
        for (int i = 0; i < 4; i++) {
#pragma unroll
            for (int j = 0; j < 4; j++) {
                sp[tx * 4 + j][ty * 4 + i] = S[i][j];
                O[i][j] *= alpha[i];
            }
        }
        __syncthreads();

        // O += P @ V
#pragma unroll
        for (int h = 0; h < 64; h++) {   // h = key index within block
            float4 p4 = *(const float4*)&sp[h][ty * 4];
            float4 v4 = *(const float4*)&sv[h][tx * 4];
            float p[4]  = {p4.x, p4.y, p4.z, p4.w};
            float vv[4] = {v4.x, v4.y, v4.z, v4.w};
#pragma unroll
            for (int i = 0; i < 4; i++)
#pragma unroll
                for (int j = 0; j < 4; j++)
                    O[i][j] = fmaf(p[i], vv[j], O[i][j]);
        }
        __syncthreads();   // protect sk/sv/sp before next iteration's loads
    }

    // Final normalize + store
#pragma unroll
    for (int i = 0; i < 4; i++) {
        const float inv_l = 1.0f / l_cur[i];
        const size_t row = qrow0 + (size_t)(ty * 4 + i);
        *(float4*)&out[row * HD_ + tx * 4] =
            make_float4(O[i][0] * inv_l, O[i][1] * inv_l,
                        O[i][2] * inv_l, O[i][3] * inv_l);
    }
}

// ---------------------------------------------------------------------------
extern "C" void kernel_launch(void* const* d_in, const int* in_sizes, int n_in,
                              void* d_out, int out_size)
{
    const float* x  = (const float*)d_in[0];
    const float* Wq = (const float*)d_in[1];
    const float* Wk = (const float*)d_in[2];
    const float* Wv = (const float*)d_in[3];
    float* out = (float*)d_out;

    cudaFuncSetAttribute(attn_kernel,
                         cudaFuncAttributeMaxDynamicSharedMemorySize,
                         ATTN_SMEM_BYTES);

    proj_qkv_kernel<<<M_ / 64, 256>>>(x, Wq, Wk, Wv);
    attn_kernel<<<dim3(T_ / 64, B_), 256, ATTN_SMEM_BYTES>>>(out);
}

// round 3
// speedup vs baseline: 1.8748x; 1.8748x over previous
#include <cuda_runtime.h>
#include <cuda_bf16.h>
#include <cstdint>

// Problem constants
static constexpr int B_  = 8;
static constexpr int T_  = 2048;
static constexpr int D_  = 1024;
static constexpr int HD_ = 64;
static constexpr int M_  = B_ * T_;       // 16384 rows
static constexpr int NTOT_ = 192;         // q|k|v fused output columns
static constexpr int TK_ = 64;            // K per chunk (128B bf16 rows)
static constexpr int NCHUNK_ = D_ / TK_;  // 16

// Scratch (device globals — no allocation allowed)
__device__ float g_q[(size_t)M_ * HD_];
__device__ float g_k[(size_t)M_ * HD_];
__device__ float g_v[(size_t)M_ * HD_];
// Pre-transposed + swizzled bf16 W tiles: [chunk][n=0..191][k=0..63]
static constexpr size_t WTILE_BYTES = (size_t)NTOT_ * 128;   // 24576 per chunk
__device__ __align__(16) uint8_t g_bhi[(size_t)NCHUNK_ * WTILE_BYTES];
__device__ __align__(16) uint8_t g_blo[(size_t)NCHUNK_ * WTILE_BYTES];

__host__ __device__ __forceinline__ uint32_t swz128(uint32_t off) {
    return off ^ ((off >> 3) & 0x70);
}
__device__ __forceinline__ uint32_t smem_u32(const void* p) {
    uint32_t a;
    asm("{ .reg .u64 t; cvta.to.shared.u64 t, %1; cvt.u32.u64 %0, t; }"
        : "=r"(a) : "l"(p));
    return a;
}
__device__ __forceinline__ void ldsm_x4(uint32_t (&r)[4], uint32_t addr) {
    asm volatile("ldmatrix.sync.aligned.m8n8.x4.shared.b16 {%0,%1,%2,%3}, [%4];"
                 : "=r"(r[0]), "=r"(r[1]), "=r"(r[2]), "=r"(r[3]) : "r"(addr));
}
__device__ __forceinline__ void ldsm_x2(uint32_t (&r)[2], uint32_t addr) {
    asm volatile("ldmatrix.sync.aligned.m8n8.x2.shared.b16 {%0,%1}, [%2];"
                 : "=r"(r[0]), "=r"(r[1]) : "r"(addr));
}
__device__ __forceinline__ void mma_bf16(float (&d)[4], const uint32_t (&a)[4],
                                         const uint32_t (&b)[2]) {
    asm volatile(
        "mma.sync.aligned.m16n8k16.row.col.f32.bf16.bf16.f32 "
        "{%0,%1,%2,%3}, {%4,%5,%6,%7}, {%8,%9}, {%0,%1,%2,%3};"
        : "+f"(d[0]), "+f"(d[1]), "+f"(d[2]), "+f"(d[3])
        : "r"(a[0]), "r"(a[1]), "r"(a[2]), "r"(a[3]), "r"(b[0]), "r"(b[1]));
}
__device__ __forceinline__ uint32_t pack_bf16x2(float lo, float hi) {
    __nv_bfloat16 l = __float2bfloat16_rn(lo);
    __nv_bfloat16 h = __float2bfloat16_rn(hi);
    return ((uint32_t)__bfloat16_as_ushort(h) << 16) | __bfloat16_as_ushort(l);
}

// ---------------------------------------------------------------------------
// Kernel 0: W -> bf16 hi/lo, transposed to [n][k-chunk] rows, SW128 swizzled.
// One thread handles 8 consecutive k for one output column c.
// ---------------------------------------------------------------------------
__global__ void prep_w_kernel(const float* __restrict__ Wq,
                              const float* __restrict__ Wk,
                              const float* __restrict__ Wv)
{
    const int t = blockIdx.x * blockDim.x + threadIdx.x;
    if (t >= NCHUNK_ * 8 * NTOT_) return;
    const int c = t % NTOT_;
    const int rest = t / NTOT_;
    const int kg = rest % 8;          // 8-k group within chunk
    const int chunk = rest / 8;
    const int n = c & 63;
    const float* W = (c < 64) ? Wq : (c < 128) ? Wk : Wv;
    const int k0 = chunk * TK_ + kg * 8;

    float f[8];
#pragma unroll
    for (int j = 0; j < 8; j++) f[j] = W[(size_t)(k0 + j) * HD_ + n];

    uint32_t hw[4], lw[4];
#pragma unroll
    for (int j = 0; j < 4; j++) {
        const float a = f[2 * j], b = f[2 * j + 1];
        const __nv_bfloat16 ha = __float2bfloat16_rn(a);
        const __nv_bfloat16 hb = __float2bfloat16_rn(b);
        hw[j] = ((uint32_t)__bfloat16_as_ushort(hb) << 16) | __bfloat16_as_ushort(ha);
        lw[j] = pack_bf16x2(a - __bfloat162float(ha), b - __bfloat162float(hb));
    }
    const size_t base = (size_t)chunk * WTILE_BYTES;
    const uint32_t off = swz128((uint32_t)c * 128u + (uint32_t)kg * 16u);
    *(uint4*)(g_bhi + base + off) = make_uint4(hw[0], hw[1], hw[2], hw[3]);
    *(uint4*)(g_blo + base + off) = make_uint4(lw[0], lw[1], lw[2], lw[3]);
}

// ---------------------------------------------------------------------------
// Kernel 1: QKV projection via mma.sync bf16 (3-term hi/lo split).
// CTA: 256 thr (8 warps), tile M=128 x N=192, K chunked by 64.
// Warp grid 2(M) x 4(N): warp tile 64x48 -> 4 m16-tiles x 6 n8-tiles.
// ---------------------------------------------------------------------------
static constexpr int A_TILE = 128 * 128;          // bytes (128 rows x 64 bf16)
static constexpr int B_TILE = NTOT_ * 128;        // bytes (192 rows x 64 bf16)
static constexpr int PROJ_SMEM = 1024 + 2 * A_TILE + 2 * B_TILE;

__global__ __launch_bounds__(256) void proj_mma_kernel(const float* __restrict__ x)
{
    extern __shared__ uint8_t dynsm[];
    const uint32_t raw = smem_u32(dynsm);
    const uint32_t base = (raw + 1023u) & ~1023u;
    uint8_t* const sm = dynsm + (base - raw);
    const uint32_t sAhi = base;
    const uint32_t sAlo = base + A_TILE;
    const uint32_t sBhi = base + 2 * A_TILE;
    const uint32_t sBlo = base + 2 * A_TILE + B_TILE;

    const int tid = threadIdx.x;
    const int wid = tid >> 5;
    const int lane = tid & 31;
    const int wm = wid >> 2;              // 0..1
    const int wn = wid & 3;               // 0..3
    const size_t row0g = (size_t)blockIdx.x * 128;

    float C[4][6][4];
#pragma unroll
    for (int mt = 0; mt < 4; mt++)
#pragma unroll
        for (int nt = 0; nt < 6; nt++)
#pragma unroll
            for (int e = 0; e < 4; e++) C[mt][nt][e] = 0.0f;

    // Per-lane ldmatrix address components
    const uint32_t a_row = (uint32_t)(lane & 15);
    const uint32_t a_kb  = (uint32_t)((lane >> 4) * 16);
    const uint32_t b_row = (uint32_t)(lane & 7);
    const uint32_t b_kb  = (uint32_t)(((lane >> 3) & 1) * 16);

    for (int kc = 0; kc < NCHUNK_; kc++) {
        // Fill A: 128 rows x 64 floats -> bf16 hi/lo, swizzled
#pragma unroll
        for (int i = 0; i < 8; i++) {
            const int idx = tid + i * 256;     // 0..2047
            const int row = idx >> 4;
            const int c4  = idx & 15;
            float4 v = *(const float4*)&x[(row0g + row) * D_ + kc * TK_ + c4 * 4];
            const uint32_t h0 = pack_bf16x2(v.x, v.y);
            const uint32_t h1 = pack_bf16x2(v.z, v.w);
            const uint32_t l0 = pack_bf16x2(
                v.x - __bfloat162float(__float2bfloat16_rn(v.x)),
                v.y - __bfloat162float(__float2bfloat16_rn(v.y)));
            const uint32_t l1 = pack_bf16x2(
                v.z - __bfloat162float(__float2bfloat16_rn(v.z)),
                v.w - __bfloat162float(__float2bfloat16_rn(v.w)));
            const uint32_t off = swz128((uint32_t)row * 128u + (uint32_t)c4 * 8u);
            *(uint2*)(sm + off)          = make_uint2(h0, h1);
            *(uint2*)(sm + A_TILE + off) = make_uint2(l0, l1);
        }
        // Fill B: copy pre-swizzled tiles (1536 float4 each)
        {
            const float4* srcH = (const float4*)(g_bhi + (size_t)kc * WTILE_BYTES);
            const float4* srcL = (const float4*)(g_blo + (size_t)kc * WTILE_BYTES);
            float4* dstH = (float4*)(sm + 2 * A_TILE);
            float4* dstL = (float4*)(sm + 2 * A_TILE + B_TILE);
#pragma unroll
            for (int i = 0; i < 6; i++) {
                const int idx = tid + i * 256;
                dstH[idx] = srcH[idx];
                dstL[idx] = srcL[idx];
            }
        }
        __syncthreads();

#pragma unroll
        for (int ks = 0; ks < 4; ks++) {
            uint32_t Ah[4][4], Al[4][4];
#pragma unroll
            for (int mt = 0; mt < 4; mt++) {
                const uint32_t roff =
                    swz128((uint32_t)(wm * 64 + mt * 16 + a_row) * 128u +
                           (uint32_t)ks * 32u + a_kb);
                ldsm_x4(Ah[mt], sAhi + roff);
                ldsm_x4(Al[mt], sAlo + roff);
            }
#pragma unroll
            for (int nt = 0; nt < 6; nt++) {
                const uint32_t boff =
                    swz128((uint32_t)(wn * 48 + nt * 8 + b_row) * 128u +
                           (uint32_t)ks * 32u + b_kb);
                uint32_t Bh[2], Bl[2];
                ldsm_x2(Bh, sBhi + boff);
                ldsm_x2(Bl, sBlo + boff);
#pragma unroll
                for (int mt = 0; mt < 4; mt++) {
                    mma_bf16(C[mt][nt], Ah[mt], Bh);
                    mma_bf16(C[mt][nt], Ah[mt], Bl);
                    mma_bf16(C[mt][nt], Al[mt], Bh);
                }
            }
        }
        __syncthreads();
    }

    // Epilogue: write C fragments to g_q/g_k/g_v
#pragma unroll
    for (int mt = 0; mt < 4; mt++) {
        const size_t r = row0g + wm * 64 + mt * 16 + (lane >> 2);
#pragma unroll
        for (int nt = 0; nt < 6; nt++) {
            const int c = wn * 48 + nt * 8 + 2 * (lane & 3);
            float* const o = (c < 64) ? g_q : (c < 128) ? g_k : g_v;
            const int n = c & 63;
            *(float2*)&o[r * HD_ + n] = make_float2(C[mt][nt][0], C[mt][nt][1]);
            *(float2*)&o[(r + 8) * HD_ + n] = make_float2(C[mt][nt][2], C[mt][nt][3]);
        }
    }
}

// ---------------------------------------------------------------------------
// Kernel 2: causal flash attention, 64x64 tiles, online softmax (SIMT fp32).
// Balanced: each block processes query-tiles qt = bx and 31-bx (33 kt-iters).
// ---------------------------------------------------------------------------
static constexpr int ATTN_SMEM_BYTES = 4 * 64 * 68 * 4;  // 69632

__global__ __launch_bounds__(256) void attn_kernel(float* __restrict__ out)
{
    extern __shared__ float smem[];
    float (*sq)[68] = (float(*)[68])(smem);
    float (*sk)[68] = (float(*)[68])(smem + 64 * 68);
    float (*sv)[68] = (float(*)[68])(smem + 2 * 64 * 68);
    float (*sp)[68] = (float(*)[68])(smem + 3 * 64 * 68);

    const int tid = threadIdx.x;
    const int tx = tid & 15;
    const int ty = tid >> 4;
    const int b  = blockIdx.y;

    for (int rep = 0; rep < 2; rep++) {
        const int qt = rep == 0 ? (int)blockIdx.x : 31 - (int)blockIdx.x;
        const size_t qrow0 = (size_t)b * T_ + (size_t)qt * 64;

#pragma unroll
        for (int it = 0; it < 4; it++) {
            const int li  = tid + it * 256;
            const int row = li >> 4;
            const int h4  = (li & 15) * 4;
            float4 v4 = *(const float4*)&g_q[(qrow0 + row) * HD_ + h4];
            sq[h4 + 0][row] = v4.x;
            sq[h4 + 1][row] = v4.y;
            sq[h4 + 2][row] = v4.z;
            sq[h4 + 3][row] = v4.w;
        }

        float m_cur[4], l_cur[4], O[4][4];
#pragma unroll
        for (int i = 0; i < 4; i++) {
            m_cur[i] = -1e30f;
            l_cur[i] = 0.0f;
#pragma unroll
            for (int j = 0; j < 4; j++) O[i][j] = 0.0f;
        }

        for (int kt = 0; kt <= qt; kt++) {
            const size_t krow0 = (size_t)b * T_ + (size_t)kt * 64;
#pragma unroll
            for (int it = 0; it < 4; it++) {
                const int li  = tid + it * 256;
                const int row = li >> 4;
                const int h4  = (li & 15) * 4;
                float4 kv = *(const float4*)&g_k[(krow0 + row) * HD_ + h4];
                sk[h4 + 0][row] = kv.x;
                sk[h4 + 1][row] = kv.y;
                sk[h4 + 2][row] = kv.z;
                sk[h4 + 3][row] = kv.w;
                float4 vv = *(const float4*)&g_v[(krow0 + row) * HD_ + h4];
                *(float4*)&sv[row][h4] = vv;
            }
            __syncthreads();

            float S[4][4];
#pragma unroll
            for (int i = 0; i < 4; i++)
#pragma unroll
                for (int j = 0; j < 4; j++) S[i][j] = 0.0f;

#pragma unroll
            for (int h = 0; h < 64; h++) {
                float4 a4 = *(const float4*)&sq[h][ty * 4];
                float4 b4 = *(const float4*)&sk[h][tx * 4];
                float a[4]  = {a4.x, a4.y, a4.z, a4.w};
                float bb[4] = {b4.x, b4.y, b4.z, b4.w};
#pragma unroll
                for (int i = 0; i < 4; i++)
#pragma unroll
                    for (int j = 0; j < 4; j++)
                        S[i][j] = fmaf(a[i], bb[j], S[i][j]);
            }

            const float scale = 0.125f;
            const bool diag = (kt == qt);
#pragma unroll
            for (int i = 0; i < 4; i++) {
#pragma unroll
                for (int j = 0; j < 4; j++) {
                    float s = S[i][j] * scale;
                    if (diag && (tx * 4 + j > ty * 4 + i)) s = -1e30f;
                    S[i][j] = s;
                }
            }

            float alpha[4];
#pragma unroll
            for (int i = 0; i < 4; i++) {
                float mx = fmaxf(fmaxf(S[i][0], S[i][1]), fmaxf(S[i][2], S[i][3]));
                mx = fmaxf(mx, __shfl_xor_sync(0xffffffffu, mx, 1));
                mx = fmaxf(mx, __shfl_xor_sync(0xffffffffu, mx, 2));
                mx = fmaxf(mx, __shfl_xor_sync(0xffffffffu, mx, 4));
                mx = fmaxf(mx, __shfl_xor_sync(0xffffffffu, mx, 8));
                const float mnew = fmaxf(m_cur[i], mx);
                alpha[i] = __expf(m_cur[i] - mnew);
                m_cur[i] = mnew;

                float sum = 0.0f;
#pragma unroll
                for (int j = 0; j < 4; j++) {
                    float p = __expf(S[i][j] - mnew);
                    S[i][j] = p;
                    sum += p;
                }
                sum += __shfl_xor_sync(0xffffffffu, sum, 1);
                sum += __shfl_xor_sync(0xffffffffu, sum, 2);
                sum += __shfl_xor_sync(0xffffffffu, sum, 4);
                sum += __shfl_xor_sync(0xffffffffu, sum, 8);
                l_cur[i] = l_cur[i] * alpha[i] + sum;
            }

#pragma unroll
            for (int i = 0; i < 4; i++) {
#pragma unroll
                for (int j = 0; j < 4; j++) {
                    sp[tx * 4 + j][ty * 4 + i] = S[i][j];
                    O[i][j] *= alpha[i];
                }
            }
            __syncthreads();

#pragma unroll
            for (int h = 0; h < 64; h++) {
                float4 p4 = *(const float4*)&sp[h][ty * 4];
                float4 v4 = *(const float4*)&sv[h][tx * 4];
                float p[4]  = {p4.x, p4.y, p4.z, p4.w};
                float vv[4] = {v4.x, v4.y, v4.z, v4.w};
#pragma unroll
                for (int i = 0; i < 4; i++)
#pragma unroll
                    for (int j = 0; j < 4; j++)
                        O[i][j] = fmaf(p[i], vv[j], O[i][j]);
            }
            __syncthreads();
        }

#pragma unroll
        for (int i = 0; i < 4; i++) {
            const float inv_l = 1.0f / l_cur[i];
            const size_t row = qrow0 + (size_t)(ty * 4 + i);
            *(float4*)&out[row * HD_ + tx * 4] =
                make_float4(O[i][0] * inv_l, O[i][1] * inv_l,
                            O[i][2] * inv_l, O[i][3] * inv_l);
        }
        __syncthreads();
    }
}

// ---------------------------------------------------------------------------
extern "C" void kernel_launch(void* const* d_in, const int* in_sizes, int n_in,
                              void* d_out, int out_size)
{
    const float* x  = (const float*)d_in[0];
    const float* Wq = (const float*)d_in[1];
    const float* Wk = (const float*)d_in[2];
    const float* Wv = (const float*)d_in[3];
    float* out = (float*)d_out;

    cudaFuncSetAttribute(proj_mma_kernel,
                         cudaFuncAttributeMaxDynamicSharedMemorySize, PROJ_SMEM);
    cudaFuncSetAttribute(attn_kernel,
                         cudaFuncAttributeMaxDynamicSharedMemorySize, ATTN_SMEM_BYTES);

    const int prep_threads = NCHUNK_ * 8 * NTOT_;
    prep_w_kernel<<<(prep_threads + 255) / 256, 256>>>(Wq, Wk, Wv);
    proj_mma_kernel<<<M_ / 128, 256, PROJ_SMEM>>>(x);
    attn_kernel<<<dim3(16, B_), 256, ATTN_SMEM_BYTES>>>(out);
}

// round 4
// speedup vs baseline: 2.7399x; 1.4615x over previous
#include <cuda_runtime.h>
#include <cuda_bf16.h>
#include <cstdint>

// Problem constants
static constexpr int B_  = 8;
static constexpr int T_  = 2048;
static constexpr int D_  = 1024;
static constexpr int HD_ = 64;
static constexpr int M_  = B_ * T_;       // 16384 rows
static constexpr int NTOT_ = 192;         // q|k|v fused output columns
static constexpr int TK_ = 64;            // K per chunk (128B bf16 rows)
static constexpr int NCHUNK_ = D_ / TK_;  // 16

// Device-global scratch (no allocation allowed).
// q (pre-scaled by 1/8), k, v stored as bf16 hi/lo pairs, row-major [row][64].
__device__ __align__(16) __nv_bfloat16 g_qhi[(size_t)M_ * HD_];
__device__ __align__(16) __nv_bfloat16 g_qlo[(size_t)M_ * HD_];
__device__ __align__(16) __nv_bfloat16 g_khi[(size_t)M_ * HD_];
__device__ __align__(16) __nv_bfloat16 g_klo[(size_t)M_ * HD_];
__device__ __align__(16) __nv_bfloat16 g_vhi[(size_t)M_ * HD_];
__device__ __align__(16) __nv_bfloat16 g_vlo[(size_t)M_ * HD_];
// Pre-transposed + swizzled bf16 W tiles: [chunk][n=0..191][k=0..63]
static constexpr size_t WTILE_BYTES = (size_t)NTOT_ * 128;   // 24576 per chunk
__device__ __align__(16) uint8_t g_bhi[(size_t)NCHUNK_ * WTILE_BYTES];
__device__ __align__(16) uint8_t g_blo[(size_t)NCHUNK_ * WTILE_BYTES];

__host__ __device__ __forceinline__ uint32_t swz128(uint32_t off) {
    return off ^ ((off >> 3) & 0x70);
}
__device__ __forceinline__ uint32_t smem_u32(const void* p) {
    uint32_t a;
    asm("{ .reg .u64 t; cvta.to.shared.u64 t, %1; cvt.u32.u64 %0, t; }"
        : "=r"(a) : "l"(p));
    return a;
}
__device__ __forceinline__ void ldsm_x4(uint32_t (&r)[4], uint32_t addr) {
    asm volatile("ldmatrix.sync.aligned.m8n8.x4.shared.b16 {%0,%1,%2,%3}, [%4];"
                 : "=r"(r[0]), "=r"(r[1]), "=r"(r[2]), "=r"(r[3]) : "r"(addr));
}
__device__ __forceinline__ void ldsm_x2(uint32_t (&r)[2], uint32_t addr) {
    asm volatile("ldmatrix.sync.aligned.m8n8.x2.shared.b16 {%0,%1}, [%2];"
                 : "=r"(r[0]), "=r"(r[1]) : "r"(addr));
}
__device__ __forceinline__ void ldsm_x2_trans(uint32_t (&r)[2], uint32_t addr) {
    asm volatile("ldmatrix.sync.aligned.m8n8.x2.trans.shared.b16 {%0,%1}, [%2];"
                 : "=r"(r[0]), "=r"(r[1]) : "r"(addr));
}
__device__ __forceinline__ void mma_bf16(float (&d)[4], const uint32_t (&a)[4],
                                         const uint32_t (&b)[2]) {
    asm volatile(
        "mma.sync.aligned.m16n8k16.row.col.f32.bf16.bf16.f32 "
        "{%0,%1,%2,%3}, {%4,%5,%6,%7}, {%8,%9}, {%0,%1,%2,%3};"
        : "+f"(d[0]), "+f"(d[1]), "+f"(d[2]), "+f"(d[3])
        : "r"(a[0]), "r"(a[1]), "r"(a[2]), "r"(a[3]), "r"(b[0]), "r"(b[1]));
}
__device__ __forceinline__ uint32_t pack_bf16x2(float lo, float hi) {
    __nv_bfloat16 l = __float2bfloat16_rn(lo);
    __nv_bfloat16 h = __float2bfloat16_rn(hi);
    return ((uint32_t)__bfloat16_as_ushort(h) << 16) | __bfloat16_as_ushort(l);
}
__device__ __forceinline__ void cp_async16(uint32_t dst, const void* src) {
    asm volatile("cp.async.ca.shared.global [%0], [%1], 16;"
                 :: "r"(dst), "l"(src));
}
#define CP_COMMIT() asm volatile("cp.async.commit_group;" ::: "memory")
#define CP_WAIT0()  asm volatile("cp.async.wait_group 0;" ::: "memory")
#define CP_WAIT1()  asm volatile("cp.async.wait_group 1;" ::: "memory")

// ---------------------------------------------------------------------------
// Kernel 0: W -> bf16 hi/lo, transposed to [n][k] rows, SW128 swizzled.
// ---------------------------------------------------------------------------
__global__ void prep_w_kernel(const float* __restrict__ Wq,
                              const float* __restrict__ Wk,
                              const float* __restrict__ Wv)
{
    const int t = blockIdx.x * blockDim.x + threadIdx.x;
    if (t >= NCHUNK_ * 8 * NTOT_) return;
    const int c = t % NTOT_;
    const int rest = t / NTOT_;
    const int kg = rest % 8;
    const int chunk = rest / 8;
    const int n = c & 63;
    const float* W = (c < 64) ? Wq : (c < 128) ? Wk : Wv;
    const int k0 = chunk * TK_ + kg * 8;

    float f[8];
#pragma unroll
    for (int j = 0; j < 8; j++) f[j] = W[(size_t)(k0 + j) * HD_ + n];

    uint32_t hw[4], lw[4];
#pragma unroll
    for (int j = 0; j < 4; j++) {
        const float a = f[2 * j], b = f[2 * j + 1];
        const __nv_bfloat16 ha = __float2bfloat16_rn(a);
        const __nv_bfloat16 hb = __float2bfloat16_rn(b);
        hw[j] = ((uint32_t)__bfloat16_as_ushort(hb) << 16) | __bfloat16_as_ushort(ha);
        lw[j] = pack_bf16x2(a - __bfloat162float(ha), b - __bfloat162float(hb));
    }
    const size_t base = (size_t)chunk * WTILE_BYTES;
    const uint32_t off = swz128((uint32_t)c * 128u + (uint32_t)kg * 16u);
    *(uint4*)(g_bhi + base + off) = make_uint4(hw[0], hw[1], hw[2], hw[3]);
    *(uint4*)(g_blo + base + off) = make_uint4(lw[0], lw[1], lw[2], lw[3]);
}

// ---------------------------------------------------------------------------
// Kernel 1: QKV projection via mma.sync bf16 (3-term split), 2-stage pipeline.
// CTA 256 thr, tile 128x192, K chunks of 64. Epilogue writes bf16 hi/lo
// q (x0.125), k, v.
// ---------------------------------------------------------------------------
static constexpr int A_TILE = 128 * 128;          // bytes
static constexpr int B_TILE = NTOT_ * 128;        // bytes
static constexpr int PROJ_STAGE = 2 * A_TILE + 2 * B_TILE;   // 81920
static constexpr int PROJ_SMEM = 1024 + 2 * PROJ_STAGE;

__global__ __launch_bounds__(256) void proj_mma_kernel(const float* __restrict__ x)
{
    extern __shared__ uint8_t dynsm[];
    const uint32_t raw = smem_u32(dynsm);
    const uint32_t base = (raw + 1023u) & ~1023u;
    uint8_t* const sm = dynsm + (base - raw);

    const int tid = threadIdx.x;
    const int wid = tid >> 5;
    const int lane = tid & 31;
    const int wm = wid >> 2;
    const int wn = wid & 3;
    const size_t row0g = (size_t)blockIdx.x * 128;

    float C[4][6][4];
#pragma unroll
    for (int mt = 0; mt < 4; mt++)
#pragma unroll
        for (int nt = 0; nt < 6; nt++)
#pragma unroll
            for (int e = 0; e < 4; e++) C[mt][nt][e] = 0.0f;

    const uint32_t a_row = (uint32_t)(lane & 15);
    const uint32_t a_kb  = (uint32_t)((lane >> 4) * 16);
    const uint32_t b_row = (uint32_t)(lane & 7);
    const uint32_t b_kb  = (uint32_t)(((lane >> 3) & 1) * 16);

    auto fill = [&](int stage, int kc) {
        uint8_t* s = sm + stage * PROJ_STAGE;
        // A: 128 rows x 64 floats -> bf16 hi/lo, swizzled
#pragma unroll
        for (int i = 0; i < 8; i++) {
            const int idx = tid + i * 256;
            const int row = idx >> 4;
            const int c4  = idx & 15;
            float4 v = *(const float4*)&x[(row0g + row) * D_ + kc * TK_ + c4 * 4];
            const uint32_t h0 = pack_bf16x2(v.x, v.y);
            const uint32_t h1 = pack_bf16x2(v.z, v.w);
            const uint32_t l0 = pack_bf16x2(
                v.x - __bfloat162float(__float2bfloat16_rn(v.x)),
                v.y - __bfloat162float(__float2bfloat16_rn(v.y)));
            const uint32_t l1 = pack_bf16x2(
                v.z - __bfloat162float(__float2bfloat16_rn(v.z)),
                v.w - __bfloat162float(__float2bfloat16_rn(v.w)));
            const uint32_t off = swz128((uint32_t)row * 128u + (uint32_t)c4 * 8u);
            *(uint2*)(s + off)          = make_uint2(h0, h1);
            *(uint2*)(s + A_TILE + off) = make_uint2(l0, l1);
        }
        // B: copy pre-swizzled tiles
        const float4* srcH = (const float4*)(g_bhi + (size_t)kc * WTILE_BYTES);
        const float4* srcL = (const float4*)(g_blo + (size_t)kc * WTILE_BYTES);
        float4* dstH = (float4*)(s + 2 * A_TILE);
        float4* dstL = (float4*)(s + 2 * A_TILE + B_TILE);
#pragma unroll
        for (int i = 0; i < 6; i++) {
            const int idx = tid + i * 256;
            dstH[idx] = srcH[idx];
            dstL[idx] = srcL[idx];
        }
    };

    fill(0, 0);
    __syncthreads();

    for (int kc = 0; kc < NCHUNK_; kc++) {
        if (kc + 1 < NCHUNK_) fill((kc + 1) & 1, kc + 1);

        const uint32_t sb = base + (kc & 1) * PROJ_STAGE;
        const uint32_t sAhi = sb, sAlo = sb + A_TILE;
        const uint32_t sBhi = sb + 2 * A_TILE, sBlo = sb + 2 * A_TILE + B_TILE;

#pragma unroll
        for (int ks = 0; ks < 4; ks++) {
            uint32_t Ah[4][4], Al[4][4];
#pragma unroll
            for (int mt = 0; mt < 4; mt++) {
                const uint32_t roff =
                    swz128((uint32_t)(wm * 64 + mt * 16 + a_row) * 128u +
                           (uint32_t)ks * 32u + a_kb);
                ldsm_x4(Ah[mt], sAhi + roff);
                ldsm_x4(Al[mt], sAlo + roff);
            }
#pragma unroll
            for (int nt = 0; nt < 6; nt++) {
                const uint32_t boff =
                    swz128((uint32_t)(wn * 48 + nt * 8 + b_row) * 128u +
                           (uint32_t)ks * 32u + b_kb);
                uint32_t Bh[2], Bl[2];
                ldsm_x2(Bh, sBhi + boff);
                ldsm_x2(Bl, sBlo + boff);
#pragma unroll
                for (int mt = 0; mt < 4; mt++) {
                    mma_bf16(C[mt][nt], Ah[mt], Bh);
                    mma_bf16(C[mt][nt], Ah[mt], Bl);
                    mma_bf16(C[mt][nt], Al[mt], Bh);
                }
            }
        }
        __syncthreads();
    }

    // Epilogue: split to bf16 hi/lo; q gets pre-scaled by 0.125
#pragma unroll
    for (int mt = 0; mt < 4; mt++) {
        const size_t r = row0g + wm * 64 + mt * 16 + (lane >> 2);
#pragma unroll
        for (int nt = 0; nt < 6; nt++) {
            const int c = wn * 48 + nt * 8 + 2 * (lane & 3);
            const int n = c & 63;
            __nv_bfloat16 *ohi, *olo;
            float sc = 1.0f;
            if (c < 64)       { ohi = g_qhi; olo = g_qlo; sc = 0.125f; }
            else if (c < 128) { ohi = g_khi; olo = g_klo; }
            else              { ohi = g_vhi; olo = g_vlo; }
#pragma unroll
            for (int half = 0; half < 2; half++) {
                const size_t rr = r + half * 8;
                const float v0 = C[mt][nt][half * 2 + 0] * sc;
                const float v1 = C[mt][nt][half * 2 + 1] * sc;
                const __nv_bfloat16 h0 = __float2bfloat16_rn(v0);
                const __nv_bfloat16 h1 = __float2bfloat16_rn(v1);
                *(uint32_t*)&ohi[rr * HD_ + n] =
                    ((uint32_t)__bfloat16_as_ushort(h1) << 16) | __bfloat16_as_ushort(h0);
                *(uint32_t*)&olo[rr * HD_ + n] =
                    pack_bf16x2(v0 - __bfloat162float(h0), v1 - __bfloat162float(h1));
            }
        }
    }
}

// ---------------------------------------------------------------------------
// Kernel 2: flash attention on mma.sync bf16 (3-term splits everywhere).
// CTA 256 thr: warps 0-3 -> q-tile p, warps 4-7 -> q-tile 31-p (shared K/V).
// Key loop kt=0..31-p, cp.async double-buffered K/V tiles.
// ---------------------------------------------------------------------------
static constexpr int QSTAGE_BYTES = 2 * 128 * 128;         // 32768 (hi|lo)
static constexpr int KV_STAGE    = 4 * 64 * 128;           // 32768 per stage
static constexpr int ATTN_SMEM   = 1024 + QSTAGE_BYTES + 2 * KV_STAGE;  // ~99K

__global__ __launch_bounds__(256) void attn_mma_kernel(float* __restrict__ out)
{
    extern __shared__ uint8_t dynsm[];
    const uint32_t raw = smem_u32(dynsm);
    const uint32_t base = (raw + 1023u) & ~1023u;

    const int tid = threadIdx.x;
    const int wid = tid >> 5;
    const int lane = tid & 31;
    const int grp = wid >> 2;             // 0: q-tile p, 1: q-tile 31-p
    const int wi  = wid & 3;              // warp-in-group: 16 rows each
    const int p = blockIdx.x;             // 0..15
    const int b = blockIdx.y;
    const int gq = grp == 0 ? p : 31 - p; // this group's 64-row q-tile
    const int ktop = 31 - p;              // pair max

    const uint32_t sQ   = base;                         // hi 16K | lo 16K
    const uint32_t sKV0 = base + QSTAGE_BYTES;          // two 32K stages

    // ---- stage Q (both tiles) via cp.async ----
    {
#pragma unroll
        for (int i = 0; i < 4; i++) {
            const int idx = tid + i * 256;      // 0..1023
            const int row = idx >> 3;           // 0..127
            const int c16 = idx & 7;
            const int qt  = row < 64 ? p : 31 - p;
            const size_t grow = (size_t)b * T_ + (size_t)qt * 64 + (row & 63);
            const uint32_t doff = swz128((uint32_t)row * 128u + (uint32_t)c16 * 16u);
            cp_async16(sQ + doff,          &g_qhi[grow * HD_ + c16 * 8]);
            cp_async16(sQ + 16384 + doff,  &g_qlo[grow * HD_ + c16 * 8]);
        }
        CP_COMMIT();
    }

    // ---- prefetch K/V tile 0 ----
    auto prefetch_kv = [&](int kt, int stage) {
        const uint32_t sb = sKV0 + stage * KV_STAGE;
        const size_t krow0 = (size_t)b * T_ + (size_t)kt * 64;
#pragma unroll
        for (int i = 0; i < 2; i++) {
            const int idx = tid + i * 256;      // 0..511
            const int row = idx >> 3;           // 0..63
            const int c16 = idx & 7;
            const uint32_t doff = swz128((uint32_t)row * 128u + (uint32_t)c16 * 16u);
            const size_t goff = (krow0 + row) * HD_ + c16 * 8;
            cp_async16(sb + doff,          &g_khi[goff]);
            cp_async16(sb +  8192 + doff,  &g_klo[goff]);
            cp_async16(sb + 16384 + doff,  &g_vhi[goff]);
            cp_async16(sb + 24576 + doff,  &g_vlo[goff]);
        }
        CP_COMMIT();
    };
    prefetch_kv(0, 0);

    // ---- wait for Q, load Q fragments ----
    CP_WAIT1();
    __syncthreads();

    uint32_t Qh[4][4], Ql[4][4];
    {
        const uint32_t a_row = (uint32_t)(lane & 15);
        const uint32_t a_kb  = (uint32_t)((lane >> 4) * 16);
#pragma unroll
        for (int ks = 0; ks < 4; ks++) {
            const uint32_t roff =
                swz128((uint32_t)(grp * 64 + wi * 16 + a_row) * 128u +
                       (uint32_t)ks * 32u + a_kb);
            ldsm_x4(Qh[ks], sQ + roff);
            ldsm_x4(Ql[ks], sQ + 16384 + roff);
        }
    }

    float O[8][4];
#pragma unroll
    for (int nh = 0; nh < 8; nh++)
#pragma unroll
        for (int e = 0; e < 4; e++) O[nh][e] = 0.0f;
    float m0 = -1e30f, m1 = -1e30f, l0 = 0.0f, l1 = 0.0f;

    const uint32_t b_row = (uint32_t)(lane & 7);
    const uint32_t b_kb  = (uint32_t)(((lane >> 3) & 1) * 16);
    const int q2 = 2 * (lane & 3);
    const int rloc = (lane >> 2);         // 0..7

    for (int kt = 0; kt <= ktop; kt++) {
        if (kt + 1 <= ktop) {
            prefetch_kv(kt + 1, (kt + 1) & 1);
            CP_WAIT1();
        } else {
            CP_WAIT0();
        }
        __syncthreads();

        if (kt <= gq) {
            const uint32_t sb = sKV0 + (kt & 1) * KV_STAGE;
            const uint32_t sKh = sb, sKl = sb + 8192;
            const uint32_t sVh = sb + 16384, sVl = sb + 24576;

            // ---- S = Q @ K^T ----
            float S[8][4];
#pragma unroll
            for (int nt = 0; nt < 8; nt++)
#pragma unroll
                for (int e = 0; e < 4; e++) S[nt][e] = 0.0f;

#pragma unroll
            for (int ks = 0; ks < 4; ks++) {
#pragma unroll
                for (int nt = 0; nt < 8; nt++) {
                    const uint32_t boff =
                        swz128((uint32_t)(nt * 8 + b_row) * 128u +
                               (uint32_t)ks * 32u + b_kb);
                    uint32_t Bh[2], Bl[2];
                    ldsm_x2(Bh, sKh + boff);
                    ldsm_x2(Bl, sKl + boff);
                    mma_bf16(S[nt], Qh[ks], Bh);
                    mma_bf16(S[nt], Qh[ks], Bl);
                    mma_bf16(S[nt], Ql[ks], Bh);
                }
            }

            // ---- causal mask on diagonal tile ----
            if (kt == gq) {
                const int r0 = wi * 16 + rloc;
#pragma unroll
                for (int nt = 0; nt < 8; nt++) {
                    const int c0 = nt * 8 + q2;
                    if (c0 > r0)     S[nt][0] = -1e30f;
                    if (c0 + 1 > r0) S[nt][1] = -1e30f;
                    if (c0 > r0 + 8)     S[nt][2] = -1e30f;
                    if (c0 + 1 > r0 + 8) S[nt][3] = -1e30f;
                }
            }

            // ---- online softmax (rows r0, r0+8; quad reduction) ----
            float mx0 = -1e30f, mx1 = -1e30f;
#pragma unroll
            for (int nt = 0; nt < 8; nt++) {
                mx0 = fmaxf(mx0, fmaxf(S[nt][0], S[nt][1]));
                mx1 = fmaxf(mx1, fmaxf(S[nt][2], S[nt][3]));
            }
            mx0 = fmaxf(mx0, __shfl_xor_sync(0xffffffffu, mx0, 1));
            mx0 = fmaxf(mx0, __shfl_xor_sync(0xffffffffu, mx0, 2));
            mx1 = fmaxf(mx1, __shfl_xor_sync(0xffffffffu, mx1, 1));
            mx1 = fmaxf(mx1, __shfl_xor_sync(0xffffffffu, mx1, 2));
            const float mn0 = fmaxf(m0, mx0);
            const float mn1 = fmaxf(m1, mx1);
            const float a0 = __expf(m0 - mn0);
            const float a1 = __expf(m1 - mn1);
            m0 = mn0; m1 = mn1;

            float sum0 = 0.0f, sum1 = 0.0f;
#pragma unroll
            for (int nt = 0; nt < 8; nt++) {
                S[nt][0] = __expf(S[nt][0] - mn0);
                S[nt][1] = __expf(S[nt][1] - mn0);
                S[nt][2] = __expf(S[nt][2] - mn1);
                S[nt][3] = __expf(S[nt][3] - mn1);
                sum0 += S[nt][0] + S[nt][1];
                sum1 += S[nt][2] + S[nt][3];
            }
            sum0 += __shfl_xor_sync(0xffffffffu, sum0, 1);
            sum0 += __shfl_xor_sync(0xffffffffu, sum0, 2);
            sum1 += __shfl_xor_sync(0xffffffffu, sum1, 1);
            sum1 += __shfl_xor_sync(0xffffffffu, sum1, 2);
            l0 = l0 * a0 + sum0;
            l1 = l1 * a1 + sum1;

#pragma unroll
            for (int nh = 0; nh < 8; nh++) {
                O[nh][0] *= a0; O[nh][1] *= a0;
                O[nh][2] *= a1; O[nh][3] *= a1;
            }

            // ---- O += P @ V ; P fragments built in registers ----
#pragma unroll
            for (int t = 0; t < 4; t++) {
                uint32_t Ph[4], Pl[4];
#pragma unroll
                for (int e = 0; e < 4; e++) {
                    const int nt = 2 * t + (e >> 1);
                    const int j  = (e & 1) * 2;
                    const float v0 = S[nt][j], v1 = S[nt][j + 1];
                    const __nv_bfloat16 h0 = __float2bfloat16_rn(v0);
                    const __nv_bfloat16 h1 = __float2bfloat16_rn(v1);
                    // A-frag order: {(r,k),(r,k+1)}, {(r+8,k)...}, {(r,k+8)...}, {(r+8,k+8)...}
                    const int slot = (e >> 1) * 2 + (e & 1);
                    Ph[slot] = ((uint32_t)__bfloat16_as_ushort(h1) << 16) |
                               __bfloat16_as_ushort(h0);
                    Pl[slot] = pack_bf16x2(v0 - __bfloat162float(h0),
                                           v1 - __bfloat162float(h1));
                }
#pragma unroll
                for (int nh = 0; nh < 8; nh++) {
                    const uint32_t voff =
                        swz128((uint32_t)(t * 16 + (lane & 15)) * 128u +
                               (uint32_t)nh * 16u);
                    uint32_t Vh[2], Vl[2];
                    ldsm_x2_trans(Vh, sVh + voff);
                    ldsm_x2_trans(Vl, sVl + voff);
                    mma_bf16(O[nh], Ph, Vh);
                    mma_bf16(O[nh], Ph, Vl);
                    mma_bf16(O[nh], Pl, Vh);
                }
            }
        }
        __syncthreads();
    }

    // ---- normalize + store ----
    const float il0 = 1.0f / l0;
    const float il1 = 1.0f / l1;
    const size_t grow = (size_t)b * T_ + (size_t)gq * 64 + wi * 16 + rloc;
#pragma unroll
    for (int nh = 0; nh < 8; nh++) {
        const int h = nh * 8 + q2;
        *(float2*)&out[grow * HD_ + h] =
            make_float2(O[nh][0] * il0, O[nh][1] * il0);
        *(float2*)&out[(grow + 8) * HD_ + h] =
            make_float2(O[nh][2] * il1, O[nh][3] * il1);
    }
}

// ---------------------------------------------------------------------------
extern "C" void kernel_launch(void* const* d_in, const int* in_sizes, int n_in,
                              void* d_out, int out_size)
{
    const float* x  = (const float*)d_in[0];
    const float* Wq = (const float*)d_in[1];
    const float* Wk = (const float*)d_in[2];
    const float* Wv = (const float*)d_in[3];
    float* out = (float*)d_out;

    cudaFuncSetAttribute(proj_mma_kernel,
                         cudaFuncAttributeMaxDynamicSharedMemorySize, PROJ_SMEM);
    cudaFuncSetAttribute(attn_mma_kernel,
                         cudaFuncAttributeMaxDynamicSharedMemorySize, ATTN_SMEM);

    const int prep_threads = NCHUNK_ * 8 * NTOT_;
    prep_w_kernel<<<(prep_threads + 255) / 256, 256>>>(Wq, Wk, Wv);
    proj_mma_kernel<<<M_ / 128, 256, PROJ_SMEM>>>(x);
    attn_mma_kernel<<<dim3(16, B_), 256, ATTN_SMEM>>>(out);
}

// round 5
// speedup vs baseline: 3.2740x; 1.1949x over previous
#include <cuda_runtime.h>
#include <cuda_bf16.h>
#include <cstdint>

// Problem constants
static constexpr int B_  = 8;
static constexpr int T_  = 2048;
static constexpr int D_  = 1024;
static constexpr int HD_ = 64;
static constexpr int M_  = B_ * T_;       // 16384 rows
static constexpr int NTOT_ = 192;         // q|k|v fused output columns
static constexpr int TK_ = 64;            // K per chunk (128B bf16 rows)
static constexpr int NCHUNK_ = D_ / TK_;  // 16

// Device-global scratch. q pre-scaled by 1/8; bf16 hi/lo pairs.
__device__ __align__(16) __nv_bfloat16 g_qhi[(size_t)M_ * HD_];
__device__ __align__(16) __nv_bfloat16 g_qlo[(size_t)M_ * HD_];
__device__ __align__(16) __nv_bfloat16 g_khi[(size_t)M_ * HD_];
__device__ __align__(16) __nv_bfloat16 g_klo[(size_t)M_ * HD_];
__device__ __align__(16) __nv_bfloat16 g_vhi[(size_t)M_ * HD_];
__device__ __align__(16) __nv_bfloat16 g_vlo[(size_t)M_ * HD_];
// Pre-transposed + swizzled bf16 W tiles: [chunk][n=0..191][k=0..63]
static constexpr size_t WTILE_BYTES = (size_t)NTOT_ * 128;   // 24576 per chunk
__device__ __align__(16) uint8_t g_bhi[(size_t)NCHUNK_ * WTILE_BYTES];
__device__ __align__(16) uint8_t g_blo[(size_t)NCHUNK_ * WTILE_BYTES];

__host__ __device__ __forceinline__ uint32_t swz128(uint32_t off) {
    return off ^ ((off >> 3) & 0x70);
}
__device__ __forceinline__ uint32_t smem_u32(const void* p) {
    uint32_t a;
    asm("{ .reg .u64 t; cvta.to.shared.u64 t, %1; cvt.u32.u64 %0, t; }"
        : "=r"(a) : "l"(p));
    return a;
}
__device__ __forceinline__ void ldsm_x4(uint32_t (&r)[4], uint32_t addr) {
    asm volatile("ldmatrix.sync.aligned.m8n8.x4.shared.b16 {%0,%1,%2,%3}, [%4];"
                 : "=r"(r[0]), "=r"(r[1]), "=r"(r[2]), "=r"(r[3]) : "r"(addr));
}
__device__ __forceinline__ void ldsm_x2(uint32_t (&r)[2], uint32_t addr) {
    asm volatile("ldmatrix.sync.aligned.m8n8.x2.shared.b16 {%0,%1}, [%2];"
                 : "=r"(r[0]), "=r"(r[1]) : "r"(addr));
}
__device__ __forceinline__ void ldsm_x2_trans(uint32_t (&r)[2], uint32_t addr) {
    asm volatile("ldmatrix.sync.aligned.m8n8.x2.trans.shared.b16 {%0,%1}, [%2];"
                 : "=r"(r[0]), "=r"(r[1]) : "r"(addr));
}
__device__ __forceinline__ void mma_bf16(float (&d)[4], const uint32_t (&a)[4],
                                         const uint32_t (&b)[2]) {
    asm volatile(
        "mma.sync.aligned.m16n8k16.row.col.f32.bf16.bf16.f32 "
        "{%0,%1,%2,%3}, {%4,%5,%6,%7}, {%8,%9}, {%0,%1,%2,%3};"
        : "+f"(d[0]), "+f"(d[1]), "+f"(d[2]), "+f"(d[3])
        : "r"(a[0]), "r"(a[1]), "r"(a[2]), "r"(a[3]), "r"(b[0]), "r"(b[1]));
}
__device__ __forceinline__ uint32_t pack_bf16x2(float lo, float hi) {
    __nv_bfloat16 l = __float2bfloat16_rn(lo);
    __nv_bfloat16 h = __float2bfloat16_rn(hi);
    return ((uint32_t)__bfloat16_as_ushort(h) << 16) | __bfloat16_as_ushort(l);
}
__device__ __forceinline__ void cp_async16(uint32_t dst, const void* src) {
    asm volatile("cp.async.ca.shared.global [%0], [%1], 16;"
                 :: "r"(dst), "l"(src));
}
#define CP_COMMIT() asm volatile("cp.async.commit_group;" ::: "memory")
#define CP_WAIT0()  asm volatile("cp.async.wait_group 0;" ::: "memory")
#define GROUP_BAR(id) asm volatile("bar.sync %0, 128;" :: "r"(id) : "memory")

// ---------------------------------------------------------------------------
// Kernel 0: W -> bf16 hi/lo, transposed to [n][k] rows, SW128 swizzled.
// ---------------------------------------------------------------------------
__global__ void prep_w_kernel(const float* __restrict__ Wq,
                              const float* __restrict__ Wk,
                              const float* __restrict__ Wv)
{
    const int t = blockIdx.x * blockDim.x + threadIdx.x;
    if (t >= NCHUNK_ * 8 * NTOT_) return;
    const int c = t % NTOT_;
    const int rest = t / NTOT_;
    const int kg = rest % 8;
    const int chunk = rest / 8;
    const int n = c & 63;
    const float* W = (c < 64) ? Wq : (c < 128) ? Wk : Wv;
    const int k0 = chunk * TK_ + kg * 8;

    float f[8];
#pragma unroll
    for (int j = 0; j < 8; j++) f[j] = W[(size_t)(k0 + j) * HD_ + n];

    uint32_t hw[4], lw[4];
#pragma unroll
    for (int j = 0; j < 4; j++) {
        const float a = f[2 * j], b = f[2 * j + 1];
        const __nv_bfloat16 ha = __float2bfloat16_rn(a);
        const __nv_bfloat16 hb = __float2bfloat16_rn(b);
        hw[j] = ((uint32_t)__bfloat16_as_ushort(hb) << 16) | __bfloat16_as_ushort(ha);
        lw[j] = pack_bf16x2(a - __bfloat162float(ha), b - __bfloat162float(hb));
    }
    const size_t base = (size_t)chunk * WTILE_BYTES;
    const uint32_t off = swz128((uint32_t)c * 128u + (uint32_t)kg * 16u);
    *(uint4*)(g_bhi + base + off) = make_uint4(hw[0], hw[1], hw[2], hw[3]);
    *(uint4*)(g_blo + base + off) = make_uint4(lw[0], lw[1], lw[2], lw[3]);
}

// ---------------------------------------------------------------------------
// Kernel 1: QKV projection via mma.sync bf16 (3-term split), 2-stage pipeline.
// B tiles copied with cp.async. Epilogue writes bf16 hi/lo q(x0.125), k, v.
// ---------------------------------------------------------------------------
static constexpr int A_TILE = 128 * 128;          // bytes
static constexpr int B_TILE = NTOT_ * 128;        // bytes
static constexpr int PROJ_STAGE = 2 * A_TILE + 2 * B_TILE;   // 81920
static constexpr int PROJ_SMEM = 1024 + 2 * PROJ_STAGE;

__global__ __launch_bounds__(256) void proj_mma_kernel(const float* __restrict__ x)
{
    extern __shared__ uint8_t dynsm[];
    const uint32_t raw = smem_u32(dynsm);
    const uint32_t base = (raw + 1023u) & ~1023u;
    uint8_t* const sm = dynsm + (base - raw);

    const int tid = threadIdx.x;
    const int wid = tid >> 5;
    const int lane = tid & 31;
    const int wm = wid >> 2;
    const int wn = wid & 3;
    const size_t row0g = (size_t)blockIdx.x * 128;

    float C[4][6][4];
#pragma unroll
    for (int mt = 0; mt < 4; mt++)
#pragma unroll
        for (int nt = 0; nt < 6; nt++)
#pragma unroll
            for (int e = 0; e < 4; e++) C[mt][nt][e] = 0.0f;

    const uint32_t a_row = (uint32_t)(lane & 15);
    const uint32_t a_kb  = (uint32_t)((lane >> 4) * 16);
    const uint32_t b_row = (uint32_t)(lane & 7);
    const uint32_t b_kb  = (uint32_t)(((lane >> 3) & 1) * 16);

    auto fillA = [&](int stage, int kc) {
        uint8_t* s = sm + stage * PROJ_STAGE;
#pragma unroll
        for (int i = 0; i < 8; i++) {
            const int idx = tid + i * 256;
            const int row = idx >> 4;
            const int c4  = idx & 15;
            float4 v = *(const float4*)&x[(row0g + row) * D_ + kc * TK_ + c4 * 4];
            const uint32_t h0 = pack_bf16x2(v.x, v.y);
            const uint32_t h1 = pack_bf16x2(v.z, v.w);
            const uint32_t l0 = pack_bf16x2(
                v.x - __bfloat162float(__float2bfloat16_rn(v.x)),
                v.y - __bfloat162float(__float2bfloat16_rn(v.y)));
            const uint32_t l1 = pack_bf16x2(
                v.z - __bfloat162float(__float2bfloat16_rn(v.z)),
                v.w - __bfloat162float(__float2bfloat16_rn(v.w)));
            const uint32_t off = swz128((uint32_t)row * 128u + (uint32_t)c4 * 8u);
            *(uint2*)(s + off)          = make_uint2(h0, h1);
            *(uint2*)(s + A_TILE + off) = make_uint2(l0, l1);
        }
    };
    auto cpB = [&](int stage, int kc) {
        const uint32_t sb = base + stage * PROJ_STAGE + 2 * A_TILE;
        const uint8_t* srcH = g_bhi + (size_t)kc * WTILE_BYTES;
        const uint8_t* srcL = g_blo + (size_t)kc * WTILE_BYTES;
#pragma unroll
        for (int i = 0; i < 6; i++) {
            const int idx = tid + i * 256;     // 0..1535
            cp_async16(sb + idx * 16, srcH + idx * 16);
            cp_async16(sb + B_TILE + idx * 16, srcL + idx * 16);
        }
    };

    fillA(0, 0); cpB(0, 0); CP_COMMIT(); CP_WAIT0();
    __syncthreads();

    for (int kc = 0; kc < NCHUNK_; kc++) {
        if (kc + 1 < NCHUNK_) {
            fillA((kc + 1) & 1, kc + 1);
            cpB((kc + 1) & 1, kc + 1);
            CP_COMMIT();
        }

        const uint32_t sb = base + (kc & 1) * PROJ_STAGE;
        const uint32_t sAhi = sb, sAlo = sb + A_TILE;
        const uint32_t sBhi = sb + 2 * A_TILE, sBlo = sb + 2 * A_TILE + B_TILE;

#pragma unroll
        for (int ks = 0; ks < 4; ks++) {
            uint32_t Ah[4][4], Al[4][4];
#pragma unroll
            for (int mt = 0; mt < 4; mt++) {
                const uint32_t roff =
                    swz128((uint32_t)(wm * 64 + mt * 16 + a_row) * 128u +
                           (uint32_t)ks * 32u + a_kb);
                ldsm_x4(Ah[mt], sAhi + roff);
                ldsm_x4(Al[mt], sAlo + roff);
            }
#pragma unroll
            for (int nt = 0; nt < 6; nt++) {
                const uint32_t boff =
                    swz128((uint32_t)(wn * 48 + nt * 8 + b_row) * 128u +
                           (uint32_t)ks * 32u + b_kb);
                uint32_t Bh[2], Bl[2];
                ldsm_x2(Bh, sBhi + boff);
                ldsm_x2(Bl, sBlo + boff);
#pragma unroll
                for (int mt = 0; mt < 4; mt++) {
                    mma_bf16(C[mt][nt], Ah[mt], Bh);
                    mma_bf16(C[mt][nt], Ah[mt], Bl);
                    mma_bf16(C[mt][nt], Al[mt], Bh);
                }
            }
        }
        if (kc + 1 < NCHUNK_) CP_WAIT0();
        __syncthreads();
    }

    // Epilogue: split to bf16 hi/lo; q pre-scaled by 0.125
#pragma unroll
    for (int mt = 0; mt < 4; mt++) {
        const size_t r = row0g + wm * 64 + mt * 16 + (lane >> 2);
#pragma unroll
        for (int nt = 0; nt < 6; nt++) {
            const int c = wn * 48 + nt * 8 + 2 * (lane & 3);
            const int n = c & 63;
            __nv_bfloat16 *ohi, *olo;
            float sc = 1.0f;
            if (c < 64)       { ohi = g_qhi; olo = g_qlo; sc = 0.125f; }
            else if (c < 128) { ohi = g_khi; olo = g_klo; }
            else              { ohi = g_vhi; olo = g_vlo; }
#pragma unroll
            for (int half = 0; half < 2; half++) {
                const size_t rr = r + half * 8;
                const float v0 = C[mt][nt][half * 2 + 0] * sc;
                const float v1 = C[mt][nt][half * 2 + 1] * sc;
                const __nv_bfloat16 h0 = __float2bfloat16_rn(v0);
                const __nv_bfloat16 h1 = __float2bfloat16_rn(v1);
                *(uint32_t*)&ohi[rr * HD_ + n] =
                    ((uint32_t)__bfloat16_as_ushort(h1) << 16) | __bfloat16_as_ushort(h0);
                *(uint32_t*)&olo[rr * HD_ + n] =
                    pack_bf16x2(v0 - __bfloat162float(h0), v1 - __bfloat162float(h1));
            }
        }
    }
}

// ---------------------------------------------------------------------------
// Kernel 2: flash attention, split-K across two warp groups + in-CTA merge.
// One CTA per (qt, b): group0 kt in [0,h), group1 kt in [h, qt], h=ceil((qt+1)/2).
// Blocks ordered largest-first (qt = 31 - bid/8).
// ---------------------------------------------------------------------------
static constexpr int Q_BYTES  = 2 * 64 * 128;       // 16384 (hi|lo)
static constexpr int KV_STAGE = 4 * 64 * 128;       // 32768
static constexpr int ATTN_SMEM = 1024 + Q_BYTES + 4 * KV_STAGE;  // ~145K

__global__ __launch_bounds__(256) void attn_mma_kernel(float* __restrict__ out)
{
    extern __shared__ uint8_t dynsm[];
    const uint32_t raw = smem_u32(dynsm);
    const uint32_t base = (raw + 1023u) & ~1023u;
    uint8_t* const smp = dynsm + (base - raw);

    const int tid = threadIdx.x;
    const int wid = tid >> 5;
    const int lane = tid & 31;
    const int grp = wid >> 2;
    const int wi  = wid & 3;
    const int gt  = tid & 127;            // thread index within group

    const int bid = blockIdx.x;
    const int qt = 31 - (bid >> 3);       // largest work first
    const int b  = bid & 7;
    const int h  = (qt + 2) >> 1;         // ceil((qt+1)/2)
    const int kt0 = grp ? h : 0;
    const int niter = grp ? (qt + 1 - h) : h;

    const uint32_t sQ  = base;
    const uint32_t sKV = base + Q_BYTES + grp * 2 * KV_STAGE;
    const size_t qrow0 = (size_t)b * T_ + (size_t)qt * 64;

    // ---- Q via cp.async (256 threads, 1024 transfers) ----
#pragma unroll
    for (int i = 0; i < 4; i++) {
        const int idx = tid + i * 256;         // 0..1023
        const int part = idx >> 9;             // 0 hi, 1 lo
        const int row = (idx >> 3) & 63;
        const int c16 = idx & 7;
        const uint32_t doff = swz128((uint32_t)row * 128u + (uint32_t)c16 * 16u);
        const __nv_bfloat16* src = part ? g_qlo : g_qhi;
        cp_async16(sQ + part * 8192 + doff, &src[(qrow0 + row) * HD_ + c16 * 8]);
    }
    CP_COMMIT();

    auto prefetch_kv = [&](int kt, int stage) {
        const uint32_t sb = sKV + stage * KV_STAGE;
        const size_t krow0 = (size_t)b * T_ + (size_t)kt * 64;
#pragma unroll
        for (int i = 0; i < 16; i++) {
            const int idx = gt + i * 128;      // 0..2047
            const int arr = idx >> 9;          // 0 khi,1 klo,2 vhi,3 vlo
            const int row = (idx >> 3) & 63;
            const int c16 = idx & 7;
            const uint32_t doff = swz128((uint32_t)row * 128u + (uint32_t)c16 * 16u);
            const __nv_bfloat16* src =
                (arr == 0) ? g_khi : (arr == 1) ? g_klo : (arr == 2) ? g_vhi : g_vlo;
            cp_async16(sb + arr * 8192 + doff, &src[(krow0 + row) * HD_ + c16 * 8]);
        }
    };
    if (niter > 0) prefetch_kv(kt0, 0);
    CP_COMMIT();
    CP_WAIT0();
    __syncthreads();

    // ---- Q fragments (same rows for both groups: this CTA's single q-tile) ----
    uint32_t Qh[4][4], Ql[4][4];
    {
        const uint32_t a_row = (uint32_t)(lane & 15);
        const uint32_t a_kb  = (uint32_t)((lane >> 4) * 16);
#pragma unroll
        for (int ks = 0; ks < 4; ks++) {
            const uint32_t roff =
                swz128((uint32_t)(wi * 16 + a_row) * 128u + (uint32_t)ks * 32u + a_kb);
            ldsm_x4(Qh[ks], sQ + roff);
            ldsm_x4(Ql[ks], sQ + 8192 + roff);
        }
    }

    float O[8][4];
#pragma unroll
    for (int nh = 0; nh < 8; nh++)
#pragma unroll
        for (int e = 0; e < 4; e++) O[nh][e] = 0.0f;
    float m0 = -1e30f, m1 = -1e30f, l0 = 0.0f, l1 = 0.0f;

    const uint32_t b_row = (uint32_t)(lane & 7);
    const uint32_t b_kb  = (uint32_t)(((lane >> 3) & 1) * 16);
    const int q2 = 2 * (lane & 3);
    const int rloc = (lane >> 2);

    for (int i = 0; i < niter; i++) {
        if (i + 1 < niter) prefetch_kv(kt0 + i + 1, (i + 1) & 1);
        CP_COMMIT();

        const int kt = kt0 + i;
        const uint32_t sb = sKV + (i & 1) * KV_STAGE;
        const uint32_t sKh = sb, sKl = sb + 8192;
        const uint32_t sVh = sb + 16384, sVl = sb + 24576;

        // ---- S = Q @ K^T ----
        float S[8][4];
#pragma unroll
        for (int nt = 0; nt < 8; nt++)
#pragma unroll
            for (int e = 0; e < 4; e++) S[nt][e] = 0.0f;

#pragma unroll
        for (int ks = 0; ks < 4; ks++) {
#pragma unroll
            for (int nt = 0; nt < 8; nt++) {
                const uint32_t boff =
                    swz128((uint32_t)(nt * 8 + b_row) * 128u +
                           (uint32_t)ks * 32u + b_kb);
                uint32_t Bh[2], Bl[2];
                ldsm_x2(Bh, sKh + boff);
                ldsm_x2(Bl, sKl + boff);
                mma_bf16(S[nt], Qh[ks], Bh);
                mma_bf16(S[nt], Qh[ks], Bl);
                mma_bf16(S[nt], Ql[ks], Bh);
            }
        }

        // ---- causal mask on diagonal tile ----
        if (kt == qt) {
            const int r0 = wi * 16 + rloc;
#pragma unroll
            for (int nt = 0; nt < 8; nt++) {
                const int c0 = nt * 8 + q2;
                if (c0 > r0)     S[nt][0] = -1e30f;
                if (c0 + 1 > r0) S[nt][1] = -1e30f;
                if (c0 > r0 + 8)     S[nt][2] = -1e30f;
                if (c0 + 1 > r0 + 8) S[nt][3] = -1e30f;
            }
        }

        // ---- online softmax ----
        float mx0 = -1e30f, mx1 = -1e30f;
#pragma unroll
        for (int nt = 0; nt < 8; nt++) {
            mx0 = fmaxf(mx0, fmaxf(S[nt][0], S[nt][1]));
            mx1 = fmaxf(mx1, fmaxf(S[nt][2], S[nt][3]));
        }
        mx0 = fmaxf(mx0, __shfl_xor_sync(0xffffffffu, mx0, 1));
        mx0 = fmaxf(mx0, __shfl_xor_sync(0xffffffffu, mx0, 2));
        mx1 = fmaxf(mx1, __shfl_xor_sync(0xffffffffu, mx1, 1));
        mx1 = fmaxf(mx1, __shfl_xor_sync(0xffffffffu, mx1, 2));
        const float mn0 = fmaxf(m0, mx0);
        const float mn1 = fmaxf(m1, mx1);
        const float a0 = __expf(m0 - mn0);
        const float a1 = __expf(m1 - mn1);
        m0 = mn0; m1 = mn1;

        float sum0 = 0.0f, sum1 = 0.0f;
#pragma unroll
        for (int nt = 0; nt < 8; nt++) {
            S[nt][0] = __expf(S[nt][0] - mn0);
            S[nt][1] = __expf(S[nt][1] - mn0);
            S[nt][2] = __expf(S[nt][2] - mn1);
            S[nt][3] = __expf(S[nt][3] - mn1);
            sum0 += S[nt][0] + S[nt][1];
            sum1 += S[nt][2] + S[nt][3];
        }
        sum0 += __shfl_xor_sync(0xffffffffu, sum0, 1);
        sum0 += __shfl_xor_sync(0xffffffffu, sum0, 2);
        sum1 += __shfl_xor_sync(0xffffffffu, sum1, 1);
        sum1 += __shfl_xor_sync(0xffffffffu, sum1, 2);
        l0 = l0 * a0 + sum0;
        l1 = l1 * a1 + sum1;

#pragma unroll
        for (int nh = 0; nh < 8; nh++) {
            O[nh][0] *= a0; O[nh][1] *= a0;
            O[nh][2] *= a1; O[nh][3] *= a1;
        }

        // ---- O += P @ V ----
#pragma unroll
        for (int t = 0; t < 4; t++) {
            uint32_t Ph[4], Pl[4];
#pragma unroll
            for (int e = 0; e < 4; e++) {
                const int nt = 2 * t + (e >> 1);
                const int j  = (e & 1) * 2;
                const float v0 = S[nt][j], v1 = S[nt][j + 1];
                const __nv_bfloat16 h0 = __float2bfloat16_rn(v0);
                const __nv_bfloat16 h1 = __float2bfloat16_rn(v1);
                const int slot = (e >> 1) * 2 + (e & 1);
                Ph[slot] = ((uint32_t)__bfloat16_as_ushort(h1) << 16) |
                           __bfloat16_as_ushort(h0);
                Pl[slot] = pack_bf16x2(v0 - __bfloat162float(h0),
                                       v1 - __bfloat162float(h1));
            }
#pragma unroll
            for (int nh = 0; nh < 8; nh++) {
                const uint32_t voff =
                    swz128((uint32_t)(t * 16 + (lane & 15)) * 128u +
                           (uint32_t)nh * 16u);
                uint32_t Vh[2], Vl[2];
                ldsm_x2_trans(Vh, sVh + voff);
                ldsm_x2_trans(Vl, sVl + voff);
                mma_bf16(O[nh], Ph, Vh);
                mma_bf16(O[nh], Ph, Vl);
                mma_bf16(O[nh], Pl, Vh);
            }
        }

        CP_WAIT0();
        GROUP_BAR(1 + grp);
    }

    // ---- split-softmax merge: group1 -> smem, group0 combines + stores ----
    float* const mO  = (float*)(smp + Q_BYTES + 2 * KV_STAGE);   // group1 stage0
    float* const mML = mO + 128 * 32;
    const int slot = wi * 32 + lane;

    if (grp == 1) {
#pragma unroll
        for (int nh = 0; nh < 8; nh++)
#pragma unroll
            for (int e = 0; e < 4; e++) mO[slot * 32 + nh * 4 + e] = O[nh][e];
        mML[slot * 4 + 0] = m0;
        mML[slot * 4 + 1] = l0;
        mML[slot * 4 + 2] = m1;
        mML[slot * 4 + 3] = l1;
    }
    __syncthreads();

    if (grp == 0) {
        const float pm0 = mML[slot * 4 + 0];
        const float pl0 = mML[slot * 4 + 1];
        const float pm1 = mML[slot * 4 + 2];
        const float pl1 = mML[slot * 4 + 3];

        const float M0 = fmaxf(m0, pm0);
        const float M1 = fmaxf(m1, pm1);
        const float a0 = __expf(m0 - M0), pa0 = __expf(pm0 - M0);
        const float a1 = __expf(m1 - M1), pa1 = __expf(pm1 - M1);
        const float il0 = 1.0f / (l0 * a0 + pl0 * pa0);
        const float il1 = 1.0f / (l1 * a1 + pl1 * pa1);

        const size_t grow = qrow0 + (size_t)(wi * 16 + rloc);
#pragma unroll
        for (int nh = 0; nh < 8; nh++) {
            const int hcol = nh * 8 + q2;
            const float p0 = mO[slot * 32 + nh * 4 + 0];
            const float p1 = mO[slot * 32 + nh * 4 + 1];
            const float p2 = mO[slot * 32 + nh * 4 + 2];
            const float p3 = mO[slot * 32 + nh * 4 + 3];
            *(float2*)&out[grow * HD_ + hcol] =
                make_float2((O[nh][0] * a0 + p0 * pa0) * il0,
                            (O[nh][1] * a0 + p1 * pa0) * il0);
            *(float2*)&out[(grow + 8) * HD_ + hcol] =
                make_float2((O[nh][2] * a1 + p2 * pa1) * il1,
                            (O[nh][3] * a1 + p3 * pa1) * il1);
        }
    }
}

// ---------------------------------------------------------------------------
extern "C" void kernel_launch(void* const* d_in, const int* in_sizes, int n_in,
                              void* d_out, int out_size)
{
    const float* x  = (const float*)d_in[0];
    const float* Wq = (const float*)d_in[1];
    const float* Wk = (const float*)d_in[2];
    const float* Wv = (const float*)d_in[3];
    float* out = (float*)d_out;

    cudaFuncSetAttribute(proj_mma_kernel,
                         cudaFuncAttributeMaxDynamicSharedMemorySize, PROJ_SMEM);
    cudaFuncSetAttribute(attn_mma_kernel,
                         cudaFuncAttributeMaxDynamicSharedMemorySize, ATTN_SMEM);

    const int prep_threads = NCHUNK_ * 8 * NTOT_;
    prep_w_kernel<<<(prep_threads + 255) / 256, 256>>>(Wq, Wk, Wv);
    proj_mma_kernel<<<M_ / 128, 256, PROJ_SMEM>>>(x);
    attn_mma_kernel<<<256, 256, ATTN_SMEM>>>(out);
}

// round 6
// speedup vs baseline: 3.9027x; 1.1921x over previous
#include <cuda_runtime.h>
#include <cuda_fp16.h>
#include <cstdint>

// Problem constants
static constexpr int B_  = 8;
static constexpr int T_  = 2048;
static constexpr int D_  = 1024;
static constexpr int HD_ = 64;
static constexpr int M_  = B_ * T_;       // 16384 rows
static constexpr int NTOT_ = 192;         // q|k|v fused output columns
static constexpr int TK_ = 64;            // K per chunk (128B fp16 rows)
static constexpr int NCHUNK_ = D_ / TK_;  // 16

// Device-global scratch (fp16). q pre-scaled by 0.125*log2e, hi/lo split.
// k, v stored hi-only (2-term attention math).
__device__ __align__(16) __half g_qhi[(size_t)M_ * HD_];
__device__ __align__(16) __half g_qlo[(size_t)M_ * HD_];
__device__ __align__(16) __half g_khi[(size_t)M_ * HD_];
__device__ __align__(16) __half g_vhi[(size_t)M_ * HD_];
// Pre-transposed + swizzled fp16 W tiles: [chunk][n=0..191][k=0..63]
static constexpr size_t WTILE_BYTES = (size_t)NTOT_ * 128;   // 24576 per chunk
__device__ __align__(16) uint8_t g_bhi[(size_t)NCHUNK_ * WTILE_BYTES];
__device__ __align__(16) uint8_t g_blo[(size_t)NCHUNK_ * WTILE_BYTES];

__host__ __device__ __forceinline__ uint32_t swz128(uint32_t off) {
    return off ^ ((off >> 3) & 0x70);
}
__device__ __forceinline__ uint32_t smem_u32(const void* p) {
    uint32_t a;
    asm("{ .reg .u64 t; cvta.to.shared.u64 t, %1; cvt.u32.u64 %0, t; }"
        : "=r"(a) : "l"(p));
    return a;
}
__device__ __forceinline__ void ldsm_x4(uint32_t (&r)[4], uint32_t addr) {
    asm volatile("ldmatrix.sync.aligned.m8n8.x4.shared.b16 {%0,%1,%2,%3}, [%4];"
                 : "=r"(r[0]), "=r"(r[1]), "=r"(r[2]), "=r"(r[3]) : "r"(addr));
}
__device__ __forceinline__ void ldsm_x2(uint32_t (&r)[2], uint32_t addr) {
    asm volatile("ldmatrix.sync.aligned.m8n8.x2.shared.b16 {%0,%1}, [%2];"
                 : "=r"(r[0]), "=r"(r[1]) : "r"(addr));
}
__device__ __forceinline__ void ldsm_x2_trans(uint32_t (&r)[2], uint32_t addr) {
    asm volatile("ldmatrix.sync.aligned.m8n8.x2.trans.shared.b16 {%0,%1}, [%2];"
                 : "=r"(r[0]), "=r"(r[1]) : "r"(addr));
}
__device__ __forceinline__ void mma_f16(float (&d)[4], const uint32_t (&a)[4],
                                        const uint32_t (&b)[2]) {
    asm volatile(
        "mma.sync.aligned.m16n8k16.row.col.f32.f16.f16.f32 "
        "{%0,%1,%2,%3}, {%4,%5,%6,%7}, {%8,%9}, {%0,%1,%2,%3};"
        : "+f"(d[0]), "+f"(d[1]), "+f"(d[2]), "+f"(d[3])
        : "r"(a[0]), "r"(a[1]), "r"(a[2]), "r"(a[3]), "r"(b[0]), "r"(b[1]));
}
__device__ __forceinline__ uint32_t pack_h2(float lo, float hi) {
    __half l = __float2half_rn(lo);
    __half h = __float2half_rn(hi);
    return ((uint32_t)__half_as_ushort(h) << 16) | __half_as_ushort(l);
}
__device__ __forceinline__ float ex2f(float x) {
    float y;
    asm("ex2.approx.ftz.f32 %0, %1;" : "=f"(y) : "f"(x));
    return y;
}
__device__ __forceinline__ void cp_async16(uint32_t dst, const void* src) {
    asm volatile("cp.async.ca.shared.global [%0], [%1], 16;"
                 :: "r"(dst), "l"(src));
}
#define CP_COMMIT() asm volatile("cp.async.commit_group;" ::: "memory")
#define CP_WAIT0()  asm volatile("cp.async.wait_group 0;" ::: "memory")
#define GROUP_BAR(id) asm volatile("bar.sync %0, 128;" :: "r"(id) : "memory")

static constexpr float SCALE_Q = 0.125f * 1.4426950408889634f;  // 1/sqrt(64)*log2e

// ---------------------------------------------------------------------------
// Kernel 0: W -> fp16 hi/lo, transposed to [n][k] rows, SW128 swizzled.
// ---------------------------------------------------------------------------
__global__ void prep_w_kernel(const float* __restrict__ Wq,
                              const float* __restrict__ Wk,
                              const float* __restrict__ Wv)
{
    const int t = blockIdx.x * blockDim.x + threadIdx.x;
    if (t >= NCHUNK_ * 8 * NTOT_) return;
    const int c = t % NTOT_;
    const int rest = t / NTOT_;
    const int kg = rest % 8;
    const int chunk = rest / 8;
    const int n = c & 63;
    const float* W = (c < 64) ? Wq : (c < 128) ? Wk : Wv;
    const int k0 = chunk * TK_ + kg * 8;

    float f[8];
#pragma unroll
    for (int j = 0; j < 8; j++) f[j] = W[(size_t)(k0 + j) * HD_ + n];

    uint32_t hw[4], lw[4];
#pragma unroll
    for (int j = 0; j < 4; j++) {
        const float a = f[2 * j], b = f[2 * j + 1];
        const __half ha = __float2half_rn(a);
        const __half hb = __float2half_rn(b);
        hw[j] = ((uint32_t)__half_as_ushort(hb) << 16) | __half_as_ushort(ha);
        lw[j] = pack_h2(a - __half2float(ha), b - __half2float(hb));
    }
    const size_t base = (size_t)chunk * WTILE_BYTES;
    const uint32_t off = swz128((uint32_t)c * 128u + (uint32_t)kg * 16u);
    *(uint4*)(g_bhi + base + off) = make_uint4(hw[0], hw[1], hw[2], hw[3]);
    *(uint4*)(g_blo + base + off) = make_uint4(lw[0], lw[1], lw[2], lw[3]);
}

// ---------------------------------------------------------------------------
// Kernel 1: QKV projection, mma.sync fp16, 3-term split, 2-stage pipeline.
// Epilogue: qhi/qlo (x SCALE_Q), khi, vhi.
// ---------------------------------------------------------------------------
static constexpr int A_TILE = 128 * 128;          // bytes
static constexpr int B_TILE = NTOT_ * 128;        // bytes
static constexpr int PROJ_STAGE = 2 * A_TILE + 2 * B_TILE;   // 81920
static constexpr int PROJ_SMEM = 1024 + 2 * PROJ_STAGE;

__global__ __launch_bounds__(256) void proj_mma_kernel(const float* __restrict__ x)
{
    extern __shared__ uint8_t dynsm[];
    const uint32_t raw = smem_u32(dynsm);
    const uint32_t base = (raw + 1023u) & ~1023u;
    uint8_t* const sm = dynsm + (base - raw);

    const int tid = threadIdx.x;
    const int wid = tid >> 5;
    const int lane = tid & 31;
    const int wm = wid >> 2;
    const int wn = wid & 3;
    const size_t row0g = (size_t)blockIdx.x * 128;

    float C[4][6][4];
#pragma unroll
    for (int mt = 0; mt < 4; mt++)
#pragma unroll
        for (int nt = 0; nt < 6; nt++)
#pragma unroll
            for (int e = 0; e < 4; e++) C[mt][nt][e] = 0.0f;

    const uint32_t a_row = (uint32_t)(lane & 15);
    const uint32_t a_kb  = (uint32_t)((lane >> 4) * 16);
    const uint32_t b_row = (uint32_t)(lane & 7);
    const uint32_t b_kb  = (uint32_t)(((lane >> 3) & 1) * 16);

    auto fillA = [&](int stage, int kc) {
        uint8_t* s = sm + stage * PROJ_STAGE;
#pragma unroll
        for (int i = 0; i < 8; i++) {
            const int idx = tid + i * 256;
            const int row = idx >> 4;
            const int c4  = idx & 15;
            float4 v = *(const float4*)&x[(row0g + row) * D_ + kc * TK_ + c4 * 4];
            const __half hx = __float2half_rn(v.x);
            const __half hy = __float2half_rn(v.y);
            const __half hz = __float2half_rn(v.z);
            const __half hw = __float2half_rn(v.w);
            const uint32_t h0 = ((uint32_t)__half_as_ushort(hy) << 16) | __half_as_ushort(hx);
            const uint32_t h1 = ((uint32_t)__half_as_ushort(hw) << 16) | __half_as_ushort(hz);
            const uint32_t l0 = pack_h2(v.x - __half2float(hx), v.y - __half2float(hy));
            const uint32_t l1 = pack_h2(v.z - __half2float(hz), v.w - __half2float(hw));
            const uint32_t off = swz128((uint32_t)row * 128u + (uint32_t)c4 * 8u);
            *(uint2*)(s + off)          = make_uint2(h0, h1);
            *(uint2*)(s + A_TILE + off) = make_uint2(l0, l1);
        }
    };
    auto cpB = [&](int stage, int kc) {
        const uint32_t sb = base + stage * PROJ_STAGE + 2 * A_TILE;
        const uint8_t* srcH = g_bhi + (size_t)kc * WTILE_BYTES;
        const uint8_t* srcL = g_blo + (size_t)kc * WTILE_BYTES;
#pragma unroll
        for (int i = 0; i < 6; i++) {
            const int idx = tid + i * 256;
            cp_async16(sb + idx * 16, srcH + idx * 16);
            cp_async16(sb + B_TILE + idx * 16, srcL + idx * 16);
        }
    };

    fillA(0, 0); cpB(0, 0); CP_COMMIT(); CP_WAIT0();
    __syncthreads();

    for (int kc = 0; kc < NCHUNK_; kc++) {
        if (kc + 1 < NCHUNK_) {
            fillA((kc + 1) & 1, kc + 1);
            cpB((kc + 1) & 1, kc + 1);
            CP_COMMIT();
        }

        const uint32_t sb = base + (kc & 1) * PROJ_STAGE;
        const uint32_t sAhi = sb, sAlo = sb + A_TILE;
        const uint32_t sBhi = sb + 2 * A_TILE, sBlo = sb + 2 * A_TILE + B_TILE;

#pragma unroll
        for (int ks = 0; ks < 4; ks++) {
            uint32_t Ah[4][4], Al[4][4];
#pragma unroll
            for (int mt = 0; mt < 4; mt++) {
                const uint32_t roff =
                    swz128((uint32_t)(wm * 64 + mt * 16 + a_row) * 128u +
                           (uint32_t)ks * 32u + a_kb);
                ldsm_x4(Ah[mt], sAhi + roff);
                ldsm_x4(Al[mt], sAlo + roff);
            }
#pragma unroll
            for (int nt = 0; nt < 6; nt++) {
                const uint32_t boff =
                    swz128((uint32_t)(wn * 48 + nt * 8 + b_row) * 128u +
                           (uint32_t)ks * 32u + b_kb);
                uint32_t Bh[2], Bl[2];
                ldsm_x2(Bh, sBhi + boff);
                ldsm_x2(Bl, sBlo + boff);
#pragma unroll
                for (int mt = 0; mt < 4; mt++) {
                    mma_f16(C[mt][nt], Ah[mt], Bh);
                    mma_f16(C[mt][nt], Ah[mt], Bl);
                    mma_f16(C[mt][nt], Al[mt], Bh);
                }
            }
        }
        if (kc + 1 < NCHUNK_) CP_WAIT0();
        __syncthreads();
    }

    // Epilogue
#pragma unroll
    for (int mt = 0; mt < 4; mt++) {
        const size_t r = row0g + wm * 64 + mt * 16 + (lane >> 2);
#pragma unroll
        for (int nt = 0; nt < 6; nt++) {
            const int c = wn * 48 + nt * 8 + 2 * (lane & 3);
            const int n = c & 63;
#pragma unroll
            for (int half = 0; half < 2; half++) {
                const size_t rr = r + half * 8;
                float v0 = C[mt][nt][half * 2 + 0];
                float v1 = C[mt][nt][half * 2 + 1];
                if (c < 64) {
                    v0 *= SCALE_Q; v1 *= SCALE_Q;
                    const __half h0 = __float2half_rn(v0);
                    const __half h1 = __float2half_rn(v1);
                    *(uint32_t*)&g_qhi[rr * HD_ + n] =
                        ((uint32_t)__half_as_ushort(h1) << 16) | __half_as_ushort(h0);
                    *(uint32_t*)&g_qlo[rr * HD_ + n] =
                        pack_h2(v0 - __half2float(h0), v1 - __half2float(h1));
                } else {
                    __half* o = (c < 128) ? g_khi : g_vhi;
                    *(uint32_t*)&o[rr * HD_ + n] = pack_h2(v0, v1);
                }
            }
        }
    }
}

// ---------------------------------------------------------------------------
// Kernel 2: flash attention fp16 2-term, split-K two warp groups + merge.
// KV stage = khi(8K) + vhi(8K). exp2-domain softmax.
// ---------------------------------------------------------------------------
static constexpr int Q_BYTES  = 2 * 64 * 128;       // 16384 (hi|lo)
static constexpr int KV_STAGE = 2 * 64 * 128;       // 16384 (khi|vhi)
static constexpr int ATTN_SMEM = 1024 + Q_BYTES + 4 * KV_STAGE;  // ~83K

__global__ __launch_bounds__(256) void attn_mma_kernel(float* __restrict__ out)
{
    extern __shared__ uint8_t dynsm[];
    const uint32_t raw = smem_u32(dynsm);
    const uint32_t base = (raw + 1023u) & ~1023u;
    uint8_t* const smp = dynsm + (base - raw);

    const int tid = threadIdx.x;
    const int wid = tid >> 5;
    const int lane = tid & 31;
    const int grp = wid >> 2;
    const int wi  = wid & 3;
    const int gt  = tid & 127;

    const int bid = blockIdx.x;
    const int qt = 31 - (bid >> 3);       // largest work first
    const int b  = bid & 7;
    const int h  = (qt + 2) >> 1;
    const int kt0 = grp ? h : 0;
    const int niter = grp ? (qt + 1 - h) : h;

    const uint32_t sQ  = base;
    const uint32_t sKV = base + Q_BYTES + grp * 2 * KV_STAGE;
    const size_t qrow0 = (size_t)b * T_ + (size_t)qt * 64;

    // ---- Q via cp.async ----
#pragma unroll
    for (int i = 0; i < 4; i++) {
        const int idx = tid + i * 256;
        const int part = idx >> 9;
        const int row = (idx >> 3) & 63;
        const int c16 = idx & 7;
        const uint32_t doff = swz128((uint32_t)row * 128u + (uint32_t)c16 * 16u);
        const __half* src = part ? g_qlo : g_qhi;
        cp_async16(sQ + part * 8192 + doff, &src[(qrow0 + row) * HD_ + c16 * 8]);
    }
    CP_COMMIT();

    auto prefetch_kv = [&](int kt, int stage) {
        const uint32_t sb = sKV + stage * KV_STAGE;
        const size_t krow0 = (size_t)b * T_ + (size_t)kt * 64;
#pragma unroll
        for (int i = 0; i < 8; i++) {
            const int idx = gt + i * 128;      // 0..1023
            const int arr = idx >> 9;          // 0 khi, 1 vhi
            const int row = (idx >> 3) & 63;
            const int c16 = idx & 7;
            const uint32_t doff = swz128((uint32_t)row * 128u + (uint32_t)c16 * 16u);
            const __half* src = arr ? g_vhi : g_khi;
            cp_async16(sb + arr * 8192 + doff, &src[(krow0 + row) * HD_ + c16 * 8]);
        }
    };
    if (niter > 0) prefetch_kv(kt0, 0);
    CP_COMMIT();
    CP_WAIT0();
    __syncthreads();

    // ---- Q fragments ----
    uint32_t Qh[4][4], Ql[4][4];
    {
        const uint32_t a_row = (uint32_t)(lane & 15);
        const uint32_t a_kb  = (uint32_t)((lane >> 4) * 16);
#pragma unroll
        for (int ks = 0; ks < 4; ks++) {
            const uint32_t roff =
                swz128((uint32_t)(wi * 16 + a_row) * 128u + (uint32_t)ks * 32u + a_kb);
            ldsm_x4(Qh[ks], sQ + roff);
            ldsm_x4(Ql[ks], sQ + 8192 + roff);
        }
    }

    float O[8][4];
#pragma unroll
    for (int nh = 0; nh < 8; nh++)
#pragma unroll
        for (int e = 0; e < 4; e++) O[nh][e] = 0.0f;
    float m0 = -1e30f, m1 = -1e30f, l0 = 0.0f, l1 = 0.0f;

    const uint32_t b_row = (uint32_t)(lane & 7);
    const uint32_t b_kb  = (uint32_t)(((lane >> 3) & 1) * 16);
    const int q2 = 2 * (lane & 3);
    const int rloc = (lane >> 2);

    for (int i = 0; i < niter; i++) {
        if (i + 1 < niter) prefetch_kv(kt0 + i + 1, (i + 1) & 1);
        CP_COMMIT();

        const int kt = kt0 + i;
        const uint32_t sb = sKV + (i & 1) * KV_STAGE;
        const uint32_t sKh = sb;
        const uint32_t sVh = sb + 8192;

        // ---- S = Q @ K^T (logits already in log2 domain) ----
        float S[8][4];
#pragma unroll
        for (int nt = 0; nt < 8; nt++)
#pragma unroll
            for (int e = 0; e < 4; e++) S[nt][e] = 0.0f;

#pragma unroll
        for (int ks = 0; ks < 4; ks++) {
#pragma unroll
            for (int nt = 0; nt < 8; nt++) {
                const uint32_t boff =
                    swz128((uint32_t)(nt * 8 + b_row) * 128u +
                           (uint32_t)ks * 32u + b_kb);
                uint32_t Bh[2];
                ldsm_x2(Bh, sKh + boff);
                mma_f16(S[nt], Qh[ks], Bh);
                mma_f16(S[nt], Ql[ks], Bh);
            }
        }

        // ---- causal mask on diagonal tile ----
        if (kt == qt) {
            const int r0 = wi * 16 + rloc;
#pragma unroll
            for (int nt = 0; nt < 8; nt++) {
                const int c0 = nt * 8 + q2;
                if (c0 > r0)     S[nt][0] = -1e30f;
                if (c0 + 1 > r0) S[nt][1] = -1e30f;
                if (c0 > r0 + 8)     S[nt][2] = -1e30f;
                if (c0 + 1 > r0 + 8) S[nt][3] = -1e30f;
            }
        }

        // ---- online softmax (base-2) ----
        float mx0 = -1e30f, mx1 = -1e30f;
#pragma unroll
        for (int nt = 0; nt < 8; nt++) {
            mx0 = fmaxf(mx0, fmaxf(S[nt][0], S[nt][1]));
            mx1 = fmaxf(mx1, fmaxf(S[nt][2], S[nt][3]));
        }
        mx0 = fmaxf(mx0, __shfl_xor_sync(0xffffffffu, mx0, 1));
        mx0 = fmaxf(mx0, __shfl_xor_sync(0xffffffffu, mx0, 2));
        mx1 = fmaxf(mx1, __shfl_xor_sync(0xffffffffu, mx1, 1));
        mx1 = fmaxf(mx1, __shfl_xor_sync(0xffffffffu, mx1, 2));
        const float mn0 = fmaxf(m0, mx0);
        const float mn1 = fmaxf(m1, mx1);
        const float a0 = ex2f(m0 - mn0);
        const float a1 = ex2f(m1 - mn1);
        m0 = mn0; m1 = mn1;

        float sum0 = 0.0f, sum1 = 0.0f;
#pragma unroll
        for (int nt = 0; nt < 8; nt++) {
            S[nt][0] = ex2f(S[nt][0] - mn0);
            S[nt][1] = ex2f(S[nt][1] - mn0);
            S[nt][2] = ex2f(S[nt][2] - mn1);
            S[nt][3] = ex2f(S[nt][3] - mn1);
            sum0 += S[nt][0] + S[nt][1];
            sum1 += S[nt][2] + S[nt][3];
        }
        sum0 += __shfl_xor_sync(0xffffffffu, sum0, 1);
        sum0 += __shfl_xor_sync(0xffffffffu, sum0, 2);
        sum1 += __shfl_xor_sync(0xffffffffu, sum1, 1);
        sum1 += __shfl_xor_sync(0xffffffffu, sum1, 2);
        l0 = l0 * a0 + sum0;
        l1 = l1 * a1 + sum1;

#pragma unroll
        for (int nh = 0; nh < 8; nh++) {
            O[nh][0] *= a0; O[nh][1] *= a0;
            O[nh][2] *= a1; O[nh][3] *= a1;
        }

        // ---- O += P @ V (P hi/lo fp16, V hi only) ----
#pragma unroll
        for (int t = 0; t < 4; t++) {
            uint32_t Ph[4], Pl[4];
#pragma unroll
            for (int e = 0; e < 4; e++) {
                const int nt = 2 * t + (e >> 1);
                const int j  = (e & 1) * 2;
                const float v0 = S[nt][j], v1 = S[nt][j + 1];
                const __half h0 = __float2half_rn(v0);
                const __half h1 = __float2half_rn(v1);
                const int slot = (e >> 1) * 2 + (e & 1);
                Ph[slot] = ((uint32_t)__half_as_ushort(h1) << 16) |
                           __half_as_ushort(h0);
                Pl[slot] = pack_h2(v0 - __half2float(h0),
                                   v1 - __half2float(h1));
            }
#pragma unroll
            for (int nh = 0; nh < 8; nh++) {
                const uint32_t voff =
                    swz128((uint32_t)(t * 16 + (lane & 15)) * 128u +
                           (uint32_t)nh * 16u);
                uint32_t Vh[2];
                ldsm_x2_trans(Vh, sVh + voff);
                mma_f16(O[nh], Ph, Vh);
                mma_f16(O[nh], Pl, Vh);
            }
        }

        CP_WAIT0();
        GROUP_BAR(1 + grp);
    }

    // ---- split-softmax merge (group1 region reused as buffers) ----
    float* const mO  = (float*)(smp + Q_BYTES + 2 * KV_STAGE);
    float* const mML = mO + 128 * 32;
    const int slot = wi * 32 + lane;

    if (grp == 1) {
#pragma unroll
        for (int nh = 0; nh < 8; nh++)
#pragma unroll
            for (int e = 0; e < 4; e++) mO[slot * 32 + nh * 4 + e] = O[nh][e];
        mML[slot * 4 + 0] = m0;
        mML[slot * 4 + 1] = l0;
        mML[slot * 4 + 2] = m1;
        mML[slot * 4 + 3] = l1;
    }
    __syncthreads();

    if (grp == 0) {
        const float pm0 = mML[slot * 4 + 0];
        const float pl0 = mML[slot * 4 + 1];
        const float pm1 = mML[slot * 4 + 2];
        const float pl1 = mML[slot * 4 + 3];

        const float M0 = fmaxf(m0, pm0);
        const float M1 = fmaxf(m1, pm1);
        const float a0 = ex2f(m0 - M0), pa0 = ex2f(pm0 - M0);
        const float a1 = ex2f(m1 - M1), pa1 = ex2f(pm1 - M1);
        const float il0 = 1.0f / (l0 * a0 + pl0 * pa0);
        const float il1 = 1.0f / (l1 * a1 + pl1 * pa1);

        const size_t grow = qrow0 + (size_t)(wi * 16 + rloc);
#pragma unroll
        for (int nh = 0; nh < 8; nh++) {
            const int hcol = nh * 8 + q2;
            const float p0 = mO[slot * 32 + nh * 4 + 0];
            const float p1 = mO[slot * 32 + nh * 4 + 1];
            const float p2 = mO[slot * 32 + nh * 4 + 2];
            const float p3 = mO[slot * 32 + nh * 4 + 3];
            *(float2*)&out[grow * HD_ + hcol] =
                make_float2((O[nh][0] * a0 + p0 * pa0) * il0,
                            (O[nh][1] * a0 + p1 * pa0) * il0);
            *(float2*)&out[(grow + 8) * HD_ + hcol] =
                make_float2((O[nh][2] * a1 + p2 * pa1) * il1,
                            (O[nh][3] * a1 + p3 * pa1) * il1);
        }
    }
}

// ---------------------------------------------------------------------------
extern "C" void kernel_launch(void* const* d_in, const int* in_sizes, int n_in,
                              void* d_out, int out_size)
{
    const float* x  = (const float*)d_in[0];
    const float* Wq = (const float*)d_in[1];
    const float* Wk = (const float*)d_in[2];
    const float* Wv = (const float*)d_in[3];
    float* out = (float*)d_out;

    cudaFuncSetAttribute(proj_mma_kernel,
                         cudaFuncAttributeMaxDynamicSharedMemorySize, PROJ_SMEM);
    cudaFuncSetAttribute(attn_mma_kernel,
                         cudaFuncAttributeMaxDynamicSharedMemorySize, ATTN_SMEM);

    const int prep_threads = NCHUNK_ * 8 * NTOT_;
    prep_w_kernel<<<(prep_threads + 255) / 256, 256>>>(Wq, Wk, Wv);
    proj_mma_kernel<<<M_ / 128, 256, PROJ_SMEM>>>(x);
    attn_mma_kernel<<<256, 256, ATTN_SMEM>>>(out);
}

// round 7
// speedup vs baseline: 4.7827x; 1.2255x over previous
#include <cuda_runtime.h>
#include <cuda_fp16.h>
#include <cstdint>

// Problem constants
static constexpr int B_  = 8;
static constexpr int T_  = 2048;
static constexpr int D_  = 1024;
static constexpr int HD_ = 64;
static constexpr int M_  = B_ * T_;       // 16384 rows
static constexpr int NTOT_ = 192;         // q|k|v fused output columns
static constexpr int TK_ = 64;            // K per chunk (128B fp16 rows)
static constexpr int NCHUNK_ = D_ / TK_;  // 16

// Device-global scratch (fp16). q pre-scaled by 0.125*log2e, hi/lo split.
// k, v stored hi-only.
__device__ __align__(16) __half g_qhi[(size_t)M_ * HD_];
__device__ __align__(16) __half g_qlo[(size_t)M_ * HD_];
__device__ __align__(16) __half g_khi[(size_t)M_ * HD_];
__device__ __align__(16) __half g_vhi[(size_t)M_ * HD_];
// Pre-transposed + swizzled fp16 W-hi tiles: [chunk][n=0..191][k=0..63]
static constexpr size_t WTILE_BYTES = (size_t)NTOT_ * 128;   // 24576 per chunk
__device__ __align__(16) uint8_t g_bhi[(size_t)NCHUNK_ * WTILE_BYTES];

__host__ __device__ __forceinline__ uint32_t swz128(uint32_t off) {
    return off ^ ((off >> 3) & 0x70);
}
__device__ __forceinline__ uint32_t smem_u32(const void* p) {
    uint32_t a;
    asm("{ .reg .u64 t; cvta.to.shared.u64 t, %1; cvt.u32.u64 %0, t; }"
        : "=r"(a) : "l"(p));
    return a;
}
__device__ __forceinline__ void ldsm_x4(uint32_t (&r)[4], uint32_t addr) {
    asm volatile("ldmatrix.sync.aligned.m8n8.x4.shared.b16 {%0,%1,%2,%3}, [%4];"
                 : "=r"(r[0]), "=r"(r[1]), "=r"(r[2]), "=r"(r[3]) : "r"(addr));
}
__device__ __forceinline__ void ldsm_x2(uint32_t (&r)[2], uint32_t addr) {
    asm volatile("ldmatrix.sync.aligned.m8n8.x2.shared.b16 {%0,%1}, [%2];"
                 : "=r"(r[0]), "=r"(r[1]) : "r"(addr));
}
__device__ __forceinline__ void ldsm_x4_trans(uint32_t (&r)[4], uint32_t addr) {
    asm volatile("ldmatrix.sync.aligned.m8n8.x4.trans.shared.b16 {%0,%1,%2,%3}, [%4];"
                 : "=r"(r[0]), "=r"(r[1]), "=r"(r[2]), "=r"(r[3]) : "r"(addr));
}
__device__ __forceinline__ void mma_f16(float (&d)[4], const uint32_t (&a)[4],
                                        uint32_t b0, uint32_t b1) {
    asm volatile(
        "mma.sync.aligned.m16n8k16.row.col.f32.f16.f16.f32 "
        "{%0,%1,%2,%3}, {%4,%5,%6,%7}, {%8,%9}, {%0,%1,%2,%3};"
        : "+f"(d[0]), "+f"(d[1]), "+f"(d[2]), "+f"(d[3])
        : "r"(a[0]), "r"(a[1]), "r"(a[2]), "r"(a[3]), "r"(b0), "r"(b1));
}
__device__ __forceinline__ uint32_t pack_h2(float lo, float hi) {
    __half l = __float2half_rn(lo);
    __half h = __float2half_rn(hi);
    return ((uint32_t)__half_as_ushort(h) << 16) | __half_as_ushort(l);
}
__device__ __forceinline__ uint32_t f2h2(float lo, float hi) {
    uint32_t r;
    asm("cvt.rn.f16x2.f32 %0, %1, %2;" : "=r"(r) : "f"(hi), "f"(lo));
    return r;
}
__device__ __forceinline__ uint32_t ex2h2(uint32_t x) {
    uint32_t r;
    asm("ex2.approx.f16x2 %0, %1;" : "=r"(r) : "r"(x));
    return r;
}
__device__ __forceinline__ float2 h22f2(uint32_t w) {
    __half2 h;
    *(uint32_t*)&h = w;
    return __half22float2(h);
}
__device__ __forceinline__ float ex2f(float x) {
    float y;
    asm("ex2.approx.ftz.f32 %0, %1;" : "=f"(y) : "f"(x));
    return y;
}
__device__ __forceinline__ void cp_async16(uint32_t dst, const void* src) {
    asm volatile("cp.async.ca.shared.global [%0], [%1], 16;"
                 :: "r"(dst), "l"(src));
}
#define CP_COMMIT() asm volatile("cp.async.commit_group;" ::: "memory")
#define CP_WAIT0()  asm volatile("cp.async.wait_group 0;" ::: "memory")
#define GROUP_BAR(id) asm volatile("bar.sync %0, 128;" :: "r"(id) : "memory")

static constexpr float SCALE_Q = 0.125f * 1.4426950408889634f;  // 1/sqrt(64)*log2e

// ---------------------------------------------------------------------------
// Kernel 0: W -> fp16 hi, transposed to [n][k] rows, SW128 swizzled.
// ---------------------------------------------------------------------------
__global__ void prep_w_kernel(const float* __restrict__ Wq,
                              const float* __restrict__ Wk,
                              const float* __restrict__ Wv)
{
    const int t = blockIdx.x * blockDim.x + threadIdx.x;
    if (t >= NCHUNK_ * 8 * NTOT_) return;
    const int c = t % NTOT_;
    const int rest = t / NTOT_;
    const int kg = rest % 8;
    const int chunk = rest / 8;
    const int n = c & 63;
    const float* W = (c < 64) ? Wq : (c < 128) ? Wk : Wv;
    const int k0 = chunk * TK_ + kg * 8;

    uint32_t hw[4];
#pragma unroll
    for (int j = 0; j < 4; j++) {
        const float a = W[(size_t)(k0 + 2 * j) * HD_ + n];
        const float b = W[(size_t)(k0 + 2 * j + 1) * HD_ + n];
        hw[j] = pack_h2(a, b);
    }
    const size_t base = (size_t)chunk * WTILE_BYTES;
    const uint32_t off = swz128((uint32_t)c * 128u + (uint32_t)kg * 16u);
    *(uint4*)(g_bhi + base + off) = make_uint4(hw[0], hw[1], hw[2], hw[3]);
}

// ---------------------------------------------------------------------------
// Kernel 1: QKV projection, mma.sync fp16, 2-term (x split hi/lo, W hi only).
// M-tile 64, grid 256, 2 CTAs/SM, 2-stage cp.async pipeline.
// ---------------------------------------------------------------------------
static constexpr int A_TILE = 64 * 128;            // 8192 bytes per hi/lo
static constexpr int B_TILE = NTOT_ * 128;         // 24576 bytes
static constexpr int PROJ_STAGE = 2 * A_TILE + B_TILE;   // 40960
static constexpr int PROJ_SMEM = 1024 + 2 * PROJ_STAGE;  // 82944

__global__ __launch_bounds__(256, 2) void proj_mma_kernel(const float* __restrict__ x)
{
    extern __shared__ uint8_t dynsm[];
    const uint32_t raw = smem_u32(dynsm);
    const uint32_t base = (raw + 1023u) & ~1023u;
    uint8_t* const sm = dynsm + (base - raw);

    const int tid = threadIdx.x;
    const int wid = tid >> 5;
    const int lane = tid & 31;
    const size_t row0g = (size_t)blockIdx.x * 64;

    float C[4][3][4];
#pragma unroll
    for (int mt = 0; mt < 4; mt++)
#pragma unroll
        for (int nt = 0; nt < 3; nt++)
#pragma unroll
            for (int e = 0; e < 4; e++) C[mt][nt][e] = 0.0f;

    const uint32_t a_row = (uint32_t)(lane & 15);
    const uint32_t a_kb  = (uint32_t)((lane >> 4) * 16);
    const uint32_t b_row = (uint32_t)(lane & 7);
    const uint32_t b_kb  = (uint32_t)(((lane >> 3) & 1) * 16);

    auto fillA = [&](int stage, int kc) {
        uint8_t* s = sm + stage * PROJ_STAGE;
#pragma unroll
        for (int i = 0; i < 4; i++) {
            const int idx = tid + i * 256;     // 0..1023
            const int row = idx >> 4;          // 0..63
            const int c4  = idx & 15;
            float4 v = *(const float4*)&x[(row0g + row) * D_ + kc * TK_ + c4 * 4];
            const __half hx = __float2half_rn(v.x);
            const __half hy = __float2half_rn(v.y);
            const __half hz = __float2half_rn(v.z);
            const __half hw = __float2half_rn(v.w);
            const uint32_t h0 = ((uint32_t)__half_as_ushort(hy) << 16) | __half_as_ushort(hx);
            const uint32_t h1 = ((uint32_t)__half_as_ushort(hw) << 16) | __half_as_ushort(hz);
            const uint32_t l0 = pack_h2(v.x - __half2float(hx), v.y - __half2float(hy));
            const uint32_t l1 = pack_h2(v.z - __half2float(hz), v.w - __half2float(hw));
            const uint32_t off = swz128((uint32_t)row * 128u + (uint32_t)c4 * 8u);
            *(uint2*)(s + off)          = make_uint2(h0, h1);
            *(uint2*)(s + A_TILE + off) = make_uint2(l0, l1);
        }
    };
    auto cpB = [&](int stage, int kc) {
        const uint32_t sb = base + stage * PROJ_STAGE + 2 * A_TILE;
        const uint8_t* srcH = g_bhi + (size_t)kc * WTILE_BYTES;
#pragma unroll
        for (int i = 0; i < 6; i++) {
            const int idx = tid + i * 256;     // 0..1535
            cp_async16(sb + idx * 16, srcH + idx * 16);
        }
    };

    fillA(0, 0); cpB(0, 0); CP_COMMIT(); CP_WAIT0();
    __syncthreads();

    for (int kc = 0; kc < NCHUNK_; kc++) {
        if (kc + 1 < NCHUNK_) {
            fillA((kc + 1) & 1, kc + 1);
            cpB((kc + 1) & 1, kc + 1);
            CP_COMMIT();
        }

        const uint32_t sb = base + (kc & 1) * PROJ_STAGE;
        const uint32_t sAhi = sb, sAlo = sb + A_TILE;
        const uint32_t sBhi = sb + 2 * A_TILE;

#pragma unroll
        for (int ks = 0; ks < 4; ks++) {
            uint32_t Ah[4][4], Al[4][4];
#pragma unroll
            for (int mt = 0; mt < 4; mt++) {
                const uint32_t roff =
                    swz128((uint32_t)(mt * 16 + a_row) * 128u +
                           (uint32_t)ks * 32u + a_kb);
                ldsm_x4(Ah[mt], sAhi + roff);
                ldsm_x4(Al[mt], sAlo + roff);
            }
#pragma unroll
            for (int nt = 0; nt < 3; nt++) {
                const uint32_t boff =
                    swz128((uint32_t)(wid * 24 + nt * 8 + b_row) * 128u +
                           (uint32_t)ks * 32u + b_kb);
                uint32_t Bh[2];
                ldsm_x2(Bh, sBhi + boff);
#pragma unroll
                for (int mt = 0; mt < 4; mt++) {
                    mma_f16(C[mt][nt], Ah[mt], Bh[0], Bh[1]);
                    mma_f16(C[mt][nt], Al[mt], Bh[0], Bh[1]);
                }
            }
        }
        if (kc + 1 < NCHUNK_) CP_WAIT0();
        __syncthreads();
    }

    // Epilogue: qhi/qlo (x SCALE_Q), khi, vhi
#pragma unroll
    for (int mt = 0; mt < 4; mt++) {
        const size_t r = row0g + mt * 16 + (lane >> 2);
#pragma unroll
        for (int nt = 0; nt < 3; nt++) {
            const int c = wid * 24 + nt * 8 + 2 * (lane & 3);
            const int n = c & 63;
#pragma unroll
            for (int half = 0; half < 2; half++) {
                const size_t rr = r + half * 8;
                float v0 = C[mt][nt][half * 2 + 0];
                float v1 = C[mt][nt][half * 2 + 1];
                if (c < 64) {
                    v0 *= SCALE_Q; v1 *= SCALE_Q;
                    const __half h0 = __float2half_rn(v0);
                    const __half h1 = __float2half_rn(v1);
                    *(uint32_t*)&g_qhi[rr * HD_ + n] =
                        ((uint32_t)__half_as_ushort(h1) << 16) | __half_as_ushort(h0);
                    *(uint32_t*)&g_qlo[rr * HD_ + n] =
                        pack_h2(v0 - __half2float(h0), v1 - __half2float(h1));
                } else {
                    __half* o = (c < 128) ? g_khi : g_vhi;
                    *(uint32_t*)&o[rr * HD_ + n] = pack_h2(v0, v1);
                }
            }
        }
    }
}

// ---------------------------------------------------------------------------
// Kernel 2: flash attention. QK 2-term fp16, PV 1-term with f16x2 exp2.
// Split-K across two warp groups + in-CTA merge. 2 CTAs/SM.
// ---------------------------------------------------------------------------
static constexpr int Q_BYTES  = 2 * 64 * 128;       // 16384 (hi|lo)
static constexpr int KV_STAGE = 2 * 64 * 128;       // 16384 (khi|vhi)
static constexpr int ATTN_SMEM = 1024 + Q_BYTES + 4 * KV_STAGE;  // 82944

__global__ __launch_bounds__(256, 2) void attn_mma_kernel(float* __restrict__ out)
{
    extern __shared__ uint8_t dynsm[];
    const uint32_t raw = smem_u32(dynsm);
    const uint32_t base = (raw + 1023u) & ~1023u;
    uint8_t* const smp = dynsm + (base - raw);

    const int tid = threadIdx.x;
    const int wid = tid >> 5;
    const int lane = tid & 31;
    const int grp = wid >> 2;
    const int wi  = wid & 3;
    const int gt  = tid & 127;

    const int bid = blockIdx.x;
    const int qt = 31 - (bid >> 3);       // largest work first
    const int b  = bid & 7;
    const int h  = (qt + 2) >> 1;
    const int kt0 = grp ? h : 0;
    const int niter = grp ? (qt + 1 - h) : h;

    const uint32_t sQ  = base;
    const uint32_t sKV = base + Q_BYTES + grp * 2 * KV_STAGE;
    const size_t qrow0 = (size_t)b * T_ + (size_t)qt * 64;

    // ---- Q via cp.async ----
#pragma unroll
    for (int i = 0; i < 4; i++) {
        const int idx = tid + i * 256;
        const int part = idx >> 9;
        const int row = (idx >> 3) & 63;
        const int c16 = idx & 7;
        const uint32_t doff = swz128((uint32_t)row * 128u + (uint32_t)c16 * 16u);
        const __half* src = part ? g_qlo : g_qhi;
        cp_async16(sQ + part * 8192 + doff, &src[(qrow0 + row) * HD_ + c16 * 8]);
    }
    CP_COMMIT();

    auto prefetch_kv = [&](int kt, int stage) {
        const uint32_t sb = sKV + stage * KV_STAGE;
        const size_t krow0 = (size_t)b * T_ + (size_t)kt * 64;
#pragma unroll
        for (int i = 0; i < 8; i++) {
            const int idx = gt + i * 128;      // 0..1023
            const int arr = idx >> 9;          // 0 khi, 1 vhi
            const int row = (idx >> 3) & 63;
            const int c16 = idx & 7;
            const uint32_t doff = swz128((uint32_t)row * 128u + (uint32_t)c16 * 16u);
            const __half* src = arr ? g_vhi : g_khi;
            cp_async16(sb + arr * 8192 + doff, &src[(krow0 + row) * HD_ + c16 * 8]);
        }
    };
    if (niter > 0) prefetch_kv(kt0, 0);
    CP_COMMIT();
    CP_WAIT0();
    __syncthreads();

    // ---- Q fragments ----
    uint32_t Qh[4][4], Ql[4][4];
    {
        const uint32_t a_row = (uint32_t)(lane & 15);
        const uint32_t a_kb  = (uint32_t)((lane >> 4) * 16);
#pragma unroll
        for (int ks = 0; ks < 4; ks++) {
            const uint32_t roff =
                swz128((uint32_t)(wi * 16 + a_row) * 128u + (uint32_t)ks * 32u + a_kb);
            ldsm_x4(Qh[ks], sQ + roff);
            ldsm_x4(Ql[ks], sQ + 8192 + roff);
        }
    }

    float O[8][4];
#pragma unroll
    for (int nh = 0; nh < 8; nh++)
#pragma unroll
        for (int e = 0; e < 4; e++) O[nh][e] = 0.0f;
    float m0 = -1e30f, m1 = -1e30f, l0 = 0.0f, l1 = 0.0f;

    // K paired-x4 addressing: g = lane>>3
    const int kg  = lane >> 3;                  // 0..3
    const uint32_t k_row8 = (uint32_t)(lane & 7);
    const uint32_t k_rowsel = (uint32_t)(kg >> 1) * 8;   // which nt of pair
    const uint32_t k_kb = (uint32_t)(kg & 1) * 16;
    // V paired-x4-trans addressing
    const uint32_t v_rowsel = (uint32_t)(kg & 1) * 8;
    const uint32_t v_colsel = (uint32_t)(kg >> 1) * 16;  // which nh of pair
    const int q2 = 2 * (lane & 3);
    const int rloc = (lane >> 2);

    for (int i = 0; i < niter; i++) {
        if (i + 1 < niter) prefetch_kv(kt0 + i + 1, (i + 1) & 1);
        CP_COMMIT();

        const int kt = kt0 + i;
        const uint32_t sb = sKV + (i & 1) * KV_STAGE;
        const uint32_t sKh = sb;
        const uint32_t sVh = sb + 8192;

        // ---- S = Q @ K^T (log2-domain logits) ----
        float S[8][4];
#pragma unroll
        for (int nt = 0; nt < 8; nt++)
#pragma unroll
            for (int e = 0; e < 4; e++) S[nt][e] = 0.0f;

#pragma unroll
        for (int ks = 0; ks < 4; ks++) {
#pragma unroll
            for (int ntp = 0; ntp < 4; ntp++) {
                const uint32_t boff =
                    swz128((uint32_t)(ntp * 16 + k_rowsel + k_row8) * 128u +
                           (uint32_t)ks * 32u + k_kb);
                uint32_t Kf[4];
                ldsm_x4(Kf, sKh + boff);
                mma_f16(S[2 * ntp],     Qh[ks], Kf[0], Kf[1]);
                mma_f16(S[2 * ntp],     Ql[ks], Kf[0], Kf[1]);
                mma_f16(S[2 * ntp + 1], Qh[ks], Kf[2], Kf[3]);
                mma_f16(S[2 * ntp + 1], Ql[ks], Kf[2], Kf[3]);
            }
        }

        // ---- causal mask on diagonal tile ----
        if (kt == qt) {
            const int r0 = wi * 16 + rloc;
#pragma unroll
            for (int nt = 0; nt < 8; nt++) {
                const int c0 = nt * 8 + q2;
                if (c0 > r0)     S[nt][0] = -1e30f;
                if (c0 + 1 > r0) S[nt][1] = -1e30f;
                if (c0 > r0 + 8)     S[nt][2] = -1e30f;
                if (c0 + 1 > r0 + 8) S[nt][3] = -1e30f;
            }
        }

        // ---- online softmax (base-2), P in fp16x2 ----
        float mx0 = -1e30f, mx1 = -1e30f;
#pragma unroll
        for (int nt = 0; nt < 8; nt++) {
            mx0 = fmaxf(mx0, fmaxf(S[nt][0], S[nt][1]));
            mx1 = fmaxf(mx1, fmaxf(S[nt][2], S[nt][3]));
        }
        mx0 = fmaxf(mx0, __shfl_xor_sync(0xffffffffu, mx0, 1));
        mx0 = fmaxf(mx0, __shfl_xor_sync(0xffffffffu, mx0, 2));
        mx1 = fmaxf(mx1, __shfl_xor_sync(0xffffffffu, mx1, 1));
        mx1 = fmaxf(mx1, __shfl_xor_sync(0xffffffffu, mx1, 2));
        const float mn0 = fmaxf(m0, mx0);
        const float mn1 = fmaxf(m1, mx1);
        const float a0 = ex2f(m0 - mn0);
        const float a1 = ex2f(m1 - mn1);
        m0 = mn0; m1 = mn1;

        uint32_t P[4][4];
        float sum0 = 0.0f, sum1 = 0.0f;
#pragma unroll
        for (int nt = 0; nt < 8; nt++) {
            const uint32_t w01 = ex2h2(f2h2(S[nt][0] - mn0, S[nt][1] - mn0));
            const uint32_t w23 = ex2h2(f2h2(S[nt][2] - mn1, S[nt][3] - mn1));
            P[nt >> 1][(nt & 1) * 2 + 0] = w01;
            P[nt >> 1][(nt & 1) * 2 + 1] = w23;
            const float2 f01 = h22f2(w01);
            const float2 f23 = h22f2(w23);
            sum0 += f01.x + f01.y;
            sum1 += f23.x + f23.y;
        }
        sum0 += __shfl_xor_sync(0xffffffffu, sum0, 1);
        sum0 += __shfl_xor_sync(0xffffffffu, sum0, 2);
        sum1 += __shfl_xor_sync(0xffffffffu, sum1, 1);
        sum1 += __shfl_xor_sync(0xffffffffu, sum1, 2);
        l0 = l0 * a0 + sum0;
        l1 = l1 * a1 + sum1;

#pragma unroll
        for (int nh = 0; nh < 8; nh++) {
            O[nh][0] *= a0; O[nh][1] *= a0;
            O[nh][2] *= a1; O[nh][3] *= a1;
        }

        // ---- O += P @ V (V paired-x4-trans) ----
#pragma unroll
        for (int t = 0; t < 4; t++) {
#pragma unroll
            for (int nhp = 0; nhp < 4; nhp++) {
                const uint32_t voff =
                    swz128((uint32_t)(t * 16 + v_rowsel + k_row8) * 128u +
                           (uint32_t)nhp * 32u + v_colsel);
                uint32_t Vf[4];
                ldsm_x4_trans(Vf, sVh + voff);
                mma_f16(O[2 * nhp],     P[t], Vf[0], Vf[1]);
                mma_f16(O[2 * nhp + 1], P[t], Vf[2], Vf[3]);
            }
        }

        CP_WAIT0();
        GROUP_BAR(1 + grp);
    }

    // ---- split-softmax merge ----
    float* const mO  = (float*)(smp + Q_BYTES + 2 * KV_STAGE);
    float* const mML = mO + 128 * 32;
    const int slot = wi * 32 + lane;

    if (grp == 1) {
#pragma unroll
        for (int nh = 0; nh < 8; nh++)
#pragma unroll
            for (int e = 0; e < 4; e++) mO[slot * 32 + nh * 4 + e] = O[nh][e];
        mML[slot * 4 + 0] = m0;
        mML[slot * 4 + 1] = l0;
        mML[slot * 4 + 2] = m1;
        mML[slot * 4 + 3] = l1;
    }
    __syncthreads();

    if (grp == 0) {
        const float pm0 = mML[slot * 4 + 0];
        const float pl0 = mML[slot * 4 + 1];
        const float pm1 = mML[slot * 4 + 2];
        const float pl1 = mML[slot * 4 + 3];

        const float M0 = fmaxf(m0, pm0);
        const float M1 = fmaxf(m1, pm1);
        const float a0 = ex2f(m0 - M0), pa0 = ex2f(pm0 - M0);
        const float a1 = ex2f(m1 - M1), pa1 = ex2f(pm1 - M1);
        const float il0 = 1.0f / (l0 * a0 + pl0 * pa0);
        const float il1 = 1.0f / (l1 * a1 + pl1 * pa1);

        const size_t grow = qrow0 + (size_t)(wi * 16 + rloc);
#pragma unroll
        for (int nh = 0; nh < 8; nh++) {
            const int hcol = nh * 8 + q2;
            const float p0 = mO[slot * 32 + nh * 4 + 0];
            const float p1 = mO[slot * 32 + nh * 4 + 1];
            const float p2 = mO[slot * 32 + nh * 4 + 2];
            const float p3 = mO[slot * 32 + nh * 4 + 3];
            *(float2*)&out[grow * HD_ + hcol] =
                make_float2((O[nh][0] * a0 + p0 * pa0) * il0,
                            (O[nh][1] * a0 + p1 * pa0) * il0);
            *(float2*)&out[(grow + 8) * HD_ + hcol] =
                make_float2((O[nh][2] * a1 + p2 * pa1) * il1,
                            (O[nh][3] * a1 + p3 * pa1) * il1);
        }
    }
}

// ---------------------------------------------------------------------------
extern "C" void kernel_launch(void* const* d_in, const int* in_sizes, int n_in,
                              void* d_out, int out_size)
{
    const float* x  = (const float*)d_in[0];
    const float* Wq = (const float*)d_in[1];
    const float* Wk = (const float*)d_in[2];
    const float* Wv = (const float*)d_in[3];
    float* out = (float*)d_out;

    cudaFuncSetAttribute(proj_mma_kernel,
                         cudaFuncAttributeMaxDynamicSharedMemorySize, PROJ_SMEM);
    cudaFuncSetAttribute(attn_mma_kernel,
                         cudaFuncAttributeMaxDynamicSharedMemorySize, ATTN_SMEM);

    const int prep_threads = NCHUNK_ * 8 * NTOT_;
    prep_w_kernel<<<(prep_threads + 255) / 256, 256>>>(Wq, Wk, Wv);
    proj_mma_kernel<<<M_ / 64, 256, PROJ_SMEM>>>(x);
    attn_mma_kernel<<<256, 256, ATTN_SMEM>>>(out);
}

// round 8
// speedup vs baseline: 5.9274x; 1.2393x over previous
#include <cuda_runtime.h>
#include <cuda_fp16.h>
#include <cstdint>

// Problem constants
static constexpr int B_  = 8;
static constexpr int T_  = 2048;
static constexpr int D_  = 1024;
static constexpr int HD_ = 64;
static constexpr int M_  = B_ * T_;       // 16384 rows
static constexpr int NTOT_ = 192;         // q|k|v fused output columns
static constexpr int TK_ = 64;            // K per chunk (128B fp16 rows)
static constexpr int NCHUNK_ = D_ / TK_;  // 16

// Device-global scratch (fp16, hi-only everywhere).
// q pre-scaled by 0.125*log2e.
__device__ __align__(16) __half g_qhi[(size_t)M_ * HD_];
__device__ __align__(16) __half g_khi[(size_t)M_ * HD_];
__device__ __align__(16) __half g_vhi[(size_t)M_ * HD_];
// Pre-transposed + swizzled fp16 W-hi tiles: [chunk][n=0..191][k=0..63]
static constexpr size_t WTILE_BYTES = (size_t)NTOT_ * 128;   // 24576 per chunk
__device__ __align__(16) uint8_t g_bhi[(size_t)NCHUNK_ * WTILE_BYTES];

__host__ __device__ __forceinline__ uint32_t swz128(uint32_t off) {
    return off ^ ((off >> 3) & 0x70);
}
__device__ __forceinline__ uint32_t smem_u32(const void* p) {
    uint32_t a;
    asm("{ .reg .u64 t; cvta.to.shared.u64 t, %1; cvt.u32.u64 %0, t; }"
        : "=r"(a) : "l"(p));
    return a;
}
__device__ __forceinline__ void ldsm_x4(uint32_t (&r)[4], uint32_t addr) {
    asm volatile("ldmatrix.sync.aligned.m8n8.x4.shared.b16 {%0,%1,%2,%3}, [%4];"
                 : "=r"(r[0]), "=r"(r[1]), "=r"(r[2]), "=r"(r[3]) : "r"(addr));
}
__device__ __forceinline__ void ldsm_x2(uint32_t (&r)[2], uint32_t addr) {
    asm volatile("ldmatrix.sync.aligned.m8n8.x2.shared.b16 {%0,%1}, [%2];"
                 : "=r"(r[0]), "=r"(r[1]) : "r"(addr));
}
__device__ __forceinline__ void ldsm_x4_trans(uint32_t (&r)[4], uint32_t addr) {
    asm volatile("ldmatrix.sync.aligned.m8n8.x4.trans.shared.b16 {%0,%1,%2,%3}, [%4];"
                 : "=r"(r[0]), "=r"(r[1]), "=r"(r[2]), "=r"(r[3]) : "r"(addr));
}
__device__ __forceinline__ void mma_f16(float (&d)[4], const uint32_t (&a)[4],
                                        uint32_t b0, uint32_t b1) {
    asm volatile(
        "mma.sync.aligned.m16n8k16.row.col.f32.f16.f16.f32 "
        "{%0,%1,%2,%3}, {%4,%5,%6,%7}, {%8,%9}, {%0,%1,%2,%3};"
        : "+f"(d[0]), "+f"(d[1]), "+f"(d[2]), "+f"(d[3])
        : "r"(a[0]), "r"(a[1]), "r"(a[2]), "r"(a[3]), "r"(b0), "r"(b1));
}
__device__ __forceinline__ uint32_t pack_h2(float lo, float hi) {
    __half l = __float2half_rn(lo);
    __half h = __float2half_rn(hi);
    return ((uint32_t)__half_as_ushort(h) << 16) | __half_as_ushort(l);
}
__device__ __forceinline__ uint32_t f2h2(float lo, float hi) {
    uint32_t r;
    asm("cvt.rn.f16x2.f32 %0, %1, %2;" : "=r"(r) : "f"(hi), "f"(lo));
    return r;
}
__device__ __forceinline__ uint32_t ex2h2(uint32_t x) {
    uint32_t r;
    asm("ex2.approx.f16x2 %0, %1;" : "=r"(r) : "r"(x));
    return r;
}
__device__ __forceinline__ float2 h22f2(uint32_t w) {
    __half2 h;
    *(uint32_t*)&h = w;
    return __half22float2(h);
}
__device__ __forceinline__ float ex2f(float x) {
    float y;
    asm("ex2.approx.ftz.f32 %0, %1;" : "=f"(y) : "f"(x));
    return y;
}
__device__ __forceinline__ void cp_async16(uint32_t dst, const void* src) {
    asm volatile("cp.async.ca.shared.global [%0], [%1], 16;"
                 :: "r"(dst), "l"(src));
}
#define CP_COMMIT() asm volatile("cp.async.commit_group;" ::: "memory")
#define CP_WAIT0()  asm volatile("cp.async.wait_group 0;" ::: "memory")
#define GROUP_BAR(id) asm volatile("bar.sync %0, 128;" :: "r"(id) : "memory")

static constexpr float SCALE_Q = 0.125f * 1.4426950408889634f;  // 1/sqrt(64)*log2e

// ---------------------------------------------------------------------------
// Kernel 0: W -> fp16 hi, transposed to [n][k] rows, SW128 swizzled.
// ---------------------------------------------------------------------------
__global__ void prep_w_kernel(const float* __restrict__ Wq,
                              const float* __restrict__ Wk,
                              const float* __restrict__ Wv)
{
    const int t = blockIdx.x * blockDim.x + threadIdx.x;
    if (t >= NCHUNK_ * 8 * NTOT_) return;
    const int c = t % NTOT_;
    const int rest = t / NTOT_;
    const int kg = rest % 8;
    const int chunk = rest / 8;
    const int n = c & 63;
    const float* W = (c < 64) ? Wq : (c < 128) ? Wk : Wv;
    const int k0 = chunk * TK_ + kg * 8;

    uint32_t hw[4];
#pragma unroll
    for (int j = 0; j < 4; j++) {
        const float a = W[(size_t)(k0 + 2 * j) * HD_ + n];
        const float b = W[(size_t)(k0 + 2 * j + 1) * HD_ + n];
        hw[j] = pack_h2(a, b);
    }
    const size_t base = (size_t)chunk * WTILE_BYTES;
    const uint32_t off = swz128((uint32_t)c * 128u + (uint32_t)kg * 16u);
    *(uint4*)(g_bhi + base + off) = make_uint4(hw[0], hw[1], hw[2], hw[3]);
}

// ---------------------------------------------------------------------------
// Kernel 1: QKV projection, mma.sync fp16, 1-term (x hi, W hi).
// M-tile 64, grid 256, 2 CTAs/SM, 2-stage cp.async pipeline.
// ---------------------------------------------------------------------------
static constexpr int A_TILE = 64 * 128;            // 8192 bytes
static constexpr int B_TILE = NTOT_ * 128;         // 24576 bytes
static constexpr int PROJ_STAGE = A_TILE + B_TILE;       // 32768
static constexpr int PROJ_SMEM = 1024 + 2 * PROJ_STAGE;  // 66560

__global__ __launch_bounds__(256, 2) void proj_mma_kernel(const float* __restrict__ x)
{
    extern __shared__ uint8_t dynsm[];
    const uint32_t raw = smem_u32(dynsm);
    const uint32_t base = (raw + 1023u) & ~1023u;
    uint8_t* const sm = dynsm + (base - raw);

    const int tid = threadIdx.x;
    const int wid = tid >> 5;
    const int lane = tid & 31;
    const size_t row0g = (size_t)blockIdx.x * 64;

    float C[4][3][4];
#pragma unroll
    for (int mt = 0; mt < 4; mt++)
#pragma unroll
        for (int nt = 0; nt < 3; nt++)
#pragma unroll
            for (int e = 0; e < 4; e++) C[mt][nt][e] = 0.0f;

    const uint32_t a_row = (uint32_t)(lane & 15);
    const uint32_t a_kb  = (uint32_t)((lane >> 4) * 16);
    const uint32_t b_row = (uint32_t)(lane & 7);
    const uint32_t b_kb  = (uint32_t)(((lane >> 3) & 1) * 16);

    auto fillA = [&](int stage, int kc) {
        uint8_t* s = sm + stage * PROJ_STAGE;
#pragma unroll
        for (int i = 0; i < 4; i++) {
            const int idx = tid + i * 256;     // 0..1023
            const int row = idx >> 4;          // 0..63
            const int c4  = idx & 15;
            float4 v = *(const float4*)&x[(row0g + row) * D_ + kc * TK_ + c4 * 4];
            const uint32_t h0 = pack_h2(v.x, v.y);
            const uint32_t h1 = pack_h2(v.z, v.w);
            const uint32_t off = swz128((uint32_t)row * 128u + (uint32_t)c4 * 8u);
            *(uint2*)(s + off) = make_uint2(h0, h1);
        }
    };
    auto cpB = [&](int stage, int kc) {
        const uint32_t sb = base + stage * PROJ_STAGE + A_TILE;
        const uint8_t* srcH = g_bhi + (size_t)kc * WTILE_BYTES;
#pragma unroll
        for (int i = 0; i < 6; i++) {
            const int idx = tid + i * 256;     // 0..1535
            cp_async16(sb + idx * 16, srcH + idx * 16);
        }
    };

    fillA(0, 0); cpB(0, 0); CP_COMMIT(); CP_WAIT0();
    __syncthreads();

    for (int kc = 0; kc < NCHUNK_; kc++) {
        if (kc + 1 < NCHUNK_) {
            fillA((kc + 1) & 1, kc + 1);
            cpB((kc + 1) & 1, kc + 1);
            CP_COMMIT();
        }

        const uint32_t sb = base + (kc & 1) * PROJ_STAGE;
        const uint32_t sAhi = sb;
        const uint32_t sBhi = sb + A_TILE;

#pragma unroll
        for (int ks = 0; ks < 4; ks++) {
            uint32_t Ah[4][4];
#pragma unroll
            for (int mt = 0; mt < 4; mt++) {
                const uint32_t roff =
                    swz128((uint32_t)(mt * 16 + a_row) * 128u +
                           (uint32_t)ks * 32u + a_kb);
                ldsm_x4(Ah[mt], sAhi + roff);
            }
#pragma unroll
            for (int nt = 0; nt < 3; nt++) {
                const uint32_t boff =
                    swz128((uint32_t)(wid * 24 + nt * 8 + b_row) * 128u +
                           (uint32_t)ks * 32u + b_kb);
                uint32_t Bh[2];
                ldsm_x2(Bh, sBhi + boff);
#pragma unroll
                for (int mt = 0; mt < 4; mt++) {
                    mma_f16(C[mt][nt], Ah[mt], Bh[0], Bh[1]);
                }
            }
        }
        if (kc + 1 < NCHUNK_) CP_WAIT0();
        __syncthreads();
    }

    // Epilogue: qhi (x SCALE_Q), khi, vhi
#pragma unroll
    for (int mt = 0; mt < 4; mt++) {
        const size_t r = row0g + mt * 16 + (lane >> 2);
#pragma unroll
        for (int nt = 0; nt < 3; nt++) {
            const int c = wid * 24 + nt * 8 + 2 * (lane & 3);
            const int n = c & 63;
#pragma unroll
            for (int half = 0; half < 2; half++) {
                const size_t rr = r + half * 8;
                float v0 = C[mt][nt][half * 2 + 0];
                float v1 = C[mt][nt][half * 2 + 1];
                __half* o;
                if (c < 64) {
                    v0 *= SCALE_Q; v1 *= SCALE_Q;
                    o = g_qhi;
                } else {
                    o = (c < 128) ? g_khi : g_vhi;
                }
                *(uint32_t*)&o[rr * HD_ + n] = pack_h2(v0, v1);
            }
        }
    }
}

// ---------------------------------------------------------------------------
// Kernel 2: flash attention. QK 1-term, PV 1-term with f16x2 exp2.
// Split-K across two warp groups + in-CTA merge. 2 CTAs/SM.
// ---------------------------------------------------------------------------
static constexpr int Q_BYTES  = 64 * 128;           // 8192 (hi only)
static constexpr int KV_STAGE = 2 * 64 * 128;       // 16384 (khi|vhi)
static constexpr int ATTN_SMEM = 1024 + Q_BYTES + 4 * KV_STAGE;  // 74752

__global__ __launch_bounds__(256, 2) void attn_mma_kernel(float* __restrict__ out)
{
    extern __shared__ uint8_t dynsm[];
    const uint32_t raw = smem_u32(dynsm);
    const uint32_t base = (raw + 1023u) & ~1023u;
    uint8_t* const smp = dynsm + (base - raw);

    const int tid = threadIdx.x;
    const int wid = tid >> 5;
    const int lane = tid & 31;
    const int grp = wid >> 2;
    const int wi  = wid & 3;
    const int gt  = tid & 127;

    const int bid = blockIdx.x;
    const int qt = 31 - (bid >> 3);       // largest work first
    const int b  = bid & 7;
    const int h  = (qt + 2) >> 1;
    const int kt0 = grp ? h : 0;
    const int niter = grp ? (qt + 1 - h) : h;

    const uint32_t sQ  = base;
    const uint32_t sKV = base + Q_BYTES + grp * 2 * KV_STAGE;
    const size_t qrow0 = (size_t)b * T_ + (size_t)qt * 64;

    // ---- Q via cp.async (hi only: 512 transfers) ----
#pragma unroll
    for (int i = 0; i < 2; i++) {
        const int idx = tid + i * 256;         // 0..511
        const int row = idx >> 3;              // 0..63
        const int c16 = idx & 7;
        const uint32_t doff = swz128((uint32_t)row * 128u + (uint32_t)c16 * 16u);
        cp_async16(sQ + doff, &g_qhi[(qrow0 + row) * HD_ + c16 * 8]);
    }
    CP_COMMIT();

    auto prefetch_kv = [&](int kt, int stage) {
        const uint32_t sb = sKV + stage * KV_STAGE;
        const size_t krow0 = (size_t)b * T_ + (size_t)kt * 64;
#pragma unroll
        for (int i = 0; i < 8; i++) {
            const int idx = gt + i * 128;      // 0..1023
            const int arr = idx >> 9;          // 0 khi, 1 vhi
            const int row = (idx >> 3) & 63;
            const int c16 = idx & 7;
            const uint32_t doff = swz128((uint32_t)row * 128u + (uint32_t)c16 * 16u);
            const __half* src = arr ? g_vhi : g_khi;
            cp_async16(sb + arr * 8192 + doff, &src[(krow0 + row) * HD_ + c16 * 8]);
        }
    };
    if (niter > 0) prefetch_kv(kt0, 0);
    CP_COMMIT();
    CP_WAIT0();
    __syncthreads();

    // ---- Q fragments ----
    uint32_t Qh[4][4];
    {
        const uint32_t a_row = (uint32_t)(lane & 15);
        const uint32_t a_kb  = (uint32_t)((lane >> 4) * 16);
#pragma unroll
        for (int ks = 0; ks < 4; ks++) {
            const uint32_t roff =
                swz128((uint32_t)(wi * 16 + a_row) * 128u + (uint32_t)ks * 32u + a_kb);
            ldsm_x4(Qh[ks], sQ + roff);
        }
    }

    float O[8][4];
#pragma unroll
    for (int nh = 0; nh < 8; nh++)
#pragma unroll
        for (int e = 0; e < 4; e++) O[nh][e] = 0.0f;
    float m0 = -1e30f, m1 = -1e30f, l0 = 0.0f, l1 = 0.0f;

    // K paired-x4 addressing
    const int kg  = lane >> 3;                  // 0..3
    const uint32_t k_row8 = (uint32_t)(lane & 7);
    const uint32_t k_rowsel = (uint32_t)(kg >> 1) * 8;
    const uint32_t k_kb = (uint32_t)(kg & 1) * 16;
    // V paired-x4-trans addressing
    const uint32_t v_rowsel = (uint32_t)(kg & 1) * 8;
    const uint32_t v_colsel = (uint32_t)(kg >> 1) * 16;
    const int q2 = 2 * (lane & 3);
    const int rloc = (lane >> 2);

    for (int i = 0; i < niter; i++) {
        if (i + 1 < niter) prefetch_kv(kt0 + i + 1, (i + 1) & 1);
        CP_COMMIT();

        const int kt = kt0 + i;
        const uint32_t sb = sKV + (i & 1) * KV_STAGE;
        const uint32_t sKh = sb;
        const uint32_t sVh = sb + 8192;

        // ---- S = Q @ K^T (log2-domain logits) ----
        float S[8][4];
#pragma unroll
        for (int nt = 0; nt < 8; nt++)
#pragma unroll
            for (int e = 0; e < 4; e++) S[nt][e] = 0.0f;

#pragma unroll
        for (int ks = 0; ks < 4; ks++) {
#pragma unroll
            for (int ntp = 0; ntp < 4; ntp++) {
                const uint32_t boff =
                    swz128((uint32_t)(ntp * 16 + k_rowsel + k_row8) * 128u +
                           (uint32_t)ks * 32u + k_kb);
                uint32_t Kf[4];
                ldsm_x4(Kf, sKh + boff);
                mma_f16(S[2 * ntp],     Qh[ks], Kf[0], Kf[1]);
                mma_f16(S[2 * ntp + 1], Qh[ks], Kf[2], Kf[3]);
            }
        }

        // ---- causal mask on diagonal tile ----
        if (kt == qt) {
            const int r0 = wi * 16 + rloc;
#pragma unroll
            for (int nt = 0; nt < 8; nt++) {
                const int c0 = nt * 8 + q2;
                if (c0 > r0)     S[nt][0] = -1e30f;
                if (c0 + 1 > r0) S[nt][1] = -1e30f;
                if (c0 > r0 + 8)     S[nt][2] = -1e30f;
                if (c0 + 1 > r0 + 8) S[nt][3] = -1e30f;
            }
        }

        // ---- online softmax (base-2), P in fp16x2 ----
        float mx0 = -1e30f, mx1 = -1e30f;
#pragma unroll
        for (int nt = 0; nt < 8; nt++) {
            mx0 = fmaxf(mx0, fmaxf(S[nt][0], S[nt][1]));
            mx1 = fmaxf(mx1, fmaxf(S[nt][2], S[nt][3]));
        }
        mx0 = fmaxf(mx0, __shfl_xor_sync(0xffffffffu, mx0, 1));
        mx0 = fmaxf(mx0, __shfl_xor_sync(0xffffffffu, mx0, 2));
        mx1 = fmaxf(mx1, __shfl_xor_sync(0xffffffffu, mx1, 1));
        mx1 = fmaxf(mx1, __shfl_xor_sync(0xffffffffu, mx1, 2));
        const float mn0 = fmaxf(m0, mx0);
        const float mn1 = fmaxf(m1, mx1);
        const float a0 = ex2f(m0 - mn0);
        const float a1 = ex2f(m1 - mn1);
        m0 = mn0; m1 = mn1;

        uint32_t P[4][4];
        float sum0 = 0.0f, sum1 = 0.0f;
#pragma unroll
        for (int nt = 0; nt < 8; nt++) {
            const uint32_t w01 = ex2h2(f2h2(S[nt][0] - mn0, S[nt][1] - mn0));
            const uint32_t w23 = ex2h2(f2h2(S[nt][2] - mn1, S[nt][3] - mn1));
            P[nt >> 1][(nt & 1) * 2 + 0] = w01;
            P[nt >> 1][(nt & 1) * 2 + 1] = w23;
            const float2 f01 = h22f2(w01);
            const float2 f23 = h22f2(w23);
            sum0 += f01.x + f01.y;
            sum1 += f23.x + f23.y;
        }
        sum0 += __shfl_xor_sync(0xffffffffu, sum0, 1);
        sum0 += __shfl_xor_sync(0xffffffffu, sum0, 2);
        sum1 += __shfl_xor_sync(0xffffffffu, sum1, 1);
        sum1 += __shfl_xor_sync(0xffffffffu, sum1, 2);
        l0 = l0 * a0 + sum0;
        l1 = l1 * a1 + sum1;

#pragma unroll
        for (int nh = 0; nh < 8; nh++) {
            O[nh][0] *= a0; O[nh][1] *= a0;
            O[nh][2] *= a1; O[nh][3] *= a1;
        }

        // ---- O += P @ V ----
#pragma unroll
        for (int t = 0; t < 4; t++) {
#pragma unroll
            for (int nhp = 0; nhp < 4; nhp++) {
                const uint32_t voff =
                    swz128((uint32_t)(t * 16 + v_rowsel + k_row8) * 128u +
                           (uint32_t)nhp * 32u + v_colsel);
                uint32_t Vf[4];
                ldsm_x4_trans(Vf, sVh + voff);
                mma_f16(O[2 * nhp],     P[t], Vf[0], Vf[1]);
                mma_f16(O[2 * nhp + 1], P[t], Vf[2], Vf[3]);
            }
        }

        CP_WAIT0();
        GROUP_BAR(1 + grp);
    }

    // ---- split-softmax merge (group1 KV region reused as buffers) ----
    float* const mO  = (float*)(smp + Q_BYTES + 2 * KV_STAGE);
    float* const mML = mO + 128 * 32;
    const int slot = wi * 32 + lane;

    if (grp == 1) {
#pragma unroll
        for (int nh = 0; nh < 8; nh++)
#pragma unroll
            for (int e = 0; e < 4; e++) mO[slot * 32 + nh * 4 + e] = O[nh][e];
        mML[slot * 4 + 0] = m0;
        mML[slot * 4 + 1] = l0;
        mML[slot * 4 + 2] = m1;
        mML[slot * 4 + 3] = l1;
    }
    __syncthreads();

    if (grp == 0) {
        const float pm0 = mML[slot * 4 + 0];
        const float pl0 = mML[slot * 4 + 1];
        const float pm1 = mML[slot * 4 + 2];
        const float pl1 = mML[slot * 4 + 3];

        const float M0 = fmaxf(m0, pm0);
        const float M1 = fmaxf(m1, pm1);
        const float a0 = ex2f(m0 - M0), pa0 = ex2f(pm0 - M0);
        const float a1 = ex2f(m1 - M1), pa1 = ex2f(pm1 - M1);
        const float il0 = 1.0f / (l0 * a0 + pl0 * pa0);
        const float il1 = 1.0f / (l1 * a1 + pl1 * pa1);

        const size_t grow = qrow0 + (size_t)(wi * 16 + rloc);
#pragma unroll
        for (int nh = 0; nh < 8; nh++) {
            const int hcol = nh * 8 + q2;
            const float p0 = mO[slot * 32 + nh * 4 + 0];
            const float p1 = mO[slot * 32 + nh * 4 + 1];
            const float p2 = mO[slot * 32 + nh * 4 + 2];
            const float p3 = mO[slot * 32 + nh * 4 + 3];
            *(float2*)&out[grow * HD_ + hcol] =
                make_float2((O[nh][0] * a0 + p0 * pa0) * il0,
                            (O[nh][1] * a0 + p1 * pa0) * il0);
            *(float2*)&out[(grow + 8) * HD_ + hcol] =
                make_float2((O[nh][2] * a1 + p2 * pa1) * il1,
                            (O[nh][3] * a1 + p3 * pa1) * il1);
        }
    }
}

// ---------------------------------------------------------------------------
extern "C" void kernel_launch(void* const* d_in, const int* in_sizes, int n_in,
                              void* d_out, int out_size)
{
    const float* x  = (const float*)d_in[0];
    const float* Wq = (const float*)d_in[1];
    const float* Wk = (const float*)d_in[2];
    const float* Wv = (const float*)d_in[3];
    float* out = (float*)d_out;

    cudaFuncSetAttribute(proj_mma_kernel,
                         cudaFuncAttributeMaxDynamicSharedMemorySize, PROJ_SMEM);
    cudaFuncSetAttribute(attn_mma_kernel,
                         cudaFuncAttributeMaxDynamicSharedMemorySize, ATTN_SMEM);

    const int prep_threads = NCHUNK_ * 8 * NTOT_;
    prep_w_kernel<<<(prep_threads + 255) / 256, 256>>>(Wq, Wk, Wv);
    proj_mma_kernel<<<M_ / 64, 256, PROJ_SMEM>>>(x);
    attn_mma_kernel<<<256, 256, ATTN_SMEM>>>(out);
}

// round 9
// speedup vs baseline: 6.6455x; 1.1212x over previous
#include <cuda_runtime.h>
#include <cuda_fp16.h>
#include <cstdint>

// Problem constants
static constexpr int B_  = 8;
static constexpr int T_  = 2048;
static constexpr int D_  = 1024;
static constexpr int HD_ = 64;
static constexpr int M_  = B_ * T_;       // 16384 rows
static constexpr int NTOT_ = 192;         // q|k|v fused output columns
static constexpr int TK_ = 64;            // K per chunk (128B fp16 rows)
static constexpr int NCHUNK_ = D_ / TK_;  // 16

// Attention split-work constants: chunks of <=9 kt-tiles.
static constexpr int CHUNK_ = 9;
static constexpr int GPB_ = 74;           // groups per batch: sum ceil((qt+1)/9)
static constexpr int NGROUPS_ = GPB_ * B_; // 592

// Device-global scratch (fp16 hi-only; q pre-scaled by 0.125*log2e).
__device__ __align__(16) __half g_qhi[(size_t)M_ * HD_];
__device__ __align__(16) __half g_khi[(size_t)M_ * HD_];
__device__ __align__(16) __half g_vhi[(size_t)M_ * HD_];
// Pre-transposed + swizzled fp16 W-hi tiles: [chunk][n=0..191][k=0..63]
static constexpr size_t WTILE_BYTES = (size_t)NTOT_ * 128;   // 24576 per chunk
__device__ __align__(16) uint8_t g_bhi[(size_t)NCHUNK_ * WTILE_BYTES];
// Attention partials: per group O[64][64] fp32 + per row (m, l)
__device__ __align__(16) float g_pO[(size_t)NGROUPS_ * 64 * 64];
__device__ __align__(16) float g_pML[(size_t)NGROUPS_ * 64 * 2];

__host__ __device__ __forceinline__ uint32_t swz128(uint32_t off) {
    return off ^ ((off >> 3) & 0x70);
}
__device__ __forceinline__ uint32_t smem_u32(const void* p) {
    uint32_t a;
    asm("{ .reg .u64 t; cvta.to.shared.u64 t, %1; cvt.u32.u64 %0, t; }"
        : "=r"(a) : "l"(p));
    return a;
}
__device__ __forceinline__ void ldsm_x4(uint32_t (&r)[4], uint32_t addr) {
    asm volatile("ldmatrix.sync.aligned.m8n8.x4.shared.b16 {%0,%1,%2,%3}, [%4];"
                 : "=r"(r[0]), "=r"(r[1]), "=r"(r[2]), "=r"(r[3]) : "r"(addr));
}
__device__ __forceinline__ void ldsm_x2(uint32_t (&r)[2], uint32_t addr) {
    asm volatile("ldmatrix.sync.aligned.m8n8.x2.shared.b16 {%0,%1}, [%2];"
                 : "=r"(r[0]), "=r"(r[1]) : "r"(addr));
}
__device__ __forceinline__ void ldsm_x4_trans(uint32_t (&r)[4], uint32_t addr) {
    asm volatile("ldmatrix.sync.aligned.m8n8.x4.trans.shared.b16 {%0,%1,%2,%3}, [%4];"
                 : "=r"(r[0]), "=r"(r[1]), "=r"(r[2]), "=r"(r[3]) : "r"(addr));
}
__device__ __forceinline__ void mma_f16(float (&d)[4], const uint32_t (&a)[4],
                                        uint32_t b0, uint32_t b1) {
    asm volatile(
        "mma.sync.aligned.m16n8k16.row.col.f32.f16.f16.f32 "
        "{%0,%1,%2,%3}, {%4,%5,%6,%7}, {%8,%9}, {%0,%1,%2,%3};"
        : "+f"(d[0]), "+f"(d[1]), "+f"(d[2]), "+f"(d[3])
        : "r"(a[0]), "r"(a[1]), "r"(a[2]), "r"(a[3]), "r"(b0), "r"(b1));
}
__device__ __forceinline__ uint32_t pack_h2(float lo, float hi) {
    __half l = __float2half_rn(lo);
    __half h = __float2half_rn(hi);
    return ((uint32_t)__half_as_ushort(h) << 16) | __half_as_ushort(l);
}
__device__ __forceinline__ uint32_t f2h2(float lo, float hi) {
    uint32_t r;
    asm("cvt.rn.f16x2.f32 %0, %1, %2;" : "=r"(r) : "f"(hi), "f"(lo));
    return r;
}
__device__ __forceinline__ uint32_t ex2h2(uint32_t x) {
    uint32_t r;
    asm("ex2.approx.f16x2 %0, %1;" : "=r"(r) : "r"(x));
    return r;
}
__device__ __forceinline__ float2 h22f2(uint32_t w) {
    __half2 h;
    *(uint32_t*)&h = w;
    return __half22float2(h);
}
__device__ __forceinline__ float ex2f(float x) {
    float y;
    asm("ex2.approx.ftz.f32 %0, %1;" : "=f"(y) : "f"(x));
    return y;
}
__device__ __forceinline__ void cp_async16(uint32_t dst, const void* src) {
    asm volatile("cp.async.ca.shared.global [%0], [%1], 16;"
                 :: "r"(dst), "l"(src));
}
#define CP_COMMIT() asm volatile("cp.async.commit_group;" ::: "memory")
#define CP_WAIT0()  asm volatile("cp.async.wait_group 0;" ::: "memory")

static constexpr float SCALE_Q = 0.125f * 1.4426950408889634f;  // 1/sqrt(64)*log2e

// ---------------------------------------------------------------------------
// Kernel 0: W -> fp16 hi, transposed to [n][k] rows, SW128 swizzled.
// 2x parallel: each thread converts 4 k-values (uint2 write).
// ---------------------------------------------------------------------------
__global__ void prep_w_kernel(const float* __restrict__ Wq,
                              const float* __restrict__ Wk,
                              const float* __restrict__ Wv)
{
    const int th = blockIdx.x * blockDim.x + threadIdx.x;
    if (th >= NCHUNK_ * 8 * NTOT_ * 2) return;
    const int jh = th & 1;
    const int t = th >> 1;
    const int c = t % NTOT_;
    const int rest = t / NTOT_;
    const int kg = rest % 8;
    const int chunk = rest / 8;
    const int n = c & 63;
    const float* W = (c < 64) ? Wq : (c < 128) ? Wk : Wv;
    const int k0 = chunk * TK_ + kg * 8 + jh * 4;

    uint32_t hw[2];
#pragma unroll
    for (int j = 0; j < 2; j++) {
        const float a = W[(size_t)(k0 + 2 * j) * HD_ + n];
        const float b = W[(size_t)(k0 + 2 * j + 1) * HD_ + n];
        hw[j] = pack_h2(a, b);
    }
    const size_t base = (size_t)chunk * WTILE_BYTES;
    const uint32_t off = swz128((uint32_t)c * 128u + (uint32_t)kg * 16u) + jh * 8u;
    *(uint2*)(g_bhi + base + off) = make_uint2(hw[0], hw[1]);
}

// ---------------------------------------------------------------------------
// Kernel 1: QKV projection, mma.sync fp16 1-term. M-tile 64, grid 256,
// 2 CTAs/SM, 2-stage cp.async pipeline. (unchanged from R8)
// ---------------------------------------------------------------------------
static constexpr int A_TILE = 64 * 128;            // 8192 bytes
static constexpr int B_TILE = NTOT_ * 128;         // 24576 bytes
static constexpr int PROJ_STAGE = A_TILE + B_TILE;       // 32768
static constexpr int PROJ_SMEM = 1024 + 2 * PROJ_STAGE;  // 66560

__global__ __launch_bounds__(256, 2) void proj_mma_kernel(const float* __restrict__ x)
{
    extern __shared__ uint8_t dynsm[];
    const uint32_t raw = smem_u32(dynsm);
    const uint32_t base = (raw + 1023u) & ~1023u;
    uint8_t* const sm = dynsm + (base - raw);

    const int tid = threadIdx.x;
    const int wid = tid >> 5;
    const int lane = tid & 31;
    const size_t row0g = (size_t)blockIdx.x * 64;

    float C[4][3][4];
#pragma unroll
    for (int mt = 0; mt < 4; mt++)
#pragma unroll
        for (int nt = 0; nt < 3; nt++)
#pragma unroll
            for (int e = 0; e < 4; e++) C[mt][nt][e] = 0.0f;

    const uint32_t a_row = (uint32_t)(lane & 15);
    const uint32_t a_kb  = (uint32_t)((lane >> 4) * 16);
    const uint32_t b_row = (uint32_t)(lane & 7);
    const uint32_t b_kb  = (uint32_t)(((lane >> 3) & 1) * 16);

    auto fillA = [&](int stage, int kc) {
        uint8_t* s = sm + stage * PROJ_STAGE;
#pragma unroll
        for (int i = 0; i < 4; i++) {
            const int idx = tid + i * 256;
            const int row = idx >> 4;
            const int c4  = idx & 15;
            float4 v = *(const float4*)&x[(row0g + row) * D_ + kc * TK_ + c4 * 4];
            const uint32_t h0 = pack_h2(v.x, v.y);
            const uint32_t h1 = pack_h2(v.z, v.w);
            const uint32_t off = swz128((uint32_t)row * 128u + (uint32_t)c4 * 8u);
            *(uint2*)(s + off) = make_uint2(h0, h1);
        }
    };
    auto cpB = [&](int stage, int kc) {
        const uint32_t sb = base + stage * PROJ_STAGE + A_TILE;
        const uint8_t* srcH = g_bhi + (size_t)kc * WTILE_BYTES;
#pragma unroll
        for (int i = 0; i < 6; i++) {
            const int idx = tid + i * 256;
            cp_async16(sb + idx * 16, srcH + idx * 16);
        }
    };

    fillA(0, 0); cpB(0, 0); CP_COMMIT(); CP_WAIT0();
    __syncthreads();

    for (int kc = 0; kc < NCHUNK_; kc++) {
        if (kc + 1 < NCHUNK_) {
            fillA((kc + 1) & 1, kc + 1);
            cpB((kc + 1) & 1, kc + 1);
            CP_COMMIT();
        }

        const uint32_t sb = base + (kc & 1) * PROJ_STAGE;
        const uint32_t sAhi = sb;
        const uint32_t sBhi = sb + A_TILE;

#pragma unroll
        for (int ks = 0; ks < 4; ks++) {
            uint32_t Ah[4][4];
#pragma unroll
            for (int mt = 0; mt < 4; mt++) {
                const uint32_t roff =
                    swz128((uint32_t)(mt * 16 + a_row) * 128u +
                           (uint32_t)ks * 32u + a_kb);
                ldsm_x4(Ah[mt], sAhi + roff);
            }
#pragma unroll
            for (int nt = 0; nt < 3; nt++) {
                const uint32_t boff =
                    swz128((uint32_t)(wid * 24 + nt * 8 + b_row) * 128u +
                           (uint32_t)ks * 32u + b_kb);
                uint32_t Bh[2];
                ldsm_x2(Bh, sBhi + boff);
#pragma unroll
                for (int mt = 0; mt < 4; mt++) {
                    mma_f16(C[mt][nt], Ah[mt], Bh[0], Bh[1]);
                }
            }
        }
        if (kc + 1 < NCHUNK_) CP_WAIT0();
        __syncthreads();
    }

#pragma unroll
    for (int mt = 0; mt < 4; mt++) {
        const size_t r = row0g + mt * 16 + (lane >> 2);
#pragma unroll
        for (int nt = 0; nt < 3; nt++) {
            const int c = wid * 24 + nt * 8 + 2 * (lane & 3);
            const int n = c & 63;
#pragma unroll
            for (int half = 0; half < 2; half++) {
                const size_t rr = r + half * 8;
                float v0 = C[mt][nt][half * 2 + 0];
                float v1 = C[mt][nt][half * 2 + 1];
                __half* o;
                if (c < 64) {
                    v0 *= SCALE_Q; v1 *= SCALE_Q;
                    o = g_qhi;
                } else {
                    o = (c < 128) ? g_khi : g_vhi;
                }
                *(uint32_t*)&o[rr * HD_ + n] = pack_h2(v0, v1);
            }
        }
    }
}

// ---------------------------------------------------------------------------
// Kernel 2: flash attention, flat chunk decomposition. One 128-thr CTA per
// work group (b, qt, kt-chunk of <=9 tiles); partials to gmem. 4 CTAs/SM.
// ---------------------------------------------------------------------------
static constexpr int Q_BYTES  = 64 * 128;           // 8192
static constexpr int KV_STAGE = 2 * 64 * 128;       // 16384 (khi|vhi)
static constexpr int ATTN_SMEM = 1024 + Q_BYTES + 2 * KV_STAGE;  // 41984

__global__ __launch_bounds__(128, 4) void attn_mma_kernel()
{
    extern __shared__ uint8_t dynsm[];
    const uint32_t raw = smem_u32(dynsm);
    const uint32_t base = (raw + 1023u) & ~1023u;

    const int tid = threadIdx.x;
    const int wi  = tid >> 5;             // warp 0..3
    const int lane = tid & 31;

    // ---- decode work item: batch, q-tile, kt chunk ----
    const int bid = blockIdx.x;
    const int b = bid / GPB_;
    int r = bid % GPB_;
    int qt = 31, s = 4;
    for (qt = 31; qt >= 0; qt--) {
        s = (qt + CHUNK_) / CHUNK_;       // ceil((qt+1)/9)
        if (r < s) break;
        r -= s;
    }
    const int n = qt + 1;
    const int cbase = n / s, crem = n % s;
    const int kt0 = r * cbase + (r < crem ? r : crem);
    const int niter = cbase + (r < crem ? 1 : 0);

    const uint32_t sQ  = base;
    const uint32_t sKV = base + Q_BYTES;
    const size_t qrow0 = (size_t)b * T_ + (size_t)qt * 64;

    // ---- Q via cp.async (512 transfers over 128 threads) ----
#pragma unroll
    for (int i = 0; i < 4; i++) {
        const int idx = tid + i * 128;
        const int row = idx >> 3;
        const int c16 = idx & 7;
        const uint32_t doff = swz128((uint32_t)row * 128u + (uint32_t)c16 * 16u);
        cp_async16(sQ + doff, &g_qhi[(qrow0 + row) * HD_ + c16 * 8]);
    }
    CP_COMMIT();

    auto prefetch_kv = [&](int kt, int stage) {
        const uint32_t sb = sKV + stage * KV_STAGE;
        const size_t krow0 = (size_t)b * T_ + (size_t)kt * 64;
#pragma unroll
        for (int i = 0; i < 8; i++) {
            const int idx = tid + i * 128;     // 0..1023
            const int arr = idx >> 9;          // 0 khi, 1 vhi
            const int row = (idx >> 3) & 63;
            const int c16 = idx & 7;
            const uint32_t doff = swz128((uint32_t)row * 128u + (uint32_t)c16 * 16u);
            const __half* src = arr ? g_vhi : g_khi;
            cp_async16(sb + arr * 8192 + doff, &src[(krow0 + row) * HD_ + c16 * 8]);
        }
    };
    prefetch_kv(kt0, 0);
    CP_COMMIT();
    CP_WAIT0();
    __syncthreads();

    // ---- Q fragments ----
    uint32_t Qh[4][4];
    {
        const uint32_t a_row = (uint32_t)(lane & 15);
        const uint32_t a_kb  = (uint32_t)((lane >> 4) * 16);
#pragma unroll
        for (int ks = 0; ks < 4; ks++) {
            const uint32_t roff =
                swz128((uint32_t)(wi * 16 + a_row) * 128u + (uint32_t)ks * 32u + a_kb);
            ldsm_x4(Qh[ks], sQ + roff);
        }
    }

    float O[8][4];
#pragma unroll
    for (int nh = 0; nh < 8; nh++)
#pragma unroll
        for (int e = 0; e < 4; e++) O[nh][e] = 0.0f;
    float m0 = -1e30f, m1 = -1e30f, l0 = 0.0f, l1 = 0.0f;

    const int kg  = lane >> 3;
    const uint32_t k_row8 = (uint32_t)(lane & 7);
    const uint32_t k_rowsel = (uint32_t)(kg >> 1) * 8;
    const uint32_t k_kb = (uint32_t)(kg & 1) * 16;
    const uint32_t v_rowsel = (uint32_t)(kg & 1) * 8;
    const uint32_t v_colsel = (uint32_t)(kg >> 1) * 16;
    const int q2 = 2 * (lane & 3);
    const int rloc = (lane >> 2);

    for (int i = 0; i < niter; i++) {
        if (i + 1 < niter) prefetch_kv(kt0 + i + 1, (i + 1) & 1);
        CP_COMMIT();

        const int kt = kt0 + i;
        const uint32_t sb = sKV + (i & 1) * KV_STAGE;
        const uint32_t sKh = sb;
        const uint32_t sVh = sb + 8192;

        // ---- S = Q @ K^T ----
        float S[8][4];
#pragma unroll
        for (int nt = 0; nt < 8; nt++)
#pragma unroll
            for (int e = 0; e < 4; e++) S[nt][e] = 0.0f;

#pragma unroll
        for (int ks = 0; ks < 4; ks++) {
#pragma unroll
            for (int ntp = 0; ntp < 4; ntp++) {
                const uint32_t boff =
                    swz128((uint32_t)(ntp * 16 + k_rowsel + k_row8) * 128u +
                           (uint32_t)ks * 32u + k_kb);
                uint32_t Kf[4];
                ldsm_x4(Kf, sKh + boff);
                mma_f16(S[2 * ntp],     Qh[ks], Kf[0], Kf[1]);
                mma_f16(S[2 * ntp + 1], Qh[ks], Kf[2], Kf[3]);
            }
        }

        // ---- causal mask on diagonal tile ----
        if (kt == qt) {
            const int r0 = wi * 16 + rloc;
#pragma unroll
            for (int nt = 0; nt < 8; nt++) {
                const int c0 = nt * 8 + q2;
                if (c0 > r0)     S[nt][0] = -1e30f;
                if (c0 + 1 > r0) S[nt][1] = -1e30f;
                if (c0 > r0 + 8)     S[nt][2] = -1e30f;
                if (c0 + 1 > r0 + 8) S[nt][3] = -1e30f;
            }
        }

        // ---- online softmax (base-2), P in fp16x2 ----
        float mx0 = -1e30f, mx1 = -1e30f;
#pragma unroll
        for (int nt = 0; nt < 8; nt++) {
            mx0 = fmaxf(mx0, fmaxf(S[nt][0], S[nt][1]));
            mx1 = fmaxf(mx1, fmaxf(S[nt][2], S[nt][3]));
        }
        mx0 = fmaxf(mx0, __shfl_xor_sync(0xffffffffu, mx0, 1));
        mx0 = fmaxf(mx0, __shfl_xor_sync(0xffffffffu, mx0, 2));
        mx1 = fmaxf(mx1, __shfl_xor_sync(0xffffffffu, mx1, 1));
        mx1 = fmaxf(mx1, __shfl_xor_sync(0xffffffffu, mx1, 2));
        const float mn0 = fmaxf(m0, mx0);
        const float mn1 = fmaxf(m1, mx1);
        const float a0 = ex2f(m0 - mn0);
        const float a1 = ex2f(m1 - mn1);
        m0 = mn0; m1 = mn1;

        uint32_t P[4][4];
        float sum0 = 0.0f, sum1 = 0.0f;
#pragma unroll
        for (int nt = 0; nt < 8; nt++) {
            const uint32_t w01 = ex2h2(f2h2(S[nt][0] - mn0, S[nt][1] - mn0));
            const uint32_t w23 = ex2h2(f2h2(S[nt][2] - mn1, S[nt][3] - mn1));
            P[nt >> 1][(nt & 1) * 2 + 0] = w01;
            P[nt >> 1][(nt & 1) * 2 + 1] = w23;
            const float2 f01 = h22f2(w01);
            const float2 f23 = h22f2(w23);
            sum0 += f01.x + f01.y;
            sum1 += f23.x + f23.y;
        }
        sum0 += __shfl_xor_sync(0xffffffffu, sum0, 1);
        sum0 += __shfl_xor_sync(0xffffffffu, sum0, 2);
        sum1 += __shfl_xor_sync(0xffffffffu, sum1, 1);
        sum1 += __shfl_xor_sync(0xffffffffu, sum1, 2);
        l0 = l0 * a0 + sum0;
        l1 = l1 * a1 + sum1;

#pragma unroll
        for (int nh = 0; nh < 8; nh++) {
            O[nh][0] *= a0; O[nh][1] *= a0;
            O[nh][2] *= a1; O[nh][3] *= a1;
        }

        // ---- O += P @ V ----
#pragma unroll
        for (int t = 0; t < 4; t++) {
#pragma unroll
            for (int nhp = 0; nhp < 4; nhp++) {
                const uint32_t voff =
                    swz128((uint32_t)(t * 16 + v_rowsel + k_row8) * 128u +
                           (uint32_t)nhp * 32u + v_colsel);
                uint32_t Vf[4];
                ldsm_x4_trans(Vf, sVh + voff);
                mma_f16(O[2 * nhp],     P[t], Vf[0], Vf[1]);
                mma_f16(O[2 * nhp + 1], P[t], Vf[2], Vf[3]);
            }
        }

        CP_WAIT0();
        __syncthreads();
    }

    // ---- write partials to gmem ----
    float* const pO = g_pO + (size_t)bid * 4096;
    const int row0 = wi * 16 + rloc;
    if ((lane & 3) == 0) {
        float* const pml = g_pML + (size_t)bid * 128;
        *(float2*)&pml[row0 * 2]       = make_float2(m0, l0);
        *(float2*)&pml[(row0 + 8) * 2] = make_float2(m1, l1);
    }
#pragma unroll
    for (int nh = 0; nh < 8; nh++) {
        const int hcol = nh * 8 + q2;
        *(float2*)&pO[row0 * 64 + hcol]       = make_float2(O[nh][0], O[nh][1]);
        *(float2*)&pO[(row0 + 8) * 64 + hcol] = make_float2(O[nh][2], O[nh][3]);
    }
}

// ---------------------------------------------------------------------------
// Kernel 3: merge partials per q-tile and write final output.
// grid 256 (one CTA per (b, qt)), 128 threads.
// ---------------------------------------------------------------------------
__global__ __launch_bounds__(128) void attn_merge_kernel(float* __restrict__ out)
{
    const int b  = blockIdx.x >> 5;
    const int qt = blockIdx.x & 31;
    const int tid = threadIdx.x;

    // group range for (b, qt): groups enumerated qt descending within batch
    int off = 0;
#pragma unroll
    for (int q = 31; q > 0; q--)
        if (q > qt) off += (q + CHUNK_) / CHUNK_;
    const int s = (qt + CHUNK_) / CHUNK_;
    const int g0 = b * GPB_ + off;

    const int row = tid >> 1;
    const int hc  = (tid & 1) * 32;

    float mp[4], lp[4];
    float M = -1e30f;
    for (int p = 0; p < s; p++) {
        const float2 ml = *(const float2*)&g_pML[(size_t)(g0 + p) * 128 + row * 2];
        mp[p] = ml.x; lp[p] = ml.y;
        M = fmaxf(M, ml.x);
    }
    float w[4];
    float L = 0.0f;
    for (int p = 0; p < s; p++) {
        w[p] = ex2f(mp[p] - M);
        L += lp[p] * w[p];
    }
    const float invL = 1.0f / L;

    const size_t orow = ((size_t)b * T_ + (size_t)qt * 64 + row) * HD_ + hc;
#pragma unroll
    for (int c4 = 0; c4 < 32; c4 += 4) {
        float4 acc = make_float4(0.f, 0.f, 0.f, 0.f);
        for (int p = 0; p < s; p++) {
            const float4 v = *(const float4*)
                &g_pO[(size_t)(g0 + p) * 4096 + row * 64 + hc + c4];
            acc.x += v.x * w[p];
            acc.y += v.y * w[p];
            acc.z += v.z * w[p];
            acc.w += v.w * w[p];
        }
        *(float4*)&out[orow + c4] =
            make_float4(acc.x * invL, acc.y * invL, acc.z * invL, acc.w * invL);
    }
}

// ---------------------------------------------------------------------------
extern "C" void kernel_launch(void* const* d_in, const int* in_sizes, int n_in,
                              void* d_out, int out_size)
{
    const float* x  = (const float*)d_in[0];
    const float* Wq = (const float*)d_in[1];
    const float* Wk = (const float*)d_in[2];
    const float* Wv = (const float*)d_in[3];
    float* out = (float*)d_out;

    cudaFuncSetAttribute(proj_mma_kernel,
                         cudaFuncAttributeMaxDynamicSharedMemorySize, PROJ_SMEM);
    cudaFuncSetAttribute(attn_mma_kernel,
                         cudaFuncAttributeMaxDynamicSharedMemorySize, ATTN_SMEM);

    const int prep_threads = NCHUNK_ * 8 * NTOT_ * 2;
    prep_w_kernel<<<(prep_threads + 255) / 256, 256>>>(Wq, Wk, Wv);
    proj_mma_kernel<<<M_ / 64, 256, PROJ_SMEM>>>(x);
    attn_mma_kernel<<<NGROUPS_, 128, ATTN_SMEM>>>();
    attn_merge_kernel<<<256, 128>>>(out);
}

// round 10
// speedup vs baseline: 7.0245x; 1.0570x over previous
#include <cuda_runtime.h>
#include <cuda_fp16.h>
#include <cstdint>

// Problem constants
static constexpr int B_  = 8;
static constexpr int T_  = 2048;
static constexpr int D_  = 1024;
static constexpr int HD_ = 64;
static constexpr int M_  = B_ * T_;       // 16384 rows
static constexpr int NTOT_ = 192;         // q|k|v fused output columns
static constexpr int TK_ = 64;            // K per chunk (128B fp16 rows)
static constexpr int NCHUNK_ = D_ / TK_;  // 16

// Attention split-work constants: chunks of <=9 kt-tiles.
static constexpr int CHUNK_ = 9;
static constexpr int GPB_ = 74;           // groups per batch: sum ceil((qt+1)/9)
static constexpr int NGROUPS_ = GPB_ * B_; // 592

// Device-global scratch (fp16 hi-only; q pre-scaled by 0.125*log2e).
__device__ __align__(16) __half g_qhi[(size_t)M_ * HD_];
__device__ __align__(16) __half g_khi[(size_t)M_ * HD_];
__device__ __align__(16) __half g_vhi[(size_t)M_ * HD_];
// Pre-transposed + swizzled fp16 W-hi tiles: [chunk][n=0..191][k=0..63]
static constexpr size_t WTILE_BYTES = (size_t)NTOT_ * 128;   // 24576 per chunk
__device__ __align__(16) uint8_t g_bhi[(size_t)NCHUNK_ * WTILE_BYTES];
// Attention partials: per group O[64][64] fp32 + per row (m, l)
__device__ __align__(16) float g_pO[(size_t)NGROUPS_ * 64 * 64];
__device__ __align__(16) float g_pML[(size_t)NGROUPS_ * 64 * 2];

__host__ __device__ __forceinline__ uint32_t swz128(uint32_t off) {
    return off ^ ((off >> 3) & 0x70);
}
__device__ __forceinline__ uint32_t smem_u32(const void* p) {
    uint32_t a;
    asm("{ .reg .u64 t; cvta.to.shared.u64 t, %1; cvt.u32.u64 %0, t; }"
        : "=r"(a) : "l"(p));
    return a;
}
__device__ __forceinline__ void ldsm_x4(uint32_t (&r)[4], uint32_t addr) {
    asm volatile("ldmatrix.sync.aligned.m8n8.x4.shared.b16 {%0,%1,%2,%3}, [%4];"
                 : "=r"(r[0]), "=r"(r[1]), "=r"(r[2]), "=r"(r[3]) : "r"(addr));
}
__device__ __forceinline__ void ldsm_x2(uint32_t (&r)[2], uint32_t addr) {
    asm volatile("ldmatrix.sync.aligned.m8n8.x2.shared.b16 {%0,%1}, [%2];"
                 : "=r"(r[0]), "=r"(r[1]) : "r"(addr));
}
__device__ __forceinline__ void ldsm_x4_trans(uint32_t (&r)[4], uint32_t addr) {
    asm volatile("ldmatrix.sync.aligned.m8n8.x4.trans.shared.b16 {%0,%1,%2,%3}, [%4];"
                 : "=r"(r[0]), "=r"(r[1]), "=r"(r[2]), "=r"(r[3]) : "r"(addr));
}
__device__ __forceinline__ void mma_f16(float (&d)[4], const uint32_t (&a)[4],
                                        uint32_t b0, uint32_t b1) {
    asm volatile(
        "mma.sync.aligned.m16n8k16.row.col.f32.f16.f16.f32 "
        "{%0,%1,%2,%3}, {%4,%5,%6,%7}, {%8,%9}, {%0,%1,%2,%3};"
        : "+f"(d[0]), "+f"(d[1]), "+f"(d[2]), "+f"(d[3])
        : "r"(a[0]), "r"(a[1]), "r"(a[2]), "r"(a[3]), "r"(b0), "r"(b1));
}
__device__ __forceinline__ uint32_t pack_h2(float lo, float hi) {
    __half l = __float2half_rn(lo);
    __half h = __float2half_rn(hi);
    return ((uint32_t)__half_as_ushort(h) << 16) | __half_as_ushort(l);
}
__device__ __forceinline__ uint32_t f2h2(float lo, float hi) {
    uint32_t r;
    asm("cvt.rn.f16x2.f32 %0, %1, %2;" : "=r"(r) : "f"(hi), "f"(lo));
    return r;
}
__device__ __forceinline__ uint32_t ex2h2(uint32_t x) {
    uint32_t r;
    asm("ex2.approx.f16x2 %0, %1;" : "=r"(r) : "r"(x));
    return r;
}
__device__ __forceinline__ float2 h22f2(uint32_t w) {
    __half2 h;
    *(uint32_t*)&h = w;
    return __half22float2(h);
}
__device__ __forceinline__ float ex2f(float x) {
    float y;
    asm("ex2.approx.ftz.f32 %0, %1;" : "=f"(y) : "f"(x));
    return y;
}
__device__ __forceinline__ void cp_async16(uint32_t dst, const void* src) {
    asm volatile("cp.async.ca.shared.global [%0], [%1], 16;"
                 :: "r"(dst), "l"(src));
}
#define CP_COMMIT() asm volatile("cp.async.commit_group;" ::: "memory")
#define CP_WAIT0()  asm volatile("cp.async.wait_group 0;" ::: "memory")

static constexpr float SCALE_Q = 0.125f * 1.4426950408889634f;  // 1/sqrt(64)*log2e

// ---------------------------------------------------------------------------
// Kernel 0: W -> fp16 hi, transposed to [n][k] rows, SW128 swizzled.
// One thread per uint32 (2 k-values): 98304 threads.
// ---------------------------------------------------------------------------
__global__ void prep_w_kernel(const float* __restrict__ Wq,
                              const float* __restrict__ Wk,
                              const float* __restrict__ Wv)
{
    const int th = blockIdx.x * blockDim.x + threadIdx.x;
    if (th >= NCHUNK_ * 8 * NTOT_ * 4) return;
    const int jh = th & 3;                 // word within 16B group
    const int t = th >> 2;
    const int c = t % NTOT_;
    const int rest = t / NTOT_;
    const int kg = rest % 8;
    const int chunk = rest / 8;
    const int n = c & 63;
    const float* W = (c < 64) ? Wq : (c < 128) ? Wk : Wv;
    const int k0 = chunk * TK_ + kg * 8 + jh * 2;

    const float a = W[(size_t)k0 * HD_ + n];
    const float b = W[(size_t)(k0 + 1) * HD_ + n];
    const size_t base = (size_t)chunk * WTILE_BYTES;
    const uint32_t off = swz128((uint32_t)c * 128u + (uint32_t)kg * 16u) + jh * 4u;
    *(uint32_t*)(g_bhi + base + off) = pack_h2(a, b);
}

// ---------------------------------------------------------------------------
// Kernel 1: QKV projection, mma.sync fp16 1-term. M-tile 64, grid 256,
// 2 CTAs/SM, 2-stage cp.async pipeline. (unchanged from R9)
// ---------------------------------------------------------------------------
static constexpr int A_TILE = 64 * 128;            // 8192 bytes
static constexpr int B_TILE = NTOT_ * 128;         // 24576 bytes
static constexpr int PROJ_STAGE = A_TILE + B_TILE;       // 32768
static constexpr int PROJ_SMEM = 1024 + 2 * PROJ_STAGE;  // 66560

__global__ __launch_bounds__(256, 2) void proj_mma_kernel(const float* __restrict__ x)
{
    extern __shared__ uint8_t dynsm[];
    const uint32_t raw = smem_u32(dynsm);
    const uint32_t base = (raw + 1023u) & ~1023u;
    uint8_t* const sm = dynsm + (base - raw);

    const int tid = threadIdx.x;
    const int wid = tid >> 5;
    const int lane = tid & 31;
    const size_t row0g = (size_t)blockIdx.x * 64;

    float C[4][3][4];
#pragma unroll
    for (int mt = 0; mt < 4; mt++)
#pragma unroll
        for (int nt = 0; nt < 3; nt++)
#pragma unroll
            for (int e = 0; e < 4; e++) C[mt][nt][e] = 0.0f;

    const uint32_t a_row = (uint32_t)(lane & 15);
    const uint32_t a_kb  = (uint32_t)((lane >> 4) * 16);
    const uint32_t b_row = (uint32_t)(lane & 7);
    const uint32_t b_kb  = (uint32_t)(((lane >> 3) & 1) * 16);

    auto fillA = [&](int stage, int kc) {
        uint8_t* s = sm + stage * PROJ_STAGE;
#pragma unroll
        for (int i = 0; i < 4; i++) {
            const int idx = tid + i * 256;
            const int row = idx >> 4;
            const int c4  = idx & 15;
            float4 v = *(const float4*)&x[(row0g + row) * D_ + kc * TK_ + c4 * 4];
            const uint32_t h0 = pack_h2(v.x, v.y);
            const uint32_t h1 = pack_h2(v.z, v.w);
            const uint32_t off = swz128((uint32_t)row * 128u + (uint32_t)c4 * 8u);
            *(uint2*)(s + off) = make_uint2(h0, h1);
        }
    };
    auto cpB = [&](int stage, int kc) {
        const uint32_t sb = base + stage * PROJ_STAGE + A_TILE;
        const uint8_t* srcH = g_bhi + (size_t)kc * WTILE_BYTES;
#pragma unroll
        for (int i = 0; i < 6; i++) {
            const int idx = tid + i * 256;
            cp_async16(sb + idx * 16, srcH + idx * 16);
        }
    };

    fillA(0, 0); cpB(0, 0); CP_COMMIT(); CP_WAIT0();
    __syncthreads();

    for (int kc = 0; kc < NCHUNK_; kc++) {
        if (kc + 1 < NCHUNK_) {
            fillA((kc + 1) & 1, kc + 1);
            cpB((kc + 1) & 1, kc + 1);
            CP_COMMIT();
        }

        const uint32_t sb = base + (kc & 1) * PROJ_STAGE;
        const uint32_t sAhi = sb;
        const uint32_t sBhi = sb + A_TILE;

#pragma unroll
        for (int ks = 0; ks < 4; ks++) {
            uint32_t Ah[4][4];
#pragma unroll
            for (int mt = 0; mt < 4; mt++) {
                const uint32_t roff =
                    swz128((uint32_t)(mt * 16 + a_row) * 128u +
                           (uint32_t)ks * 32u + a_kb);
                ldsm_x4(Ah[mt], sAhi + roff);
            }
#pragma unroll
            for (int nt = 0; nt < 3; nt++) {
                const uint32_t boff =
                    swz128((uint32_t)(wid * 24 + nt * 8 + b_row) * 128u +
                           (uint32_t)ks * 32u + b_kb);
                uint32_t Bh[2];
                ldsm_x2(Bh, sBhi + boff);
#pragma unroll
                for (int mt = 0; mt < 4; mt++) {
                    mma_f16(C[mt][nt], Ah[mt], Bh[0], Bh[1]);
                }
            }
        }
        if (kc + 1 < NCHUNK_) CP_WAIT0();
        __syncthreads();
    }

#pragma unroll
    for (int mt = 0; mt < 4; mt++) {
        const size_t r = row0g + mt * 16 + (lane >> 2);
#pragma unroll
        for (int nt = 0; nt < 3; nt++) {
            const int c = wid * 24 + nt * 8 + 2 * (lane & 3);
            const int n = c & 63;
#pragma unroll
            for (int half = 0; half < 2; half++) {
                const size_t rr = r + half * 8;
                float v0 = C[mt][nt][half * 2 + 0];
                float v1 = C[mt][nt][half * 2 + 1];
                __half* o;
                if (c < 64) {
                    v0 *= SCALE_Q; v1 *= SCALE_Q;
                    o = g_qhi;
                } else {
                    o = (c < 128) ? g_khi : g_vhi;
                }
                *(uint32_t*)&o[rr * HD_ + n] = pack_h2(v0, v1);
            }
        }
    }
}

// ---------------------------------------------------------------------------
// Kernel 2: flash attention, flat chunk decomposition. One 128-thr CTA per
// work group (b, qt, kt-chunk of <=9 tiles); partials to gmem. 4 CTAs/SM.
// (unchanged from R9)
// ---------------------------------------------------------------------------
static constexpr int Q_BYTES  = 64 * 128;           // 8192
static constexpr int KV_STAGE = 2 * 64 * 128;       // 16384 (khi|vhi)
static constexpr int ATTN_SMEM = 1024 + Q_BYTES + 2 * KV_STAGE;  // 41984

__global__ __launch_bounds__(128, 4) void attn_mma_kernel()
{
    extern __shared__ uint8_t dynsm[];
    const uint32_t raw = smem_u32(dynsm);
    const uint32_t base = (raw + 1023u) & ~1023u;

    const int tid = threadIdx.x;
    const int wi  = tid >> 5;
    const int lane = tid & 31;

    // ---- decode work item: batch, q-tile, kt chunk ----
    const int bid = blockIdx.x;
    const int b = bid / GPB_;
    int r = bid % GPB_;
    int qt = 31, s = 4;
    for (qt = 31; qt >= 0; qt--) {
        s = (qt + CHUNK_) / CHUNK_;
        if (r < s) break;
        r -= s;
    }
    const int n = qt + 1;
    const int cbase = n / s, crem = n % s;
    const int kt0 = r * cbase + (r < crem ? r : crem);
    const int niter = cbase + (r < crem ? 1 : 0);

    const uint32_t sQ  = base;
    const uint32_t sKV = base + Q_BYTES;
    const size_t qrow0 = (size_t)b * T_ + (size_t)qt * 64;

#pragma unroll
    for (int i = 0; i < 4; i++) {
        const int idx = tid + i * 128;
        const int row = idx >> 3;
        const int c16 = idx & 7;
        const uint32_t doff = swz128((uint32_t)row * 128u + (uint32_t)c16 * 16u);
        cp_async16(sQ + doff, &g_qhi[(qrow0 + row) * HD_ + c16 * 8]);
    }
    CP_COMMIT();

    auto prefetch_kv = [&](int kt, int stage) {
        const uint32_t sb = sKV + stage * KV_STAGE;
        const size_t krow0 = (size_t)b * T_ + (size_t)kt * 64;
#pragma unroll
        for (int i = 0; i < 8; i++) {
            const int idx = tid + i * 128;
            const int arr = idx >> 9;
            const int row = (idx >> 3) & 63;
            const int c16 = idx & 7;
            const uint32_t doff = swz128((uint32_t)row * 128u + (uint32_t)c16 * 16u);
            const __half* src = arr ? g_vhi : g_khi;
            cp_async16(sb + arr * 8192 + doff, &src[(krow0 + row) * HD_ + c16 * 8]);
        }
    };
    prefetch_kv(kt0, 0);
    CP_COMMIT();
    CP_WAIT0();
    __syncthreads();

    uint32_t Qh[4][4];
    {
        const uint32_t a_row = (uint32_t)(lane & 15);
        const uint32_t a_kb  = (uint32_t)((lane >> 4) * 16);
#pragma unroll
        for (int ks = 0; ks < 4; ks++) {
            const uint32_t roff =
                swz128((uint32_t)(wi * 16 + a_row) * 128u + (uint32_t)ks * 32u + a_kb);
            ldsm_x4(Qh[ks], sQ + roff);
        }
    }

    float O[8][4];
#pragma unroll
    for (int nh = 0; nh < 8; nh++)
#pragma unroll
        for (int e = 0; e < 4; e++) O[nh][e] = 0.0f;
    float m0 = -1e30f, m1 = -1e30f, l0 = 0.0f, l1 = 0.0f;

    const int kg  = lane >> 3;
    const uint32_t k_row8 = (uint32_t)(lane & 7);
    const uint32_t k_rowsel = (uint32_t)(kg >> 1) * 8;
    const uint32_t k_kb = (uint32_t)(kg & 1) * 16;
    const uint32_t v_rowsel = (uint32_t)(kg & 1) * 8;
    const uint32_t v_colsel = (uint32_t)(kg >> 1) * 16;
    const int q2 = 2 * (lane & 3);
    const int rloc = (lane >> 2);

    for (int i = 0; i < niter; i++) {
        if (i + 1 < niter) prefetch_kv(kt0 + i + 1, (i + 1) & 1);
        CP_COMMIT();

        const int kt = kt0 + i;
        const uint32_t sb = sKV + (i & 1) * KV_STAGE;
        const uint32_t sKh = sb;
        const uint32_t sVh = sb + 8192;

        float S[8][4];
#pragma unroll
        for (int nt = 0; nt < 8; nt++)
#pragma unroll
            for (int e = 0; e < 4; e++) S[nt][e] = 0.0f;

#pragma unroll
        for (int ks = 0; ks < 4; ks++) {
#pragma unroll
            for (int ntp = 0; ntp < 4; ntp++) {
                const uint32_t boff =
                    swz128((uint32_t)(ntp * 16 + k_rowsel + k_row8) * 128u +
                           (uint32_t)ks * 32u + k_kb);
                uint32_t Kf[4];
                ldsm_x4(Kf, sKh + boff);
                mma_f16(S[2 * ntp],     Qh[ks], Kf[0], Kf[1]);
                mma_f16(S[2 * ntp + 1], Qh[ks], Kf[2], Kf[3]);
            }
        }

        if (kt == qt) {
            const int r0 = wi * 16 + rloc;
#pragma unroll
            for (int nt = 0; nt < 8; nt++) {
                const int c0 = nt * 8 + q2;
                if (c0 > r0)     S[nt][0] = -1e30f;
                if (c0 + 1 > r0) S[nt][1] = -1e30f;
                if (c0 > r0 + 8)     S[nt][2] = -1e30f;
                if (c0 + 1 > r0 + 8) S[nt][3] = -1e30f;
            }
        }

        float mx0 = -1e30f, mx1 = -1e30f;
#pragma unroll
        for (int nt = 0; nt < 8; nt++) {
            mx0 = fmaxf(mx0, fmaxf(S[nt][0], S[nt][1]));
            mx1 = fmaxf(mx1, fmaxf(S[nt][2], S[nt][3]));
        }
        mx0 = fmaxf(mx0, __shfl_xor_sync(0xffffffffu, mx0, 1));
        mx0 = fmaxf(mx0, __shfl_xor_sync(0xffffffffu, mx0, 2));
        mx1 = fmaxf(mx1, __shfl_xor_sync(0xffffffffu, mx1, 1));
        mx1 = fmaxf(mx1, __shfl_xor_sync(0xffffffffu, mx1, 2));
        const float mn0 = fmaxf(m0, mx0);
        const float mn1 = fmaxf(m1, mx1);
        const float a0 = ex2f(m0 - mn0);
        const float a1 = ex2f(m1 - mn1);
        m0 = mn0; m1 = mn1;

        uint32_t P[4][4];
        float sum0 = 0.0f, sum1 = 0.0f;
#pragma unroll
        for (int nt = 0; nt < 8; nt++) {
            const uint32_t w01 = ex2h2(f2h2(S[nt][0] - mn0, S[nt][1] - mn0));
            const uint32_t w23 = ex2h2(f2h2(S[nt][2] - mn1, S[nt][3] - mn1));
            P[nt >> 1][(nt & 1) * 2 + 0] = w01;
            P[nt >> 1][(nt & 1) * 2 + 1] = w23;
            const float2 f01 = h22f2(w01);
            const float2 f23 = h22f2(w23);
            sum0 += f01.x + f01.y;
            sum1 += f23.x + f23.y;
        }
        sum0 += __shfl_xor_sync(0xffffffffu, sum0, 1);
        sum0 += __shfl_xor_sync(0xffffffffu, sum0, 2);
        sum1 += __shfl_xor_sync(0xffffffffu, sum1, 1);
        sum1 += __shfl_xor_sync(0xffffffffu, sum1, 2);
        l0 = l0 * a0 + sum0;
        l1 = l1 * a1 + sum1;

#pragma unroll
        for (int nh = 0; nh < 8; nh++) {
            O[nh][0] *= a0; O[nh][1] *= a0;
            O[nh][2] *= a1; O[nh][3] *= a1;
        }

#pragma unroll
        for (int t = 0; t < 4; t++) {
#pragma unroll
            for (int nhp = 0; nhp < 4; nhp++) {
                const uint32_t voff =
                    swz128((uint32_t)(t * 16 + v_rowsel + k_row8) * 128u +
                           (uint32_t)nhp * 32u + v_colsel);
                uint32_t Vf[4];
                ldsm_x4_trans(Vf, sVh + voff);
                mma_f16(O[2 * nhp],     P[t], Vf[0], Vf[1]);
                mma_f16(O[2 * nhp + 1], P[t], Vf[2], Vf[3]);
            }
        }

        CP_WAIT0();
        __syncthreads();
    }

    // ---- write partials to gmem ----
    float* const pO = g_pO + (size_t)bid * 4096;
    const int row0 = wi * 16 + rloc;
    if ((lane & 3) == 0) {
        float* const pml = g_pML + (size_t)bid * 128;
        *(float2*)&pml[row0 * 2]       = make_float2(m0, l0);
        *(float2*)&pml[(row0 + 8) * 2] = make_float2(m1, l1);
    }
#pragma unroll
    for (int nh = 0; nh < 8; nh++) {
        const int hcol = nh * 8 + q2;
        *(float2*)&pO[row0 * 64 + hcol]       = make_float2(O[nh][0], O[nh][1]);
        *(float2*)&pO[(row0 + 8) * 64 + hcol] = make_float2(O[nh][2], O[nh][3]);
    }
}

// ---------------------------------------------------------------------------
// Kernel 3: merge partials. One thread per 8 output floats: 131072 threads,
// grid 512 x 256. High MLP, all partial loads independent.
// ---------------------------------------------------------------------------
__global__ __launch_bounds__(256) void attn_merge_kernel(float* __restrict__ out)
{
    const int gid = blockIdx.x * 256 + threadIdx.x;    // 0..131071
    const int row_glob = gid >> 3;                     // 0..16383
    const int seg = (gid & 7) * 8;                     // 0,8,..,56

    const int b   = row_glob >> 11;
    const int within = row_glob & 2047;
    const int qt  = within >> 6;
    const int row = within & 63;

    // group base for (b, qt): groups enumerated qt descending within batch
    int off = 0;
    for (int q = qt + 1; q < 32; q++) off += (q + CHUNK_) / CHUNK_;
    const int s = (qt + CHUNK_) / CHUNK_;
    const int g0 = b * GPB_ + off;

    float mp[4], lp[4];
    float M = -1e30f;
#pragma unroll 4
    for (int p = 0; p < s; p++) {
        const float2 ml = *(const float2*)&g_pML[(size_t)(g0 + p) * 128 + row * 2];
        mp[p] = ml.x; lp[p] = ml.y;
        M = fmaxf(M, ml.x);
    }
    float w[4];
    float L = 0.0f;
#pragma unroll 4
    for (int p = 0; p < s; p++) {
        w[p] = ex2f(mp[p] - M);
        L += lp[p] * w[p];
    }
    const float invL = 1.0f / L;

    float4 acc0 = make_float4(0.f, 0.f, 0.f, 0.f);
    float4 acc1 = make_float4(0.f, 0.f, 0.f, 0.f);
#pragma unroll 4
    for (int p = 0; p < s; p++) {
        const float* src = &g_pO[(size_t)(g0 + p) * 4096 + row * 64 + seg];
        const float4 v0 = *(const float4*)&src[0];
        const float4 v1 = *(const float4*)&src[4];
        acc0.x += v0.x * w[p]; acc0.y += v0.y * w[p];
        acc0.z += v0.z * w[p]; acc0.w += v0.w * w[p];
        acc1.x += v1.x * w[p]; acc1.y += v1.y * w[p];
        acc1.z += v1.z * w[p]; acc1.w += v1.w * w[p];
    }

    const size_t orow = (size_t)row_glob * HD_ + seg;
    *(float4*)&out[orow] =
        make_float4(acc0.x * invL, acc0.y * invL, acc0.z * invL, acc0.w * invL);
    *(float4*)&out[orow + 4] =
        make_float4(acc1.x * invL, acc1.y * invL, acc1.z * invL, acc1.w * invL);
}

// ---------------------------------------------------------------------------
extern "C" void kernel_launch(void* const* d_in, const int* in_sizes, int n_in,
                              void* d_out, int out_size)
{
    const float* x  = (const float*)d_in[0];
    const float* Wq = (const float*)d_in[1];
    const float* Wk = (const float*)d_in[2];
    const float* Wv = (const float*)d_in[3];
    float* out = (float*)d_out;

    cudaFuncSetAttribute(proj_mma_kernel,
                         cudaFuncAttributeMaxDynamicSharedMemorySize, PROJ_SMEM);
    cudaFuncSetAttribute(attn_mma_kernel,
                         cudaFuncAttributeMaxDynamicSharedMemorySize, ATTN_SMEM);

    const int prep_threads = NCHUNK_ * 8 * NTOT_ * 4;
    prep_w_kernel<<<(prep_threads + 255) / 256, 256>>>(Wq, Wk, Wv);
    proj_mma_kernel<<<M_ / 64, 256, PROJ_SMEM>>>(x);
    attn_mma_kernel<<<NGROUPS_, 128, ATTN_SMEM>>>();
    attn_merge_kernel<<<512, 256>>>(out);
}